// round 3
// baseline (speedup 1.0000x reference)
#include <cuda_runtime.h>

#define B 4096
#define NTHREADS 256

// ---------------------------------------------------------------------------
// Scratch (no allocations allowed): one big __device__ array, fixed offsets.
// ---------------------------------------------------------------------------
#define OFF_WE0   0            // 128x128 folded phiE k0 weight
#define OFF_BE0   16384        // 128 folded bias k0
#define OFF_BE1   16512        // 128 folded bias k1
#define OFF_T     16640        // 3B x 128  (MLP hidden temp)
#define OFF_M0    1589504      // B x 128   (k0 message)
#define OFF_P     2113792      // 3B x 256  (packed GEMM inputs)
#define OFF_U     5259520      // 3B x 128  (post-LN hidden)
#define OFF_H     6832384      // 2B x 128  (h_a, h_b)
#define OFF_M1    7880960      // 3B x 128  (m_ab, m_ba, m_bb)
#define OFF_UMIX  9453824      // B x 128
#define OFF_HMIX  9978112      // B x 128
#define OFF_ZG    10502400     // B x 128
#define OFF_X     11026688     // B x 256
#define SCRATCH_TOTAL 12075264

__device__ float g_scratch[SCRATCH_TOTAL];

// ---------------------------------------------------------------------------
// Prep: fold phiE k=0 weights (z0 appears twice) and edge-attr bias terms.
// ---------------------------------------------------------------------------
__global__ __launch_bounds__(NTHREADS) void prep_kernel(
    const float* __restrict__ phiE_W1, const float* __restrict__ phiE_b1,
    const float* __restrict__ edge_attr)
{
    int i = blockIdx.x * NTHREADS + threadIdx.x;
    float e = edge_attr[0];
    if (i < 16384) {
        int r = i >> 7, c = i & 127;
        g_scratch[OFF_WE0 + i] = phiE_W1[r * 128 + c] + phiE_W1[(128 + r) * 128 + c];
    }
    if (i < 128) {
        g_scratch[OFF_BE0 + i] = phiE_b1[i]       + e * phiE_W1[256 * 128 + i];
        g_scratch[OFF_BE1 + i] = phiE_b1[128 + i] + e * phiE_W1[257 * 128 + 256 * 128 + i];
    }
}

// ---------------------------------------------------------------------------
// Generic fused layer: out[M,128] = epi(A[M,K] @ W[K,128] + bias)
// epi: optional ReLU -> optional LayerNorm(g,b) -> optional residual add.
// Block: 32 rows x 128 cols, 256 threads, thread tile 4x4.
// ---------------------------------------------------------------------------
template<int K, int KC>
__global__ __launch_bounds__(NTHREADS) void layer_kernel(
    const float* __restrict__ A, const float* __restrict__ W,
    const float* __restrict__ bias, float* __restrict__ out,
    const float* __restrict__ lng, const float* __restrict__ lnb,
    const float* __restrict__ resid, int resid_mod, int do_relu)
{
    __shared__ float As[32 * K];
    __shared__ float Ws[KC * 128];
    const int tid = threadIdx.x;
    const int m0 = blockIdx.x * 32;
    {
        const float4* Ag = reinterpret_cast<const float4*>(A + (long)m0 * K);
        float4* As4 = reinterpret_cast<float4*>(As);
        #pragma unroll
        for (int i = tid; i < 8 * K; i += NTHREADS) As4[i] = Ag[i];
    }
    const int lane = tid & 31, warp = tid >> 5;
    const int r0 = warp * 4, c0 = lane * 4;
    float acc[4][4];
    #pragma unroll
    for (int i = 0; i < 4; i++) { acc[i][0] = 0.f; acc[i][1] = 0.f; acc[i][2] = 0.f; acc[i][3] = 0.f; }

    for (int kc = 0; kc < K; kc += KC) {
        __syncthreads();
        {
            const float4* Wg = reinterpret_cast<const float4*>(W + (long)kc * 128);
            float4* Ws4 = reinterpret_cast<float4*>(Ws);
            #pragma unroll
            for (int i = tid; i < KC * 32; i += NTHREADS) Ws4[i] = Wg[i];
        }
        __syncthreads();
        #pragma unroll 8
        for (int k = 0; k < KC; k++) {
            float4 wv = *reinterpret_cast<const float4*>(&Ws[k * 128 + c0]);
            #pragma unroll
            for (int i = 0; i < 4; i++) {
                float a = As[(r0 + i) * K + kc + k];
                acc[i][0] = fmaf(a, wv.x, acc[i][0]);
                acc[i][1] = fmaf(a, wv.y, acc[i][1]);
                acc[i][2] = fmaf(a, wv.z, acc[i][2]);
                acc[i][3] = fmaf(a, wv.w, acc[i][3]);
            }
        }
    }

    float4 bv = *reinterpret_cast<const float4*>(&bias[c0]);
    #pragma unroll
    for (int i = 0; i < 4; i++) {
        acc[i][0] += bv.x; acc[i][1] += bv.y; acc[i][2] += bv.z; acc[i][3] += bv.w;
    }
    if (do_relu) {
        #pragma unroll
        for (int i = 0; i < 4; i++) {
            acc[i][0] = fmaxf(acc[i][0], 0.f); acc[i][1] = fmaxf(acc[i][1], 0.f);
            acc[i][2] = fmaxf(acc[i][2], 0.f); acc[i][3] = fmaxf(acc[i][3], 0.f);
        }
    }
    if (lng != nullptr) {
        float4 gv = *reinterpret_cast<const float4*>(&lng[c0]);
        float4 ev = *reinterpret_cast<const float4*>(&lnb[c0]);
        #pragma unroll
        for (int i = 0; i < 4; i++) {
            float s = acc[i][0] + acc[i][1] + acc[i][2] + acc[i][3];
            float q = acc[i][0]*acc[i][0] + acc[i][1]*acc[i][1] + acc[i][2]*acc[i][2] + acc[i][3]*acc[i][3];
            #pragma unroll
            for (int off = 16; off > 0; off >>= 1) {
                s += __shfl_xor_sync(0xffffffffu, s, off);
                q += __shfl_xor_sync(0xffffffffu, q, off);
            }
            float mu = s * (1.f / 128.f);
            float var = q * (1.f / 128.f) - mu * mu;
            float rs = rsqrtf(var + 1e-5f);
            acc[i][0] = (acc[i][0] - mu) * rs * gv.x + ev.x;
            acc[i][1] = (acc[i][1] - mu) * rs * gv.y + ev.y;
            acc[i][2] = (acc[i][2] - mu) * rs * gv.z + ev.z;
            acc[i][3] = (acc[i][3] - mu) * rs * gv.w + ev.w;
        }
    }
    if (resid != nullptr) {
        #pragma unroll
        for (int i = 0; i < 4; i++) {
            int row = m0 + r0 + i;
            float4 rv = *reinterpret_cast<const float4*>(&resid[(long)(row % resid_mod) * 128 + c0]);
            acc[i][0] += rv.x; acc[i][1] += rv.y; acc[i][2] += rv.z; acc[i][3] += rv.w;
        }
    }
    #pragma unroll
    for (int i = 0; i < 4; i++) {
        int row = m0 + r0 + i;
        *reinterpret_cast<float4*>(&out[(long)row * 128 + c0]) =
            make_float4(acc[i][0], acc[i][1], acc[i][2], acc[i][3]);
    }
}

// ---------------------------------------------------------------------------
// Shared head: x = LN256(relu(zg[B,128] @ sh_W[128,256] + sh_b))
// ---------------------------------------------------------------------------
__global__ __launch_bounds__(NTHREADS) void sh_kernel(
    const float* __restrict__ A, const float* __restrict__ W,
    const float* __restrict__ bias, const float* __restrict__ lng,
    const float* __restrict__ lnb, float* __restrict__ out)
{
    __shared__ float As[32 * 128];
    __shared__ float Ws[32 * 256];
    const int tid = threadIdx.x;
    const int m0 = blockIdx.x * 32;
    {
        const float4* Ag = reinterpret_cast<const float4*>(A + (long)m0 * 128);
        float4* As4 = reinterpret_cast<float4*>(As);
        #pragma unroll
        for (int i = tid; i < 1024; i += NTHREADS) As4[i] = Ag[i];
    }
    const int lane = tid & 31, warp = tid >> 5;
    const int r0 = warp * 4, c0 = lane * 4, c1 = 128 + lane * 4;
    float acc[4][8];
    #pragma unroll
    for (int i = 0; i < 4; i++)
        #pragma unroll
        for (int j = 0; j < 8; j++) acc[i][j] = 0.f;

    for (int kc = 0; kc < 128; kc += 32) {
        __syncthreads();
        {
            const float4* Wg = reinterpret_cast<const float4*>(W + (long)kc * 256);
            float4* Ws4 = reinterpret_cast<float4*>(Ws);
            #pragma unroll
            for (int i = tid; i < 2048; i += NTHREADS) Ws4[i] = Wg[i];
        }
        __syncthreads();
        #pragma unroll 4
        for (int k = 0; k < 32; k++) {
            float4 w0 = *reinterpret_cast<const float4*>(&Ws[k * 256 + c0]);
            float4 w1 = *reinterpret_cast<const float4*>(&Ws[k * 256 + c1]);
            #pragma unroll
            for (int i = 0; i < 4; i++) {
                float a = As[(r0 + i) * 128 + kc + k];
                acc[i][0] = fmaf(a, w0.x, acc[i][0]); acc[i][1] = fmaf(a, w0.y, acc[i][1]);
                acc[i][2] = fmaf(a, w0.z, acc[i][2]); acc[i][3] = fmaf(a, w0.w, acc[i][3]);
                acc[i][4] = fmaf(a, w1.x, acc[i][4]); acc[i][5] = fmaf(a, w1.y, acc[i][5]);
                acc[i][6] = fmaf(a, w1.z, acc[i][6]); acc[i][7] = fmaf(a, w1.w, acc[i][7]);
            }
        }
    }
    float4 bv0 = *reinterpret_cast<const float4*>(&bias[c0]);
    float4 bv1 = *reinterpret_cast<const float4*>(&bias[c1]);
    float4 g0 = *reinterpret_cast<const float4*>(&lng[c0]);
    float4 g1 = *reinterpret_cast<const float4*>(&lng[c1]);
    float4 e0 = *reinterpret_cast<const float4*>(&lnb[c0]);
    float4 e1 = *reinterpret_cast<const float4*>(&lnb[c1]);
    #pragma unroll
    for (int i = 0; i < 4; i++) {
        acc[i][0] = fmaxf(acc[i][0] + bv0.x, 0.f); acc[i][1] = fmaxf(acc[i][1] + bv0.y, 0.f);
        acc[i][2] = fmaxf(acc[i][2] + bv0.z, 0.f); acc[i][3] = fmaxf(acc[i][3] + bv0.w, 0.f);
        acc[i][4] = fmaxf(acc[i][4] + bv1.x, 0.f); acc[i][5] = fmaxf(acc[i][5] + bv1.y, 0.f);
        acc[i][6] = fmaxf(acc[i][6] + bv1.z, 0.f); acc[i][7] = fmaxf(acc[i][7] + bv1.w, 0.f);
        float s = 0.f, q = 0.f;
        #pragma unroll
        for (int j = 0; j < 8; j++) { s += acc[i][j]; q += acc[i][j] * acc[i][j]; }
        #pragma unroll
        for (int off = 16; off > 0; off >>= 1) {
            s += __shfl_xor_sync(0xffffffffu, s, off);
            q += __shfl_xor_sync(0xffffffffu, q, off);
        }
        float mu = s * (1.f / 256.f);
        float var = q * (1.f / 256.f) - mu * mu;
        float rs = rsqrtf(var + 1e-5f);
        acc[i][0] = (acc[i][0]-mu)*rs*g0.x + e0.x; acc[i][1] = (acc[i][1]-mu)*rs*g0.y + e0.y;
        acc[i][2] = (acc[i][2]-mu)*rs*g0.z + e0.z; acc[i][3] = (acc[i][3]-mu)*rs*g0.w + e0.w;
        acc[i][4] = (acc[i][4]-mu)*rs*g1.x + e1.x; acc[i][5] = (acc[i][5]-mu)*rs*g1.y + e1.y;
        acc[i][6] = (acc[i][6]-mu)*rs*g1.z + e1.z; acc[i][7] = (acc[i][7]-mu)*rs*g1.w + e1.w;
        int row = m0 + r0 + i;
        *reinterpret_cast<float4*>(&out[(long)row * 256 + c0]) =
            make_float4(acc[i][0], acc[i][1], acc[i][2], acc[i][3]);
        *reinterpret_cast<float4*>(&out[(long)row * 256 + c1]) =
            make_float4(acc[i][4], acc[i][5], acc[i][6], acc[i][7]);
    }
}

// ---------------------------------------------------------------------------
// Policy head GEMM: logits[B,960] = x[B,256] @ pol_W[256,960] + pol_b
// 64x64 tiles, 256 threads, 4x4 register tile, KC=32.
// ---------------------------------------------------------------------------
__global__ __launch_bounds__(NTHREADS) void pol_kernel(
    const float* __restrict__ X, const float* __restrict__ W,
    const float* __restrict__ bias, float* __restrict__ out)
{
    __shared__ float Xs[64 * 33];
    __shared__ float Ws[32 * 64];
    const int tid = threadIdx.x;
    const int m0 = blockIdx.y * 64;
    const int n0 = blockIdx.x * 64;
    const int rt = (tid >> 4) * 4;
    const int ct = (tid & 15) * 4;
    float acc[4][4];
    #pragma unroll
    for (int i = 0; i < 4; i++) { acc[i][0]=0.f; acc[i][1]=0.f; acc[i][2]=0.f; acc[i][3]=0.f; }

    for (int kc = 0; kc < 256; kc += 32) {
        __syncthreads();
        #pragma unroll
        for (int i = tid; i < 64 * 32; i += NTHREADS) {
            int r = i >> 5, k = i & 31;
            Xs[r * 33 + k] = X[(long)(m0 + r) * 256 + kc + k];
        }
        #pragma unroll
        for (int i = tid; i < 32 * 16; i += NTHREADS) {
            int r = i >> 4, c4 = (i & 15) * 4;
            *reinterpret_cast<float4*>(&Ws[r * 64 + c4]) =
                *reinterpret_cast<const float4*>(&W[(long)(kc + r) * 960 + n0 + c4]);
        }
        __syncthreads();
        #pragma unroll 8
        for (int k = 0; k < 32; k++) {
            float4 wv = *reinterpret_cast<const float4*>(&Ws[k * 64 + ct]);
            #pragma unroll
            for (int i = 0; i < 4; i++) {
                float a = Xs[(rt + i) * 33 + k];
                acc[i][0] = fmaf(a, wv.x, acc[i][0]);
                acc[i][1] = fmaf(a, wv.y, acc[i][1]);
                acc[i][2] = fmaf(a, wv.z, acc[i][2]);
                acc[i][3] = fmaf(a, wv.w, acc[i][3]);
            }
        }
    }
    float4 bv = *reinterpret_cast<const float4*>(&bias[n0 + ct]);
    #pragma unroll
    for (int i = 0; i < 4; i++) {
        int row = m0 + rt + i;
        *reinterpret_cast<float4*>(&out[(long)row * 960 + n0 + ct]) =
            make_float4(acc[i][0]+bv.x, acc[i][1]+bv.y, acc[i][2]+bv.z, acc[i][3]+bv.w);
    }
}

// ---------------------------------------------------------------------------
// Value head: V[m] = dot(x[m,:256], val_W) + val_b
// ---------------------------------------------------------------------------
__global__ __launch_bounds__(NTHREADS) void val_kernel(
    const float* __restrict__ x, const float* __restrict__ vW,
    const float* __restrict__ vb, float* __restrict__ V)
{
    int warp = threadIdx.x >> 5, lane = threadIdx.x & 31;
    int m = blockIdx.x * 8 + warp;
    float s = 0.f;
    #pragma unroll
    for (int k = lane; k < 256; k += 32) s += x[(long)m * 256 + k] * vW[k];
    #pragma unroll
    for (int off = 16; off > 0; off >>= 1) s += __shfl_xor_sync(0xffffffffu, s, off);
    if (lane == 0) V[m] = s + vb[0];
}

// ---------------------------------------------------------------------------
// Pack kernels: build concatenated [h, agg] style GEMM inputs in scratch.
// ---------------------------------------------------------------------------
__global__ __launch_bounds__(NTHREADS) void pack0_kernel(const float* __restrict__ z0)
{
    // P[2B,256]: rows <B: [z0, 1*m0]; rows >=B: [z0, 2*m0]
    int g = blockIdx.x * NTHREADS + threadIdx.x;       // float4 index, 2B*64 total
    int m = g >> 6, k4 = g & 63;
    int b = m & (B - 1);
    float4* P = reinterpret_cast<float4*>(g_scratch + OFF_P);
    float4 v;
    if (k4 < 32) {
        v = *reinterpret_cast<const float4*>(&z0[(long)b * 128 + k4 * 4]);
    } else {
        v = *reinterpret_cast<const float4*>(&g_scratch[OFF_M0 + (long)b * 128 + (k4 - 32) * 4]);
        if (m >= B) { v.x *= 2.f; v.y *= 2.f; v.z *= 2.f; v.w *= 2.f; }
    }
    P[(long)m * 64 + k4] = v;
}

__global__ __launch_bounds__(NTHREADS) void pack1_kernel()
{
    // P[3B,256]: v0:[h_a,h_b] v1:[h_b,h_a] v2:[h_b,h_b]
    int g = blockIdx.x * NTHREADS + threadIdx.x;       // 3B*64 float4s
    int m = g >> 6, k4 = g & 63;
    int v = m >> 12, b = m & (B - 1);
    const float* ha = g_scratch + OFF_H;
    const float* hb = ha + (long)B * 128;
    const float* xi = (v == 0) ? ha : hb;
    const float* xj = (v == 1) ? ha : hb;
    float4* P = reinterpret_cast<float4*>(g_scratch + OFF_P);
    float4 val;
    if (k4 < 32) val = *reinterpret_cast<const float4*>(&xi[(long)b * 128 + k4 * 4]);
    else         val = *reinterpret_cast<const float4*>(&xj[(long)b * 128 + (k4 - 32) * 4]);
    P[(long)m * 64 + k4] = val;
}

__global__ __launch_bounds__(NTHREADS) void pack2_kernel()
{
    // P[3B,256]: v0:[h_a, m_ab] v1:[h_b, m_ba+m_bb] v2:[h_b, 2*m_bb]
    int g = blockIdx.x * NTHREADS + threadIdx.x;
    int m = g >> 6, k4 = g & 63;
    int v = m >> 12, b = m & (B - 1);
    const float* ha  = g_scratch + OFF_H;
    const float* hb  = ha + (long)B * 128;
    const float* mab = g_scratch + OFF_M1;
    const float* mba = mab + (long)B * 128;
    const float* mbb = mba + (long)B * 128;
    float4* P = reinterpret_cast<float4*>(g_scratch + OFF_P);
    float4 val;
    if (k4 < 32) {
        const float* src = (v == 0) ? ha : hb;
        val = *reinterpret_cast<const float4*>(&src[(long)b * 128 + k4 * 4]);
    } else {
        long o = (long)b * 128 + (k4 - 32) * 4;
        if (v == 0) {
            val = *reinterpret_cast<const float4*>(&mab[o]);
        } else if (v == 1) {
            float4 a = *reinterpret_cast<const float4*>(&mba[o]);
            float4 c = *reinterpret_cast<const float4*>(&mbb[o]);
            val = make_float4(a.x + c.x, a.y + c.y, a.z + c.z, a.w + c.w);
        } else {
            float4 c = *reinterpret_cast<const float4*>(&mbb[o]);
            val = make_float4(2.f * c.x, 2.f * c.y, 2.f * c.z, 2.f * c.w);
        }
    }
    P[(long)m * 64 + k4] = val;
}

__global__ __launch_bounds__(NTHREADS) void mix_kernel()
{
    // umix = (2uA + 2uB + 60uC)/64 ; hmix = (2h_a + 62h_b)/64
    int g = blockIdx.x * NTHREADS + threadIdx.x;       // B*32 float4s
    const float4* uA = reinterpret_cast<const float4*>(g_scratch + OFF_U);
    const float4* uB = uA + (long)B * 32;
    const float4* uC = uB + (long)B * 32;
    const float4* ha = reinterpret_cast<const float4*>(g_scratch + OFF_H);
    const float4* hb = ha + (long)B * 32;
    float4 a = uA[g], b = uB[g], c = uC[g];
    float4 r;
    r.x = (2.f * (a.x + b.x) + 60.f * c.x) * (1.f / 64.f);
    r.y = (2.f * (a.y + b.y) + 60.f * c.y) * (1.f / 64.f);
    r.z = (2.f * (a.z + b.z) + 60.f * c.z) * (1.f / 64.f);
    r.w = (2.f * (a.w + b.w) + 60.f * c.w) * (1.f / 64.f);
    reinterpret_cast<float4*>(g_scratch + OFF_UMIX)[g] = r;
    float4 p = ha[g], q = hb[g];
    float4 r2;
    r2.x = (2.f * p.x + 62.f * q.x) * (1.f / 64.f);
    r2.y = (2.f * p.y + 62.f * q.y) * (1.f / 64.f);
    r2.z = (2.f * p.z + 62.f * q.z) * (1.f / 64.f);
    r2.w = (2.f * p.w + 62.f * q.w) * (1.f / 64.f);
    reinterpret_cast<float4*>(g_scratch + OFF_HMIX)[g] = r2;
}

// ---------------------------------------------------------------------------
// Launch
// ---------------------------------------------------------------------------
extern "C" void kernel_launch(void* const* d_in, const int* in_sizes, int n_in,
                              void* d_out, int out_size)
{
    const float* z0       = (const float*)d_in[0];
    const float* edge     = (const float*)d_in[3];
    const float* phiE_W1  = (const float*)d_in[4];
    const float* phiE_b1  = (const float*)d_in[5];
    const float* phiE_W2  = (const float*)d_in[6];
    const float* phiE_b2  = (const float*)d_in[7];
    const float* phiN_W1  = (const float*)d_in[8];
    const float* phiN_b1  = (const float*)d_in[9];
    const float* phiN_g   = (const float*)d_in[10];
    const float* phiN_be  = (const float*)d_in[11];
    const float* phiN_W2  = (const float*)d_in[12];
    const float* phiN_b2  = (const float*)d_in[13];
    const float* sh_W     = (const float*)d_in[14];
    const float* sh_b     = (const float*)d_in[15];
    const float* ln_g     = (const float*)d_in[16];
    const float* ln_b     = (const float*)d_in[17];
    const float* pol_W    = (const float*)d_in[18];
    const float* pol_b    = (const float*)d_in[19];
    const float* val_W    = (const float*)d_in[20];
    const float* val_b    = (const float*)d_in[21];
    float* outf = (float*)d_out;

    float* S = nullptr;
    cudaGetSymbolAddress((void**)&S, g_scratch);

    // --- k=0: folded edge MLP -> m0 ---
    prep_kernel<<<64, NTHREADS>>>(phiE_W1, phiE_b1, edge);
    layer_kernel<128, 64><<<B / 32, NTHREADS>>>(z0, S + OFF_WE0, S + OFF_BE0, S + OFF_T,
                                                nullptr, nullptr, nullptr, 1, 1);
    layer_kernel<128, 64><<<B / 32, NTHREADS>>>(S + OFF_T, phiE_W2, phiE_b2, S + OFF_M0,
                                                nullptr, nullptr, nullptr, 1, 0);
    // --- k=0 node update: two classes (deg 1 / deg 2) in one 2B GEMM ---
    pack0_kernel<<<2 * B * 64 / NTHREADS, NTHREADS>>>(z0);
    layer_kernel<256, 32><<<2 * B / 32, NTHREADS>>>(S + OFF_P, phiN_W1, phiN_b1, S + OFF_U,
                                                    phiN_g, phiN_be, nullptr, 1, 1);
    layer_kernel<128, 64><<<2 * B / 32, NTHREADS>>>(S + OFF_U, phiN_W2, phiN_b2, S + OFF_H,
                                                    nullptr, nullptr, z0, B, 0);
    // --- k=1 edge MLP: 3 class pairs in one 3B GEMM ---
    pack1_kernel<<<3 * B * 64 / NTHREADS, NTHREADS>>>();
    layer_kernel<256, 32><<<3 * B / 32, NTHREADS>>>(S + OFF_P, phiE_W1 + 257 * 128, S + OFF_BE1,
                                                    S + OFF_T, nullptr, nullptr, nullptr, 1, 1);
    layer_kernel<128, 64><<<3 * B / 32, NTHREADS>>>(S + OFF_T, phiE_W2 + 128 * 128,
                                                    phiE_b2 + 128, S + OFF_M1,
                                                    nullptr, nullptr, nullptr, 1, 0);
    // --- k=1 node hidden: 3 classes in one 3B GEMM ---
    pack2_kernel<<<3 * B * 64 / NTHREADS, NTHREADS>>>();
    layer_kernel<256, 32><<<3 * B / 32, NTHREADS>>>(S + OFF_P, phiN_W1 + 256 * 128,
                                                    phiN_b1 + 128, S + OFF_U,
                                                    phiN_g + 128, phiN_be + 128, nullptr, 1, 1);
    // --- fold node mean into a single GEMM: z_G = umix@W2 + b2 + hmix ---
    mix_kernel<<<B * 32 / NTHREADS, NTHREADS>>>();
    layer_kernel<128, 64><<<B / 32, NTHREADS>>>(S + OFF_UMIX, phiN_W2 + 128 * 128,
                                                phiN_b2 + 128, S + OFF_ZG,
                                                nullptr, nullptr, S + OFF_HMIX, B, 0);
    // --- heads ---
    sh_kernel<<<B / 32, NTHREADS>>>(S + OFF_ZG, sh_W, sh_b, ln_g, ln_b, S + OFF_X);
    pol_kernel<<<dim3(15, B / 64), NTHREADS>>>(S + OFF_X, pol_W, pol_b, outf);
    val_kernel<<<B / 8, NTHREADS>>>(S + OFF_X, val_W, val_b, outf + (long)B * 960);
}

// round 8
// speedup vs baseline: 1.1013x; 1.1013x over previous
#include <cuda_runtime.h>
#include <cuda_bf16.h>

#define B 4096
#define NTHREADS 256

// ---------------------------------------------------------------------------
// Scratch (no allocations allowed).
// ---------------------------------------------------------------------------
#define OFF_WE0   0            // 128x128 folded phiE k0 weight
#define OFF_BE0   16384        // 128 folded bias k0
#define OFF_BE1   16512        // 128 folded bias k1
#define OFF_T     16640        // 3B x 128  (MLP hidden temp)
#define OFF_M0    1589504      // B x 128   (k0 message)
#define OFF_U     5259520      // 3B x 128  (post-LN hidden)
#define OFF_H     6832384      // 2B x 128  (h_a, h_b)
#define OFF_M1    7880960      // 3B x 128  (m_ab, m_ba, m_bb)
#define OFF_UMIX  9453824      // B x 128
#define OFF_HMIX  9978112      // B x 128
#define OFF_ZG    10502400     // B x 128
#define OFF_X     11026688     // B x 256
#define SCRATCH_TOTAL 12075264

__device__ float g_scratch[SCRATCH_TOTAL];

// bf16 scratch: transposed/split pol weights + split x
#define OB_WTH 0               // [960,256] bf16 hi
#define OB_WTL 245760          // [960,256] bf16 lo
#define OB_XH  491520          // [B,256] bf16 hi
#define OB_XL  1540096         // [B,256] bf16 lo
#define BF_TOTAL 2588672
__device__ __nv_bfloat16 g_bf[BF_TOTAL];

// ---------------------------------------------------------------------------
// Prep: fold phiE k=0 weights and edge-attr bias terms.
// ---------------------------------------------------------------------------
__global__ __launch_bounds__(NTHREADS) void prep_kernel(
    const float* __restrict__ phiE_W1, const float* __restrict__ phiE_b1,
    const float* __restrict__ edge_attr)
{
    int i = blockIdx.x * NTHREADS + threadIdx.x;
    float e = edge_attr[0];
    if (i < 16384) {
        int r = i >> 7, c = i & 127;
        g_scratch[OFF_WE0 + i] = phiE_W1[r * 128 + c] + phiE_W1[(128 + r) * 128 + c];
    }
    if (i < 128) {
        g_scratch[OFF_BE0 + i] = phiE_b1[i]       + e * phiE_W1[256 * 128 + i];
        g_scratch[OFF_BE1 + i] = phiE_b1[128 + i] + e * phiE_W1[257 * 128 + 256 * 128 + i];
    }
}

// ---------------------------------------------------------------------------
// Transpose + bf16-split pol_W: W[256,960] fp32 -> WT hi/lo [960,256] bf16
// ---------------------------------------------------------------------------
__global__ void wsplit_kernel(const float* __restrict__ W)
{
    __shared__ float t[32][33];
    int kb = blockIdx.y * 32, nb = blockIdx.x * 32;
    int tx = threadIdx.x, ty = threadIdx.y;
    for (int j = ty; j < 32; j += 8)
        t[j][tx] = W[(long)(kb + j) * 960 + nb + tx];
    __syncthreads();
    for (int j = ty; j < 32; j += 8) {
        float v = t[tx][j];
        __nv_bfloat16 h = __float2bfloat16(v);
        long o = (long)(nb + j) * 256 + kb + tx;
        g_bf[OB_WTH + o] = h;
        g_bf[OB_WTL + o] = __float2bfloat16(v - __bfloat162float(h));
    }
}

// ---------------------------------------------------------------------------
// Generic fused layer (K=128): out[M,128] = epi(A @ W + bias)
// ---------------------------------------------------------------------------
__global__ __launch_bounds__(NTHREADS) void layer128_kernel(
    const float* __restrict__ A, const float* __restrict__ W,
    const float* __restrict__ bias, float* __restrict__ out,
    const float* __restrict__ resid, int resid_mod, int do_relu)
{
    __shared__ float As[32 * 128];
    __shared__ float Ws[64 * 128];
    const int tid = threadIdx.x;
    const int m0 = blockIdx.x * 32;
    {
        const float4* Ag = reinterpret_cast<const float4*>(A + (long)m0 * 128);
        float4* As4 = reinterpret_cast<float4*>(As);
        #pragma unroll
        for (int i = tid; i < 1024; i += NTHREADS) As4[i] = Ag[i];
    }
    const int lane = tid & 31, warp = tid >> 5;
    const int r0 = warp * 4, c0 = lane * 4;
    float acc[4][4];
    #pragma unroll
    for (int i = 0; i < 4; i++) { acc[i][0]=0.f; acc[i][1]=0.f; acc[i][2]=0.f; acc[i][3]=0.f; }

    for (int kc = 0; kc < 128; kc += 64) {
        __syncthreads();
        {
            const float4* Wg = reinterpret_cast<const float4*>(W + (long)kc * 128);
            float4* Ws4 = reinterpret_cast<float4*>(Ws);
            #pragma unroll
            for (int i = tid; i < 2048; i += NTHREADS) Ws4[i] = Wg[i];
        }
        __syncthreads();
        #pragma unroll 8
        for (int k = 0; k < 64; k++) {
            float4 wv = *reinterpret_cast<const float4*>(&Ws[k * 128 + c0]);
            #pragma unroll
            for (int i = 0; i < 4; i++) {
                float a = As[(r0 + i) * 128 + kc + k];
                acc[i][0] = fmaf(a, wv.x, acc[i][0]);
                acc[i][1] = fmaf(a, wv.y, acc[i][1]);
                acc[i][2] = fmaf(a, wv.z, acc[i][2]);
                acc[i][3] = fmaf(a, wv.w, acc[i][3]);
            }
        }
    }
    float4 bv = *reinterpret_cast<const float4*>(&bias[c0]);
    #pragma unroll
    for (int i = 0; i < 4; i++) {
        acc[i][0] += bv.x; acc[i][1] += bv.y; acc[i][2] += bv.z; acc[i][3] += bv.w;
    }
    if (do_relu) {
        #pragma unroll
        for (int i = 0; i < 4; i++) {
            acc[i][0] = fmaxf(acc[i][0], 0.f); acc[i][1] = fmaxf(acc[i][1], 0.f);
            acc[i][2] = fmaxf(acc[i][2], 0.f); acc[i][3] = fmaxf(acc[i][3], 0.f);
        }
    }
    if (resid != nullptr) {
        #pragma unroll
        for (int i = 0; i < 4; i++) {
            int row = m0 + r0 + i;
            float4 rv = *reinterpret_cast<const float4*>(&resid[(long)(row % resid_mod) * 128 + c0]);
            acc[i][0] += rv.x; acc[i][1] += rv.y; acc[i][2] += rv.z; acc[i][3] += rv.w;
        }
    }
    #pragma unroll
    for (int i = 0; i < 4; i++) {
        int row = m0 + r0 + i;
        *reinterpret_cast<float4*>(&out[(long)row * 128 + c0]) =
            make_float4(acc[i][0], acc[i][1], acc[i][2], acc[i][3]);
    }
}

// ---------------------------------------------------------------------------
// K=256 layer with FUSED pack: A row m (class v=m0>>12, b=m&4095) is
// [ f[v][b,:] , s[v]*(a[v][b,:] (+ bb[v][b,:])) ].  relu always; LN optional.
// ---------------------------------------------------------------------------
struct PackSrc {
    const float* f[3];
    const float* a[3];
    const float* bb[3];
    float s[3];
};

__global__ __launch_bounds__(NTHREADS) void layer256f_kernel(
    PackSrc ps, const float* __restrict__ W, const float* __restrict__ bias,
    float* __restrict__ out, const float* __restrict__ lng, const float* __restrict__ lnb)
{
    __shared__ float As[32 * 256];
    __shared__ float Ws[32 * 128];
    const int tid = threadIdx.x;
    const int m0 = blockIdx.x * 32;
    const int v = m0 >> 12;
    const float4* F  = reinterpret_cast<const float4*>(ps.f[v]);
    const float4* A1 = reinterpret_cast<const float4*>(ps.a[v]);
    const float4* A2 = reinterpret_cast<const float4*>(ps.bb[v]);
    const float s = ps.s[v];
    float4* As4 = reinterpret_cast<float4*>(As);
    #pragma unroll
    for (int i = tid; i < 2048; i += NTHREADS) {
        int r = i >> 6, k4 = i & 63;
        int b = (m0 + r) & (B - 1);
        float4 val;
        if (k4 < 32) {
            val = F[b * 32 + k4];
        } else {
            val = A1[b * 32 + (k4 - 32)];
            if (A2 != nullptr) {
                float4 w = A2[b * 32 + (k4 - 32)];
                val.x += w.x; val.y += w.y; val.z += w.z; val.w += w.w;
            }
            val.x *= s; val.y *= s; val.z *= s; val.w *= s;
        }
        As4[i] = val;
    }
    const int lane = tid & 31, warp = tid >> 5;
    const int r0 = warp * 4, c0 = lane * 4;
    float acc[4][4];
    #pragma unroll
    for (int i = 0; i < 4; i++) { acc[i][0]=0.f; acc[i][1]=0.f; acc[i][2]=0.f; acc[i][3]=0.f; }

    for (int kc = 0; kc < 256; kc += 32) {
        __syncthreads();
        {
            const float4* Wg = reinterpret_cast<const float4*>(W + (long)kc * 128);
            float4* Ws4 = reinterpret_cast<float4*>(Ws);
            #pragma unroll
            for (int i = tid; i < 1024; i += NTHREADS) Ws4[i] = Wg[i];
        }
        __syncthreads();
        #pragma unroll 8
        for (int k = 0; k < 32; k++) {
            float4 wv = *reinterpret_cast<const float4*>(&Ws[k * 128 + c0]);
            #pragma unroll
            for (int i = 0; i < 4; i++) {
                float a = As[(r0 + i) * 256 + kc + k];
                acc[i][0] = fmaf(a, wv.x, acc[i][0]);
                acc[i][1] = fmaf(a, wv.y, acc[i][1]);
                acc[i][2] = fmaf(a, wv.z, acc[i][2]);
                acc[i][3] = fmaf(a, wv.w, acc[i][3]);
            }
        }
    }
    float4 bv = *reinterpret_cast<const float4*>(&bias[c0]);
    #pragma unroll
    for (int i = 0; i < 4; i++) {
        acc[i][0] = fmaxf(acc[i][0] + bv.x, 0.f);
        acc[i][1] = fmaxf(acc[i][1] + bv.y, 0.f);
        acc[i][2] = fmaxf(acc[i][2] + bv.z, 0.f);
        acc[i][3] = fmaxf(acc[i][3] + bv.w, 0.f);
    }
    if (lng != nullptr) {
        float4 gv = *reinterpret_cast<const float4*>(&lng[c0]);
        float4 ev = *reinterpret_cast<const float4*>(&lnb[c0]);
        #pragma unroll
        for (int i = 0; i < 4; i++) {
            float su = acc[i][0] + acc[i][1] + acc[i][2] + acc[i][3];
            float q = acc[i][0]*acc[i][0] + acc[i][1]*acc[i][1] + acc[i][2]*acc[i][2] + acc[i][3]*acc[i][3];
            #pragma unroll
            for (int off = 16; off > 0; off >>= 1) {
                su += __shfl_xor_sync(0xffffffffu, su, off);
                q  += __shfl_xor_sync(0xffffffffu, q, off);
            }
            float mu = su * (1.f / 128.f);
            float var = q * (1.f / 128.f) - mu * mu;
            float rs = rsqrtf(var + 1e-5f);
            acc[i][0] = (acc[i][0] - mu) * rs * gv.x + ev.x;
            acc[i][1] = (acc[i][1] - mu) * rs * gv.y + ev.y;
            acc[i][2] = (acc[i][2] - mu) * rs * gv.z + ev.z;
            acc[i][3] = (acc[i][3] - mu) * rs * gv.w + ev.w;
        }
    }
    #pragma unroll
    for (int i = 0; i < 4; i++) {
        int row = m0 + r0 + i;
        *reinterpret_cast<float4*>(&out[(long)row * 128 + c0]) =
            make_float4(acc[i][0], acc[i][1], acc[i][2], acc[i][3]);
    }
}

// ---------------------------------------------------------------------------
// Shared head: x = LN256(relu(zg @ sh_W + sh_b)); emits fp32 x + bf16 hi/lo
// ---------------------------------------------------------------------------
__global__ __launch_bounds__(NTHREADS) void sh_kernel(
    const float* __restrict__ A, const float* __restrict__ W,
    const float* __restrict__ bias, const float* __restrict__ lng,
    const float* __restrict__ lnb, float* __restrict__ out,
    __nv_bfloat16* __restrict__ xh, __nv_bfloat16* __restrict__ xl)
{
    __shared__ float As[32 * 128];
    __shared__ float Ws[32 * 256];
    const int tid = threadIdx.x;
    const int m0 = blockIdx.x * 32;
    {
        const float4* Ag = reinterpret_cast<const float4*>(A + (long)m0 * 128);
        float4* As4 = reinterpret_cast<float4*>(As);
        #pragma unroll
        for (int i = tid; i < 1024; i += NTHREADS) As4[i] = Ag[i];
    }
    const int lane = tid & 31, warp = tid >> 5;
    const int r0 = warp * 4, c0 = lane * 4, c1 = 128 + lane * 4;
    float acc[4][8];
    #pragma unroll
    for (int i = 0; i < 4; i++)
        #pragma unroll
        for (int j = 0; j < 8; j++) acc[i][j] = 0.f;

    for (int kc = 0; kc < 128; kc += 32) {
        __syncthreads();
        {
            const float4* Wg = reinterpret_cast<const float4*>(W + (long)kc * 256);
            float4* Ws4 = reinterpret_cast<float4*>(Ws);
            #pragma unroll
            for (int i = tid; i < 2048; i += NTHREADS) Ws4[i] = Wg[i];
        }
        __syncthreads();
        #pragma unroll 4
        for (int k = 0; k < 32; k++) {
            float4 w0 = *reinterpret_cast<const float4*>(&Ws[k * 256 + c0]);
            float4 w1 = *reinterpret_cast<const float4*>(&Ws[k * 256 + c1]);
            #pragma unroll
            for (int i = 0; i < 4; i++) {
                float a = As[(r0 + i) * 128 + kc + k];
                acc[i][0] = fmaf(a, w0.x, acc[i][0]); acc[i][1] = fmaf(a, w0.y, acc[i][1]);
                acc[i][2] = fmaf(a, w0.z, acc[i][2]); acc[i][3] = fmaf(a, w0.w, acc[i][3]);
                acc[i][4] = fmaf(a, w1.x, acc[i][4]); acc[i][5] = fmaf(a, w1.y, acc[i][5]);
                acc[i][6] = fmaf(a, w1.z, acc[i][6]); acc[i][7] = fmaf(a, w1.w, acc[i][7]);
            }
        }
    }
    float4 bv0 = *reinterpret_cast<const float4*>(&bias[c0]);
    float4 bv1 = *reinterpret_cast<const float4*>(&bias[c1]);
    float4 g0 = *reinterpret_cast<const float4*>(&lng[c0]);
    float4 g1 = *reinterpret_cast<const float4*>(&lng[c1]);
    float4 e0 = *reinterpret_cast<const float4*>(&lnb[c0]);
    float4 e1 = *reinterpret_cast<const float4*>(&lnb[c1]);
    #pragma unroll
    for (int i = 0; i < 4; i++) {
        acc[i][0] = fmaxf(acc[i][0] + bv0.x, 0.f); acc[i][1] = fmaxf(acc[i][1] + bv0.y, 0.f);
        acc[i][2] = fmaxf(acc[i][2] + bv0.z, 0.f); acc[i][3] = fmaxf(acc[i][3] + bv0.w, 0.f);
        acc[i][4] = fmaxf(acc[i][4] + bv1.x, 0.f); acc[i][5] = fmaxf(acc[i][5] + bv1.y, 0.f);
        acc[i][6] = fmaxf(acc[i][6] + bv1.z, 0.f); acc[i][7] = fmaxf(acc[i][7] + bv1.w, 0.f);
        float s = 0.f, q = 0.f;
        #pragma unroll
        for (int j = 0; j < 8; j++) { s += acc[i][j]; q += acc[i][j] * acc[i][j]; }
        #pragma unroll
        for (int off = 16; off > 0; off >>= 1) {
            s += __shfl_xor_sync(0xffffffffu, s, off);
            q += __shfl_xor_sync(0xffffffffu, q, off);
        }
        float mu = s * (1.f / 256.f);
        float var = q * (1.f / 256.f) - mu * mu;
        float rs = rsqrtf(var + 1e-5f);
        acc[i][0] = (acc[i][0]-mu)*rs*g0.x + e0.x; acc[i][1] = (acc[i][1]-mu)*rs*g0.y + e0.y;
        acc[i][2] = (acc[i][2]-mu)*rs*g0.z + e0.z; acc[i][3] = (acc[i][3]-mu)*rs*g0.w + e0.w;
        acc[i][4] = (acc[i][4]-mu)*rs*g1.x + e1.x; acc[i][5] = (acc[i][5]-mu)*rs*g1.y + e1.y;
        acc[i][6] = (acc[i][6]-mu)*rs*g1.z + e1.z; acc[i][7] = (acc[i][7]-mu)*rs*g1.w + e1.w;
        int row = m0 + r0 + i;
        *reinterpret_cast<float4*>(&out[(long)row * 256 + c0]) =
            make_float4(acc[i][0], acc[i][1], acc[i][2], acc[i][3]);
        *reinterpret_cast<float4*>(&out[(long)row * 256 + c1]) =
            make_float4(acc[i][4], acc[i][5], acc[i][6], acc[i][7]);
        __nv_bfloat162* XH = reinterpret_cast<__nv_bfloat162*>(xh + (long)row * 256);
        __nv_bfloat162* XL = reinterpret_cast<__nv_bfloat162*>(xl + (long)row * 256);
        #pragma unroll
        for (int j = 0; j < 2; j++) {
            float va = acc[i][j*2], vb = acc[i][j*2+1];
            __nv_bfloat16 ha = __float2bfloat16(va), hb = __float2bfloat16(vb);
            __nv_bfloat162 hp; hp.x = ha; hp.y = hb;
            XH[lane * 2 + j] = hp;
            __nv_bfloat162 lp;
            lp.x = __float2bfloat16(va - __bfloat162float(ha));
            lp.y = __float2bfloat16(vb - __bfloat162float(hb));
            XL[lane * 2 + j] = lp;
            float vc = acc[i][4 + j*2], vd = acc[i][4 + j*2+1];
            __nv_bfloat16 hc = __float2bfloat16(vc), hd = __float2bfloat16(vd);
            __nv_bfloat162 hp2; hp2.x = hc; hp2.y = hd;
            XH[64 + lane * 2 + j] = hp2;
            __nv_bfloat162 lp2;
            lp2.x = __float2bfloat16(vc - __bfloat162float(hc));
            lp2.y = __float2bfloat16(vd - __bfloat162float(hd));
            XL[64 + lane * 2 + j] = lp2;
        }
    }
}

// ---------------------------------------------------------------------------
// Policy head via mma.sync bf16-split (baseline PTX; works under compute_103).
// D = Xhi*Whi^T + Xhi*Wlo^T + Xlo*Whi^T  (lo*lo dropped, err ~2^-16)
// Block tile 128(m) x 64(n); 8 warps as 4m x 2n; warp tile 32x32.
// A = X [B,256] row-major (K contig); B = WT [960,256] row-major (K contig)
// -> mma row.col, both operands loaded with non-trans ldmatrix.
// ---------------------------------------------------------------------------
#define PAD 72   // 64 bf16 + 8 pad -> 144B row stride, conflict-free ldmatrix

__device__ __forceinline__ unsigned smem_u32(const void* p) {
    unsigned a;
    asm("{ .reg .u64 t; cvta.to.shared.u64 t, %1; cvt.u32.u64 %0, t; }" : "=r"(a) : "l"(p));
    return a;
}

__global__ __launch_bounds__(NTHREADS) void pol_mma_kernel(
    const __nv_bfloat16* __restrict__ Xhi, const __nv_bfloat16* __restrict__ Xlo,
    const __nv_bfloat16* __restrict__ Whi, const __nv_bfloat16* __restrict__ Wlo,
    const float* __restrict__ bias, float* __restrict__ out)
{
    __shared__ __align__(16) __nv_bfloat16 As[128 * PAD];
    __shared__ __align__(16) __nv_bfloat16 Bs[64 * PAD];
    const int tid = threadIdx.x;
    const int lane = tid & 31, w = tid >> 5;
    const int wm = (w & 3) * 32, wn = (w >> 2) * 32;
    const int m0 = blockIdx.y * 128, n0 = blockIdx.x * 64;

    float acc[2][4][4];
    #pragma unroll
    for (int mt = 0; mt < 2; mt++)
        #pragma unroll
        for (int nt = 0; nt < 4; nt++)
            #pragma unroll
            for (int q = 0; q < 4; q++) acc[mt][nt][q] = 0.f;

    const __nv_bfloat16* Aps[3] = {Xhi, Xhi, Xlo};
    const __nv_bfloat16* Bps[3] = {Whi, Wlo, Whi};

    const unsigned a_base = smem_u32(As);
    const unsigned b_base = smem_u32(Bs);
    const int lrow = lane & 15, lcol8 = (lane >> 4) * 8;

    for (int p = 0; p < 3; p++) {
        const __nv_bfloat16* Ap = Aps[p];
        const __nv_bfloat16* Bp = Bps[p];
        for (int kc = 0; kc < 256; kc += 64) {
            __syncthreads();
            #pragma unroll
            for (int i = tid; i < 1024; i += NTHREADS) {
                int r = i >> 3, c8 = i & 7;
                *reinterpret_cast<uint4*>(&As[r * PAD + c8 * 8]) =
                    *reinterpret_cast<const uint4*>(&Ap[(long)(m0 + r) * 256 + kc + c8 * 8]);
            }
            #pragma unroll
            for (int i = tid; i < 512; i += NTHREADS) {
                int r = i >> 3, c8 = i & 7;
                *reinterpret_cast<uint4*>(&Bs[r * PAD + c8 * 8]) =
                    *reinterpret_cast<const uint4*>(&Bp[(long)(n0 + r) * 256 + kc + c8 * 8]);
            }
            __syncthreads();
            #pragma unroll
            for (int k16 = 0; k16 < 4; k16++) {
                unsigned a[2][4];
                #pragma unroll
                for (int mt = 0; mt < 2; mt++) {
                    unsigned addr = a_base +
                        ((wm + mt * 16 + lrow) * PAD + k16 * 16 + lcol8) * 2;
                    asm volatile("ldmatrix.sync.aligned.m8n8.x4.shared.b16 "
                                 "{%0,%1,%2,%3}, [%4];"
                                 : "=r"(a[mt][0]), "=r"(a[mt][1]),
                                   "=r"(a[mt][2]), "=r"(a[mt][3]) : "r"(addr));
                }
                unsigned b[4][2];
                #pragma unroll
                for (int nh = 0; nh < 2; nh++) {
                    unsigned r0, r1, r2, r3;
                    unsigned addr = b_base +
                        ((wn + nh * 16 + lrow) * PAD + k16 * 16 + lcol8) * 2;
                    asm volatile("ldmatrix.sync.aligned.m8n8.x4.shared.b16 "
                                 "{%0,%1,%2,%3}, [%4];"
                                 : "=r"(r0), "=r"(r1), "=r"(r2), "=r"(r3) : "r"(addr));
                    b[nh * 2 + 0][0] = r0; b[nh * 2 + 0][1] = r2;
                    b[nh * 2 + 1][0] = r1; b[nh * 2 + 1][1] = r3;
                }
                #pragma unroll
                for (int mt = 0; mt < 2; mt++)
                    #pragma unroll
                    for (int nt = 0; nt < 4; nt++) {
                        asm volatile(
                            "mma.sync.aligned.m16n8k16.row.col.f32.bf16.bf16.f32 "
                            "{%0,%1,%2,%3}, {%4,%5,%6,%7}, {%8,%9}, {%0,%1,%2,%3};"
                            : "+f"(acc[mt][nt][0]), "+f"(acc[mt][nt][1]),
                              "+f"(acc[mt][nt][2]), "+f"(acc[mt][nt][3])
                            : "r"(a[mt][0]), "r"(a[mt][1]), "r"(a[mt][2]), "r"(a[mt][3]),
                              "r"(b[nt][0]), "r"(b[nt][1]));
                    }
            }
        }
    }
    const int gid = lane >> 2, tq = (lane & 3) * 2;
    #pragma unroll
    for (int mt = 0; mt < 2; mt++) {
        #pragma unroll
        for (int nt = 0; nt < 4; nt++) {
            int col = n0 + wn + nt * 8 + tq;
            float bx = bias[col], by = bias[col + 1];
            int row0 = m0 + wm + mt * 16 + gid;
            float2 v0 = make_float2(acc[mt][nt][0] + bx, acc[mt][nt][1] + by);
            float2 v1 = make_float2(acc[mt][nt][2] + bx, acc[mt][nt][3] + by);
            *reinterpret_cast<float2*>(&out[(long)row0 * 960 + col]) = v0;
            *reinterpret_cast<float2*>(&out[(long)(row0 + 8) * 960 + col]) = v1;
        }
    }
}

// ---------------------------------------------------------------------------
// Value head
// ---------------------------------------------------------------------------
__global__ __launch_bounds__(NTHREADS) void val_kernel(
    const float* __restrict__ x, const float* __restrict__ vW,
    const float* __restrict__ vb, float* __restrict__ V)
{
    int warp = threadIdx.x >> 5, lane = threadIdx.x & 31;
    int m = blockIdx.x * 8 + warp;
    float s = 0.f;
    #pragma unroll
    for (int k = lane; k < 256; k += 32) s += x[(long)m * 256 + k] * vW[k];
    #pragma unroll
    for (int off = 16; off > 0; off >>= 1) s += __shfl_xor_sync(0xffffffffu, s, off);
    if (lane == 0) V[m] = s + vb[0];
}

// ---------------------------------------------------------------------------
// umix = (2uA + 2uB + 60uC)/64 ; hmix = (2h_a + 62h_b)/64
// ---------------------------------------------------------------------------
__global__ __launch_bounds__(NTHREADS) void mix_kernel()
{
    int g = blockIdx.x * NTHREADS + threadIdx.x;
    const float4* uA = reinterpret_cast<const float4*>(g_scratch + OFF_U);
    const float4* uB = uA + (long)B * 32;
    const float4* uC = uB + (long)B * 32;
    const float4* ha = reinterpret_cast<const float4*>(g_scratch + OFF_H);
    const float4* hb = ha + (long)B * 32;
    float4 a = uA[g], b = uB[g], c = uC[g];
    float4 r;
    r.x = (2.f*(a.x+b.x) + 60.f*c.x) * (1.f/64.f);
    r.y = (2.f*(a.y+b.y) + 60.f*c.y) * (1.f/64.f);
    r.z = (2.f*(a.z+b.z) + 60.f*c.z) * (1.f/64.f);
    r.w = (2.f*(a.w+b.w) + 60.f*c.w) * (1.f/64.f);
    reinterpret_cast<float4*>(g_scratch + OFF_UMIX)[g] = r;
    float4 p = ha[g], q = hb[g];
    float4 r2;
    r2.x = (2.f*p.x + 62.f*q.x) * (1.f/64.f);
    r2.y = (2.f*p.y + 62.f*q.y) * (1.f/64.f);
    r2.z = (2.f*p.z + 62.f*q.z) * (1.f/64.f);
    r2.w = (2.f*p.w + 62.f*q.w) * (1.f/64.f);
    reinterpret_cast<float4*>(g_scratch + OFF_HMIX)[g] = r2;
}

// ---------------------------------------------------------------------------
// Launch
// ---------------------------------------------------------------------------
extern "C" void kernel_launch(void* const* d_in, const int* in_sizes, int n_in,
                              void* d_out, int out_size)
{
    const float* z0       = (const float*)d_in[0];
    const float* edge     = (const float*)d_in[3];
    const float* phiE_W1  = (const float*)d_in[4];
    const float* phiE_b1  = (const float*)d_in[5];
    const float* phiE_W2  = (const float*)d_in[6];
    const float* phiE_b2  = (const float*)d_in[7];
    const float* phiN_W1  = (const float*)d_in[8];
    const float* phiN_b1  = (const float*)d_in[9];
    const float* phiN_g   = (const float*)d_in[10];
    const float* phiN_be  = (const float*)d_in[11];
    const float* phiN_W2  = (const float*)d_in[12];
    const float* phiN_b2  = (const float*)d_in[13];
    const float* sh_W     = (const float*)d_in[14];
    const float* sh_b     = (const float*)d_in[15];
    const float* ln_g     = (const float*)d_in[16];
    const float* ln_b     = (const float*)d_in[17];
    const float* pol_W    = (const float*)d_in[18];
    const float* pol_b    = (const float*)d_in[19];
    const float* val_W    = (const float*)d_in[20];
    const float* val_b    = (const float*)d_in[21];
    float* outf = (float*)d_out;

    float* S = nullptr;
    cudaGetSymbolAddress((void**)&S, g_scratch);
    __nv_bfloat16* Bf = nullptr;
    cudaGetSymbolAddress((void**)&Bf, g_bf);

    const float* ha  = S + OFF_H;
    const float* hb  = ha + (long)B * 128;
    const float* mab = S + OFF_M1;
    const float* mba = mab + (long)B * 128;
    const float* mbb = mba + (long)B * 128;
    const float* m0p = S + OFF_M0;

    // --- prep: fold k0 edge weights + transpose/split pol_W ---
    prep_kernel<<<64, NTHREADS>>>(phiE_W1, phiE_b1, edge);
    wsplit_kernel<<<dim3(30, 8), dim3(32, 8)>>>(pol_W);

    // --- k=0 edge MLP (folded): m0 ---
    layer128_kernel<<<B / 32, NTHREADS>>>(z0, S + OFF_WE0, S + OFF_BE0, S + OFF_T,
                                          nullptr, 1, 1);
    layer128_kernel<<<B / 32, NTHREADS>>>(S + OFF_T, phiE_W2, phiE_b2, S + OFF_M0,
                                          nullptr, 1, 0);
    // --- k=0 node update (fused pack): 2 classes ---
    {
        PackSrc ps;
        ps.f[0] = z0;  ps.f[1] = z0;  ps.f[2] = z0;
        ps.a[0] = m0p; ps.a[1] = m0p; ps.a[2] = m0p;
        ps.bb[0] = nullptr; ps.bb[1] = nullptr; ps.bb[2] = nullptr;
        ps.s[0] = 1.f; ps.s[1] = 2.f; ps.s[2] = 1.f;
        layer256f_kernel<<<2 * B / 32, NTHREADS>>>(ps, phiN_W1, phiN_b1, S + OFF_U,
                                                   phiN_g, phiN_be);
    }
    layer128_kernel<<<2 * B / 32, NTHREADS>>>(S + OFF_U, phiN_W2, phiN_b2, S + OFF_H,
                                              z0, B, 0);
    // --- k=1 edge MLP (fused pack): 3 class pairs ---
    {
        PackSrc ps;
        ps.f[0] = ha; ps.f[1] = hb; ps.f[2] = hb;
        ps.a[0] = hb; ps.a[1] = ha; ps.a[2] = hb;
        ps.bb[0] = nullptr; ps.bb[1] = nullptr; ps.bb[2] = nullptr;
        ps.s[0] = 1.f; ps.s[1] = 1.f; ps.s[2] = 1.f;
        layer256f_kernel<<<3 * B / 32, NTHREADS>>>(ps, phiE_W1 + 257 * 128, S + OFF_BE1,
                                                   S + OFF_T, nullptr, nullptr);
    }
    layer128_kernel<<<3 * B / 32, NTHREADS>>>(S + OFF_T, phiE_W2 + 128 * 128,
                                              phiE_b2 + 128, S + OFF_M1, nullptr, 1, 0);
    // --- k=1 node hidden (fused pack): 3 classes ---
    {
        PackSrc ps;
        ps.f[0] = ha;  ps.f[1] = hb;  ps.f[2] = hb;
        ps.a[0] = mab; ps.a[1] = mba; ps.a[2] = mbb;
        ps.bb[0] = nullptr; ps.bb[1] = mbb; ps.bb[2] = nullptr;
        ps.s[0] = 1.f; ps.s[1] = 1.f; ps.s[2] = 2.f;
        layer256f_kernel<<<3 * B / 32, NTHREADS>>>(ps, phiN_W1 + 256 * 128, phiN_b1 + 128,
                                                   S + OFF_U, phiN_g + 128, phiN_be + 128);
    }
    // --- fold node-mean into one GEMM ---
    mix_kernel<<<B * 32 / NTHREADS, NTHREADS>>>();
    layer128_kernel<<<B / 32, NTHREADS>>>(S + OFF_UMIX, phiN_W2 + 128 * 128,
                                          phiN_b2 + 128, S + OFF_ZG, S + OFF_HMIX, B, 0);
    // --- heads ---
    sh_kernel<<<B / 32, NTHREADS>>>(S + OFF_ZG, sh_W, sh_b, ln_g, ln_b, S + OFF_X,
                                    Bf + OB_XH, Bf + OB_XL);
    pol_mma_kernel<<<dim3(960 / 64, B / 128), NTHREADS>>>(
        Bf + OB_XH, Bf + OB_XL, Bf + OB_WTH, Bf + OB_WTL, pol_b, outf);
    val_kernel<<<B / 8, NTHREADS>>>(S + OFF_X, val_W, val_b, outf + (long)B * 960);
}

// round 11
// speedup vs baseline: 1.4253x; 1.2943x over previous
#include <cuda_runtime.h>
#include <cuda_bf16.h>

#define B 4096
#define NTHREADS 256

// ---------------------------------------------------------------------------
// fp32 scratch
// ---------------------------------------------------------------------------
#define OFF_BE0   16384        // 128 folded bias k0
#define OFF_BE1   16512        // 128 folded bias k1
#define OFF_T     16640        // 3B x 128
#define OFF_M0    1589504      // B x 128
#define OFF_U     5259520      // 3B x 128
#define OFF_H     6832384      // 2B x 128
#define OFF_M1    7880960      // 3B x 128
#define OFF_UMIX  9453824      // B x 128
#define OFF_HMIX  9978112      // B x 128
#define OFF_ZG    10502400     // B x 128
#define OFF_X     11026688     // B x 256
#define SCRATCH_TOTAL 12075264
__device__ float g_scratch[SCRATCH_TOTAL];

// bf16 scratch
#define OB_WTH 0               // pol WT hi [960,256]
#define OB_WTL 245760          // pol WT lo
#define OB_XH  491520          // x hi [B,256]
#define OB_XL  1540096         // x lo
#define WB     2588672         // backbone weights (transposed, hi/lo)
#define WB_WE0H (WB+0)
#define WB_WE0L (WB+16384)
#define WB_E2AH (WB+32768)
#define WB_E2AL (WB+49152)
#define WB_N1AH (WB+65536)
#define WB_N1AL (WB+98304)
#define WB_N2AH (WB+131072)
#define WB_N2AL (WB+147456)
#define WB_E1BH (WB+163840)
#define WB_E1BL (WB+196608)
#define WB_E2BH (WB+229376)
#define WB_E2BL (WB+245760+16384)   // 262144... compute: 229376+16384=245760 conflicts? no: lo=245760+16384
#define BF_TOTAL 3014656
__device__ __nv_bfloat16 g_bf[BF_TOTAL];

// explicit offsets (avoid macro arithmetic mistakes)
// job0 WE0T  hi WB+0       lo WB+16384
// job1 E2k0T hi WB+32768   lo WB+49152
// job2 N1k0T hi WB+65536   lo WB+98304
// job3 N2k0T hi WB+131072  lo WB+147456
// job4 E1k1T hi WB+163840  lo WB+196608
// job5 E2k1T hi WB+229376  lo WB+245760
// job6 N1k1T hi WB+262144  lo WB+294912
// job7 N2k1T hi WB+327680  lo WB+344064
// job8 shWT  hi WB+360448  lo WB+393216   (end WB+425984 = 3014656)

__device__ __forceinline__ unsigned smem_u32(const void* p) {
    unsigned a;
    asm("{ .reg .u64 t; cvta.to.shared.u64 t, %1; cvt.u32.u64 %0, t; }" : "=r"(a) : "l"(p));
    return a;
}

// ---------------------------------------------------------------------------
// Prep: folded edge-bias terms (fp32)
// ---------------------------------------------------------------------------
__global__ __launch_bounds__(128) void prep_kernel(
    const float* __restrict__ phiE_W1, const float* __restrict__ phiE_b1,
    const float* __restrict__ edge_attr)
{
    int i = threadIdx.x;
    float e = edge_attr[0];
    g_scratch[OFF_BE0 + i] = phiE_b1[i]       + e * phiE_W1[256 * 128 + i];
    g_scratch[OFF_BE1 + i] = phiE_b1[128 + i] + e * phiE_W1[257 * 128 + 256 * 128 + i];
}

// ---------------------------------------------------------------------------
// Batched weight transpose + bf16 split: src [K,N] fp32 -> dst [N,K] bf16 hi/lo
// ---------------------------------------------------------------------------
struct WJob { const float* src; const float* src2; int K; int N; long dstHi; long dstLo; };
struct WJobs { WJob j[9]; };

__global__ void wsplitT_kernel(WJobs jobs)
{
    WJob jb = jobs.j[blockIdx.z];
    int kb = blockIdx.y * 32, nb = blockIdx.x * 32;
    if (kb >= jb.K || nb >= jb.N) return;
    __shared__ float t[32][33];
    int tx = threadIdx.x, ty = threadIdx.y;
    for (int j = ty; j < 32; j += 8) {
        float v = jb.src[(long)(kb + j) * jb.N + nb + tx];
        if (jb.src2) v += jb.src2[(long)(kb + j) * jb.N + nb + tx];
        t[j][tx] = v;
    }
    __syncthreads();
    for (int j = ty; j < 32; j += 8) {
        float v = t[tx][j];
        __nv_bfloat16 h = __float2bfloat16(v);
        long o = (long)(nb + j) * jb.K + kb + tx;
        g_bf[jb.dstHi + o] = h;
        g_bf[jb.dstLo + o] = __float2bfloat16(v - __bfloat162float(h));
    }
}

// pol weight transpose+split (960 cols)
__global__ void wsplit_kernel(const float* __restrict__ W)
{
    __shared__ float t[32][33];
    int kb = blockIdx.y * 32, nb = blockIdx.x * 32;
    int tx = threadIdx.x, ty = threadIdx.y;
    for (int j = ty; j < 32; j += 8)
        t[j][tx] = W[(long)(kb + j) * 960 + nb + tx];
    __syncthreads();
    for (int j = ty; j < 32; j += 8) {
        float v = t[tx][j];
        __nv_bfloat16 h = __float2bfloat16(v);
        long o = (long)(nb + j) * 256 + kb + tx;
        g_bf[OB_WTH + o] = h;
        g_bf[OB_WTL + o] = __float2bfloat16(v - __bfloat162float(h));
    }
}

// ---------------------------------------------------------------------------
// Backbone mma layer: out[M,128] = epi(A[M,K] @ W[K,128] + bias)
// A fp32 (pack-fused, split to bf16 hi/lo at load); W pre-split [128,K] bf16.
// 3-pass split product: hi*hi + hi*lo + lo*hi.
// Block 64m x 128n, 8 warps (2m x 4n), warp tile 32x32, K-chunk 32.
// ---------------------------------------------------------------------------
struct PackSrc {
    const float* f[3];
    const float* a[3];
    const float* bb[3];
    float s[3];
};

#define APAD 40
#define SM_ALO 5120
#define SM_WHI 10240
#define SM_WLO 20480
#define SM_TOT 33792   // >= max(tiles 30720, C stage 64*132*4=33792)

template<int K, bool PACK>
__global__ __launch_bounds__(NTHREADS) void mlayer_kernel(
    PackSrc ps, const __nv_bfloat16* __restrict__ WhiT,
    const __nv_bfloat16* __restrict__ WloT,
    const float* __restrict__ bias, float* __restrict__ out,
    const float* __restrict__ lng, const float* __restrict__ lnb,
    const float* __restrict__ resid, int resid_mod, int do_relu)
{
    __shared__ __align__(16) char sm[SM_TOT];
    __nv_bfloat16* sAhi = reinterpret_cast<__nv_bfloat16*>(sm);
    __nv_bfloat16* sAlo = reinterpret_cast<__nv_bfloat16*>(sm + SM_ALO);
    __nv_bfloat16* sWhi = reinterpret_cast<__nv_bfloat16*>(sm + SM_WHI);
    __nv_bfloat16* sWlo = reinterpret_cast<__nv_bfloat16*>(sm + SM_WLO);
    const int tid = threadIdx.x, lane = tid & 31, w = tid >> 5;
    const int m0 = blockIdx.x * 64;
    const int v = m0 >> 12;
    const float4* F  = reinterpret_cast<const float4*>(ps.f[v]);
    const float4* A1 = reinterpret_cast<const float4*>(ps.a[v]);
    const float4* A2 = reinterpret_cast<const float4*>(ps.bb[v]);
    const float s = ps.s[v];
    const int wm = (w & 1) * 32, wn = (w >> 1) * 32;

    float acc[2][4][4];
    #pragma unroll
    for (int mt = 0; mt < 2; mt++)
        #pragma unroll
        for (int nt = 0; nt < 4; nt++)
            #pragma unroll
            for (int q = 0; q < 4; q++) acc[mt][nt][q] = 0.f;

    const unsigned ahB = smem_u32(sAhi), alB = smem_u32(sAlo);
    const unsigned whB = smem_u32(sWhi), wlB = smem_u32(sWlo);
    const int lrow = lane & 15, lcol8 = (lane >> 4) * 8;

    for (int kc = 0; kc < K; kc += 32) {
        __syncthreads();
        // A: 64 rows x 8 float4, fp32 -> bf16 hi/lo split into smem
        #pragma unroll
        for (int i = tid; i < 512; i += NTHREADS) {
            int r = i >> 3, c4 = i & 7;
            int b = (m0 + r) & (B - 1);
            int kk4 = (kc >> 2) + c4;
            float4 val;
            if (!PACK || kk4 < 32) {
                val = F[(long)b * 32 + kk4];
            } else {
                val = A1[(long)b * 32 + kk4 - 32];
                if (A2 != nullptr) {
                    float4 t2 = A2[(long)b * 32 + kk4 - 32];
                    val.x += t2.x; val.y += t2.y; val.z += t2.z; val.w += t2.w;
                }
                val.x *= s; val.y *= s; val.z *= s; val.w *= s;
            }
            __nv_bfloat16 h0 = __float2bfloat16(val.x), h1 = __float2bfloat16(val.y);
            __nv_bfloat16 h2 = __float2bfloat16(val.z), h3 = __float2bfloat16(val.w);
            __nv_bfloat162 hp0; hp0.x = h0; hp0.y = h1;
            __nv_bfloat162 hp1; hp1.x = h2; hp1.y = h3;
            int o = r * APAD + c4 * 4;
            *reinterpret_cast<__nv_bfloat162*>(&sAhi[o])     = hp0;
            *reinterpret_cast<__nv_bfloat162*>(&sAhi[o + 2]) = hp1;
            __nv_bfloat162 lp0, lp1;
            lp0.x = __float2bfloat16(val.x - __bfloat162float(h0));
            lp0.y = __float2bfloat16(val.y - __bfloat162float(h1));
            lp1.x = __float2bfloat16(val.z - __bfloat162float(h2));
            lp1.y = __float2bfloat16(val.w - __bfloat162float(h3));
            *reinterpret_cast<__nv_bfloat162*>(&sAlo[o])     = lp0;
            *reinterpret_cast<__nv_bfloat162*>(&sAlo[o + 2]) = lp1;
        }
        // W: 128 rows x 32 cols bf16, hi+lo
        #pragma unroll
        for (int i = tid; i < 1024; i += NTHREADS) {
            int mtx = i >> 9;
            int r = (i >> 2) & 127, c8 = i & 3;
            const __nv_bfloat16* src = mtx ? WloT : WhiT;
            __nv_bfloat16* dst = mtx ? sWlo : sWhi;
            *reinterpret_cast<uint4*>(&dst[r * APAD + c8 * 8]) =
                *reinterpret_cast<const uint4*>(&src[(long)r * K + kc + c8 * 8]);
        }
        __syncthreads();
        #pragma unroll
        for (int k16 = 0; k16 < 2; k16++) {
            unsigned ah[2][4], al[2][4];
            #pragma unroll
            for (int mt = 0; mt < 2; mt++) {
                unsigned off = ((wm + mt * 16 + lrow) * APAD + k16 * 16 + lcol8) * 2;
                asm volatile("ldmatrix.sync.aligned.m8n8.x4.shared.b16 {%0,%1,%2,%3}, [%4];"
                             : "=r"(ah[mt][0]), "=r"(ah[mt][1]), "=r"(ah[mt][2]), "=r"(ah[mt][3])
                             : "r"(ahB + off));
                asm volatile("ldmatrix.sync.aligned.m8n8.x4.shared.b16 {%0,%1,%2,%3}, [%4];"
                             : "=r"(al[mt][0]), "=r"(al[mt][1]), "=r"(al[mt][2]), "=r"(al[mt][3])
                             : "r"(alB + off));
            }
            unsigned bh[4][2], bl[4][2];
            #pragma unroll
            for (int nh = 0; nh < 2; nh++) {
                unsigned off = ((wn + nh * 16 + lrow) * APAD + k16 * 16 + lcol8) * 2;
                unsigned r0, r1, r2, r3;
                asm volatile("ldmatrix.sync.aligned.m8n8.x4.shared.b16 {%0,%1,%2,%3}, [%4];"
                             : "=r"(r0), "=r"(r1), "=r"(r2), "=r"(r3) : "r"(whB + off));
                bh[nh*2+0][0] = r0; bh[nh*2+0][1] = r2;
                bh[nh*2+1][0] = r1; bh[nh*2+1][1] = r3;
                asm volatile("ldmatrix.sync.aligned.m8n8.x4.shared.b16 {%0,%1,%2,%3}, [%4];"
                             : "=r"(r0), "=r"(r1), "=r"(r2), "=r"(r3) : "r"(wlB + off));
                bl[nh*2+0][0] = r0; bl[nh*2+0][1] = r2;
                bl[nh*2+1][0] = r1; bl[nh*2+1][1] = r3;
            }
            #pragma unroll
            for (int mt = 0; mt < 2; mt++)
                #pragma unroll
                for (int nt = 0; nt < 4; nt++) {
                    asm volatile(
                        "mma.sync.aligned.m16n8k16.row.col.f32.bf16.bf16.f32 "
                        "{%0,%1,%2,%3}, {%4,%5,%6,%7}, {%8,%9}, {%0,%1,%2,%3};"
                        : "+f"(acc[mt][nt][0]), "+f"(acc[mt][nt][1]),
                          "+f"(acc[mt][nt][2]), "+f"(acc[mt][nt][3])
                        : "r"(ah[mt][0]), "r"(ah[mt][1]), "r"(ah[mt][2]), "r"(ah[mt][3]),
                          "r"(bh[nt][0]), "r"(bh[nt][1]));
                    asm volatile(
                        "mma.sync.aligned.m16n8k16.row.col.f32.bf16.bf16.f32 "
                        "{%0,%1,%2,%3}, {%4,%5,%6,%7}, {%8,%9}, {%0,%1,%2,%3};"
                        : "+f"(acc[mt][nt][0]), "+f"(acc[mt][nt][1]),
                          "+f"(acc[mt][nt][2]), "+f"(acc[mt][nt][3])
                        : "r"(ah[mt][0]), "r"(ah[mt][1]), "r"(ah[mt][2]), "r"(ah[mt][3]),
                          "r"(bl[nt][0]), "r"(bl[nt][1]));
                    asm volatile(
                        "mma.sync.aligned.m16n8k16.row.col.f32.bf16.bf16.f32 "
                        "{%0,%1,%2,%3}, {%4,%5,%6,%7}, {%8,%9}, {%0,%1,%2,%3};"
                        : "+f"(acc[mt][nt][0]), "+f"(acc[mt][nt][1]),
                          "+f"(acc[mt][nt][2]), "+f"(acc[mt][nt][3])
                        : "r"(al[mt][0]), "r"(al[mt][1]), "r"(al[mt][2]), "r"(al[mt][3]),
                          "r"(bh[nt][0]), "r"(bh[nt][1]));
                }
        }
    }

    // stage accums to smem (C 64x132 fp32), then row-wise fp32 epilogue
    __syncthreads();
    float* Cs = reinterpret_cast<float*>(sm);
    const int gid = lane >> 2, tq = (lane & 3) * 2;
    #pragma unroll
    for (int mt = 0; mt < 2; mt++)
        #pragma unroll
        for (int nt = 0; nt < 4; nt++) {
            int r = wm + mt * 16 + gid, c = wn + nt * 8 + tq;
            Cs[r * 132 + c]           = acc[mt][nt][0];
            Cs[r * 132 + c + 1]       = acc[mt][nt][1];
            Cs[(r + 8) * 132 + c]     = acc[mt][nt][2];
            Cs[(r + 8) * 132 + c + 1] = acc[mt][nt][3];
        }
    __syncthreads();

    float4 bv = *reinterpret_cast<const float4*>(&bias[lane * 4]);
    #pragma unroll
    for (int rr = 0; rr < 8; rr++) {
        int r = w * 8 + rr;
        int row = m0 + r;
        float4 vv = *reinterpret_cast<float4*>(&Cs[r * 132 + lane * 4]);
        vv.x += bv.x; vv.y += bv.y; vv.z += bv.z; vv.w += bv.w;
        if (do_relu) {
            vv.x = fmaxf(vv.x, 0.f); vv.y = fmaxf(vv.y, 0.f);
            vv.z = fmaxf(vv.z, 0.f); vv.w = fmaxf(vv.w, 0.f);
        }
        if (lng != nullptr) {
            float su = vv.x + vv.y + vv.z + vv.w;
            float q = vv.x*vv.x + vv.y*vv.y + vv.z*vv.z + vv.w*vv.w;
            #pragma unroll
            for (int off = 16; off > 0; off >>= 1) {
                su += __shfl_xor_sync(0xffffffffu, su, off);
                q  += __shfl_xor_sync(0xffffffffu, q, off);
            }
            float mu = su * (1.f / 128.f);
            float var = q * (1.f / 128.f) - mu * mu;
            float rs = rsqrtf(var + 1e-5f);
            float4 gv = *reinterpret_cast<const float4*>(&lng[lane * 4]);
            float4 ev = *reinterpret_cast<const float4*>(&lnb[lane * 4]);
            vv.x = (vv.x - mu) * rs * gv.x + ev.x;
            vv.y = (vv.y - mu) * rs * gv.y + ev.y;
            vv.z = (vv.z - mu) * rs * gv.z + ev.z;
            vv.w = (vv.w - mu) * rs * gv.w + ev.w;
        }
        if (resid != nullptr) {
            float4 rv = *reinterpret_cast<const float4*>(
                &resid[(long)(row % resid_mod) * 128 + lane * 4]);
            vv.x += rv.x; vv.y += rv.y; vv.z += rv.z; vv.w += rv.w;
        }
        *reinterpret_cast<float4*>(&out[(long)row * 128 + lane * 4]) = vv;
    }
}

// ---------------------------------------------------------------------------
// Shared head (SIMT): x = LN256(relu(zg @ sh_W + sh_b)); emits fp32 + bf16 hi/lo
// ---------------------------------------------------------------------------
__global__ __launch_bounds__(NTHREADS) void sh_kernel(
    const float* __restrict__ A, const float* __restrict__ W,
    const float* __restrict__ bias, const float* __restrict__ lng,
    const float* __restrict__ lnb, float* __restrict__ out,
    __nv_bfloat16* __restrict__ xh, __nv_bfloat16* __restrict__ xl)
{
    __shared__ float As[32 * 128];
    __shared__ float Ws[32 * 256];
    const int tid = threadIdx.x;
    const int m0 = blockIdx.x * 32;
    {
        const float4* Ag = reinterpret_cast<const float4*>(A + (long)m0 * 128);
        float4* As4 = reinterpret_cast<float4*>(As);
        #pragma unroll
        for (int i = tid; i < 1024; i += NTHREADS) As4[i] = Ag[i];
    }
    const int lane = tid & 31, warp = tid >> 5;
    const int r0 = warp * 4, c0 = lane * 4, c1 = 128 + lane * 4;
    float acc[4][8];
    #pragma unroll
    for (int i = 0; i < 4; i++)
        #pragma unroll
        for (int j = 0; j < 8; j++) acc[i][j] = 0.f;

    for (int kc = 0; kc < 128; kc += 32) {
        __syncthreads();
        {
            const float4* Wg = reinterpret_cast<const float4*>(W + (long)kc * 256);
            float4* Ws4 = reinterpret_cast<float4*>(Ws);
            #pragma unroll
            for (int i = tid; i < 2048; i += NTHREADS) Ws4[i] = Wg[i];
        }
        __syncthreads();
        #pragma unroll 4
        for (int k = 0; k < 32; k++) {
            float4 w0 = *reinterpret_cast<const float4*>(&Ws[k * 256 + c0]);
            float4 w1 = *reinterpret_cast<const float4*>(&Ws[k * 256 + c1]);
            #pragma unroll
            for (int i = 0; i < 4; i++) {
                float a = As[(r0 + i) * 128 + kc + k];
                acc[i][0] = fmaf(a, w0.x, acc[i][0]); acc[i][1] = fmaf(a, w0.y, acc[i][1]);
                acc[i][2] = fmaf(a, w0.z, acc[i][2]); acc[i][3] = fmaf(a, w0.w, acc[i][3]);
                acc[i][4] = fmaf(a, w1.x, acc[i][4]); acc[i][5] = fmaf(a, w1.y, acc[i][5]);
                acc[i][6] = fmaf(a, w1.z, acc[i][6]); acc[i][7] = fmaf(a, w1.w, acc[i][7]);
            }
        }
    }
    float4 bv0 = *reinterpret_cast<const float4*>(&bias[c0]);
    float4 bv1 = *reinterpret_cast<const float4*>(&bias[c1]);
    float4 g0 = *reinterpret_cast<const float4*>(&lng[c0]);
    float4 g1 = *reinterpret_cast<const float4*>(&lng[c1]);
    float4 e0 = *reinterpret_cast<const float4*>(&lnb[c0]);
    float4 e1 = *reinterpret_cast<const float4*>(&lnb[c1]);
    #pragma unroll
    for (int i = 0; i < 4; i++) {
        acc[i][0] = fmaxf(acc[i][0] + bv0.x, 0.f); acc[i][1] = fmaxf(acc[i][1] + bv0.y, 0.f);
        acc[i][2] = fmaxf(acc[i][2] + bv0.z, 0.f); acc[i][3] = fmaxf(acc[i][3] + bv0.w, 0.f);
        acc[i][4] = fmaxf(acc[i][4] + bv1.x, 0.f); acc[i][5] = fmaxf(acc[i][5] + bv1.y, 0.f);
        acc[i][6] = fmaxf(acc[i][6] + bv1.z, 0.f); acc[i][7] = fmaxf(acc[i][7] + bv1.w, 0.f);
        float s = 0.f, q = 0.f;
        #pragma unroll
        for (int j = 0; j < 8; j++) { s += acc[i][j]; q += acc[i][j] * acc[i][j]; }
        #pragma unroll
        for (int off = 16; off > 0; off >>= 1) {
            s += __shfl_xor_sync(0xffffffffu, s, off);
            q += __shfl_xor_sync(0xffffffffu, q, off);
        }
        float mu = s * (1.f / 256.f);
        float var = q * (1.f / 256.f) - mu * mu;
        float rs = rsqrtf(var + 1e-5f);
        acc[i][0] = (acc[i][0]-mu)*rs*g0.x + e0.x; acc[i][1] = (acc[i][1]-mu)*rs*g0.y + e0.y;
        acc[i][2] = (acc[i][2]-mu)*rs*g0.z + e0.z; acc[i][3] = (acc[i][3]-mu)*rs*g0.w + e0.w;
        acc[i][4] = (acc[i][4]-mu)*rs*g1.x + e1.x; acc[i][5] = (acc[i][5]-mu)*rs*g1.y + e1.y;
        acc[i][6] = (acc[i][6]-mu)*rs*g1.z + e1.z; acc[i][7] = (acc[i][7]-mu)*rs*g1.w + e1.w;
        int row = m0 + r0 + i;
        *reinterpret_cast<float4*>(&out[(long)row * 256 + c0]) =
            make_float4(acc[i][0], acc[i][1], acc[i][2], acc[i][3]);
        *reinterpret_cast<float4*>(&out[(long)row * 256 + c1]) =
            make_float4(acc[i][4], acc[i][5], acc[i][6], acc[i][7]);
        __nv_bfloat162* XH = reinterpret_cast<__nv_bfloat162*>(xh + (long)row * 256);
        __nv_bfloat162* XL = reinterpret_cast<__nv_bfloat162*>(xl + (long)row * 256);
        #pragma unroll
        for (int j = 0; j < 2; j++) {
            float va = acc[i][j*2], vb = acc[i][j*2+1];
            __nv_bfloat16 ha = __float2bfloat16(va), hb = __float2bfloat16(vb);
            __nv_bfloat162 hp; hp.x = ha; hp.y = hb;
            XH[lane * 2 + j] = hp;
            __nv_bfloat162 lp;
            lp.x = __float2bfloat16(va - __bfloat162float(ha));
            lp.y = __float2bfloat16(vb - __bfloat162float(hb));
            XL[lane * 2 + j] = lp;
            float vc = acc[i][4 + j*2], vd = acc[i][4 + j*2+1];
            __nv_bfloat16 hc = __float2bfloat16(vc), hd = __float2bfloat16(vd);
            __nv_bfloat162 hp2; hp2.x = hc; hp2.y = hd;
            XH[64 + lane * 2 + j] = hp2;
            __nv_bfloat162 lp2;
            lp2.x = __float2bfloat16(vc - __bfloat162float(hc));
            lp2.y = __float2bfloat16(vd - __bfloat162float(hd));
            XL[64 + lane * 2 + j] = lp2;
        }
    }
}

// ---------------------------------------------------------------------------
// Policy head mma (validated round 8)
// ---------------------------------------------------------------------------
#define PPAD 72

__global__ __launch_bounds__(NTHREADS) void pol_mma_kernel(
    const __nv_bfloat16* __restrict__ Xhi, const __nv_bfloat16* __restrict__ Xlo,
    const __nv_bfloat16* __restrict__ Whi, const __nv_bfloat16* __restrict__ Wlo,
    const float* __restrict__ bias, float* __restrict__ out)
{
    __shared__ __align__(16) __nv_bfloat16 As[128 * PPAD];
    __shared__ __align__(16) __nv_bfloat16 Bs[64 * PPAD];
    const int tid = threadIdx.x;
    const int lane = tid & 31, w = tid >> 5;
    const int wm = (w & 3) * 32, wn = (w >> 2) * 32;
    const int m0 = blockIdx.y * 128, n0 = blockIdx.x * 64;

    float acc[2][4][4];
    #pragma unroll
    for (int mt = 0; mt < 2; mt++)
        #pragma unroll
        for (int nt = 0; nt < 4; nt++)
            #pragma unroll
            for (int q = 0; q < 4; q++) acc[mt][nt][q] = 0.f;

    const __nv_bfloat16* Aps[3] = {Xhi, Xhi, Xlo};
    const __nv_bfloat16* Bps[3] = {Whi, Wlo, Whi};

    const unsigned a_base = smem_u32(As);
    const unsigned b_base = smem_u32(Bs);
    const int lrow = lane & 15, lcol8 = (lane >> 4) * 8;

    for (int p = 0; p < 3; p++) {
        const __nv_bfloat16* Ap = Aps[p];
        const __nv_bfloat16* Bp = Bps[p];
        for (int kc = 0; kc < 256; kc += 64) {
            __syncthreads();
            #pragma unroll
            for (int i = tid; i < 1024; i += NTHREADS) {
                int r = i >> 3, c8 = i & 7;
                *reinterpret_cast<uint4*>(&As[r * PPAD + c8 * 8]) =
                    *reinterpret_cast<const uint4*>(&Ap[(long)(m0 + r) * 256 + kc + c8 * 8]);
            }
            #pragma unroll
            for (int i = tid; i < 512; i += NTHREADS) {
                int r = i >> 3, c8 = i & 7;
                *reinterpret_cast<uint4*>(&Bs[r * PPAD + c8 * 8]) =
                    *reinterpret_cast<const uint4*>(&Bp[(long)(n0 + r) * 256 + kc + c8 * 8]);
            }
            __syncthreads();
            #pragma unroll
            for (int k16 = 0; k16 < 4; k16++) {
                unsigned a[2][4];
                #pragma unroll
                for (int mt = 0; mt < 2; mt++) {
                    unsigned addr = a_base +
                        ((wm + mt * 16 + lrow) * PPAD + k16 * 16 + lcol8) * 2;
                    asm volatile("ldmatrix.sync.aligned.m8n8.x4.shared.b16 "
                                 "{%0,%1,%2,%3}, [%4];"
                                 : "=r"(a[mt][0]), "=r"(a[mt][1]),
                                   "=r"(a[mt][2]), "=r"(a[mt][3]) : "r"(addr));
                }
                unsigned b[4][2];
                #pragma unroll
                for (int nh = 0; nh < 2; nh++) {
                    unsigned r0, r1, r2, r3;
                    unsigned addr = b_base +
                        ((wn + nh * 16 + lrow) * PPAD + k16 * 16 + lcol8) * 2;
                    asm volatile("ldmatrix.sync.aligned.m8n8.x4.shared.b16 "
                                 "{%0,%1,%2,%3}, [%4];"
                                 : "=r"(r0), "=r"(r1), "=r"(r2), "=r"(r3) : "r"(addr));
                    b[nh * 2 + 0][0] = r0; b[nh * 2 + 0][1] = r2;
                    b[nh * 2 + 1][0] = r1; b[nh * 2 + 1][1] = r3;
                }
                #pragma unroll
                for (int mt = 0; mt < 2; mt++)
                    #pragma unroll
                    for (int nt = 0; nt < 4; nt++) {
                        asm volatile(
                            "mma.sync.aligned.m16n8k16.row.col.f32.bf16.bf16.f32 "
                            "{%0,%1,%2,%3}, {%4,%5,%6,%7}, {%8,%9}, {%0,%1,%2,%3};"
                            : "+f"(acc[mt][nt][0]), "+f"(acc[mt][nt][1]),
                              "+f"(acc[mt][nt][2]), "+f"(acc[mt][nt][3])
                            : "r"(a[mt][0]), "r"(a[mt][1]), "r"(a[mt][2]), "r"(a[mt][3]),
                              "r"(b[nt][0]), "r"(b[nt][1]));
                    }
            }
        }
    }
    const int gid = lane >> 2, tq = (lane & 3) * 2;
    #pragma unroll
    for (int mt = 0; mt < 2; mt++) {
        #pragma unroll
        for (int nt = 0; nt < 4; nt++) {
            int col = n0 + wn + nt * 8 + tq;
            float bx = bias[col], by = bias[col + 1];
            int row0 = m0 + wm + mt * 16 + gid;
            float2 v0 = make_float2(acc[mt][nt][0] + bx, acc[mt][nt][1] + by);
            float2 v1 = make_float2(acc[mt][nt][2] + bx, acc[mt][nt][3] + by);
            *reinterpret_cast<float2*>(&out[(long)row0 * 960 + col]) = v0;
            *reinterpret_cast<float2*>(&out[(long)(row0 + 8) * 960 + col]) = v1;
        }
    }
}

// ---------------------------------------------------------------------------
// Value head
// ---------------------------------------------------------------------------
__global__ __launch_bounds__(NTHREADS) void val_kernel(
    const float* __restrict__ x, const float* __restrict__ vW,
    const float* __restrict__ vb, float* __restrict__ V)
{
    int warp = threadIdx.x >> 5, lane = threadIdx.x & 31;
    int m = blockIdx.x * 8 + warp;
    float s = 0.f;
    #pragma unroll
    for (int k = lane; k < 256; k += 32) s += x[(long)m * 256 + k] * vW[k];
    #pragma unroll
    for (int off = 16; off > 0; off >>= 1) s += __shfl_xor_sync(0xffffffffu, s, off);
    if (lane == 0) V[m] = s + vb[0];
}

// ---------------------------------------------------------------------------
// umix = (2uA + 2uB + 60uC)/64 ; hmix = (2h_a + 62h_b)/64
// ---------------------------------------------------------------------------
__global__ __launch_bounds__(NTHREADS) void mix_kernel()
{
    int g = blockIdx.x * NTHREADS + threadIdx.x;
    const float4* uA = reinterpret_cast<const float4*>(g_scratch + OFF_U);
    const float4* uB = uA + (long)B * 32;
    const float4* uC = uB + (long)B * 32;
    const float4* ha = reinterpret_cast<const float4*>(g_scratch + OFF_H);
    const float4* hb = ha + (long)B * 32;
    float4 a = uA[g], b = uB[g], c = uC[g];
    float4 r;
    r.x = (2.f*(a.x+b.x) + 60.f*c.x) * (1.f/64.f);
    r.y = (2.f*(a.y+b.y) + 60.f*c.y) * (1.f/64.f);
    r.z = (2.f*(a.z+b.z) + 60.f*c.z) * (1.f/64.f);
    r.w = (2.f*(a.w+b.w) + 60.f*c.w) * (1.f/64.f);
    reinterpret_cast<float4*>(g_scratch + OFF_UMIX)[g] = r;
    float4 p = ha[g], q = hb[g];
    float4 r2;
    r2.x = (2.f*p.x + 62.f*q.x) * (1.f/64.f);
    r2.y = (2.f*p.y + 62.f*q.y) * (1.f/64.f);
    r2.z = (2.f*p.z + 62.f*q.z) * (1.f/64.f);
    r2.w = (2.f*p.w + 62.f*q.w) * (1.f/64.f);
    reinterpret_cast<float4*>(g_scratch + OFF_HMIX)[g] = r2;
}

// ---------------------------------------------------------------------------
// Launch
// ---------------------------------------------------------------------------
extern "C" void kernel_launch(void* const* d_in, const int* in_sizes, int n_in,
                              void* d_out, int out_size)
{
    const float* z0       = (const float*)d_in[0];
    const float* edge     = (const float*)d_in[3];
    const float* phiE_W1  = (const float*)d_in[4];
    const float* phiE_b1  = (const float*)d_in[5];
    const float* phiE_W2  = (const float*)d_in[6];
    const float* phiE_b2  = (const float*)d_in[7];
    const float* phiN_W1  = (const float*)d_in[8];
    const float* phiN_b1  = (const float*)d_in[9];
    const float* phiN_g   = (const float*)d_in[10];
    const float* phiN_be  = (const float*)d_in[11];
    const float* phiN_W2  = (const float*)d_in[12];
    const float* phiN_b2  = (const float*)d_in[13];
    const float* sh_W     = (const float*)d_in[14];
    const float* sh_b     = (const float*)d_in[15];
    const float* ln_g     = (const float*)d_in[16];
    const float* ln_b     = (const float*)d_in[17];
    const float* pol_W    = (const float*)d_in[18];
    const float* pol_b    = (const float*)d_in[19];
    const float* val_W    = (const float*)d_in[20];
    const float* val_b    = (const float*)d_in[21];
    float* outf = (float*)d_out;

    float* S = nullptr;
    cudaGetSymbolAddress((void**)&S, g_scratch);
    __nv_bfloat16* Bf = nullptr;
    cudaGetSymbolAddress((void**)&Bf, g_bf);

    const float* ha  = S + OFF_H;
    const float* hb  = ha + (long)B * 128;
    const float* mab = S + OFF_M1;
    const float* mba = mab + (long)B * 128;
    const float* mbb = mba + (long)B * 128;
    const float* m0p = S + OFF_M0;
    const float* T   = S + OFF_T;
    const float* U   = S + OFF_U;

    // --- prep + weight splits ---
    prep_kernel<<<1, 128>>>(phiE_W1, phiE_b1, edge);
    wsplit_kernel<<<dim3(30, 8), dim3(32, 8)>>>(pol_W);
    {
        WJobs jb;
        jb.j[0] = { phiE_W1,                 phiE_W1 + 128*128, 128, 128, WB+0,      WB+16384 };
        jb.j[1] = { phiE_W2,                 nullptr,           128, 128, WB+32768,  WB+49152 };
        jb.j[2] = { phiN_W1,                 nullptr,           256, 128, WB+65536,  WB+98304 };
        jb.j[3] = { phiN_W2,                 nullptr,           128, 128, WB+131072, WB+147456 };
        jb.j[4] = { phiE_W1 + 257*128,       nullptr,           256, 128, WB+163840, WB+196608 };
        jb.j[5] = { phiE_W2 + 128*128,       nullptr,           128, 128, WB+229376, WB+245760 };
        jb.j[6] = { phiN_W1 + 256*128,       nullptr,           256, 128, WB+262144, WB+294912 };
        jb.j[7] = { phiN_W2 + 128*128,       nullptr,           128, 128, WB+327680, WB+344064 };
        jb.j[8] = { sh_W,                    nullptr,           128, 256, WB+360448, WB+393216 };
        wsplitT_kernel<<<dim3(8, 8, 9), dim3(32, 8)>>>(jb);
    }

    PackSrc p0; for (int i = 0; i < 3; i++) { p0.f[i]=nullptr; p0.a[i]=nullptr; p0.bb[i]=nullptr; p0.s[i]=1.f; }

    // 1: z0 @ WE0T -> T (relu)
    { PackSrc p = p0; p.f[0] = z0;
      mlayer_kernel<128,false><<<B/64, NTHREADS>>>(p, Bf+WB+0, Bf+WB+16384,
          S+OFF_BE0, S+OFF_T, nullptr, nullptr, nullptr, 1, 1); }
    // 2: T @ E2k0 -> M0
    { PackSrc p = p0; p.f[0] = T;
      mlayer_kernel<128,false><<<B/64, NTHREADS>>>(p, Bf+WB+32768, Bf+WB+49152,
          phiE_b2, S+OFF_M0, nullptr, nullptr, nullptr, 1, 0); }
    // 3: pack0 @ N1k0 -> U (relu+LN), M=2B
    { PackSrc p = p0;
      p.f[0]=z0; p.f[1]=z0; p.a[0]=m0p; p.a[1]=m0p; p.s[0]=1.f; p.s[1]=2.f;
      mlayer_kernel<256,true><<<2*B/64, NTHREADS>>>(p, Bf+WB+65536, Bf+WB+98304,
          phiN_b1, S+OFF_U, phiN_g, phiN_be, nullptr, 1, 1); }
    // 4: U @ N2k0 + z0 -> H, M=2B
    { PackSrc p = p0; p.f[0]=U; p.f[1]=U + (long)B*128;
      mlayer_kernel<128,false><<<2*B/64, NTHREADS>>>(p, Bf+WB+131072, Bf+WB+147456,
          phiN_b2, S+OFF_H, nullptr, nullptr, z0, B, 0); }
    // 5: pack1 @ E1k1 -> T (relu), M=3B
    { PackSrc p = p0;
      p.f[0]=ha; p.f[1]=hb; p.f[2]=hb; p.a[0]=hb; p.a[1]=ha; p.a[2]=hb;
      mlayer_kernel<256,true><<<3*B/64, NTHREADS>>>(p, Bf+WB+163840, Bf+WB+196608,
          S+OFF_BE1, S+OFF_T, nullptr, nullptr, nullptr, 1, 1); }
    // 6: T @ E2k1 -> M1, M=3B
    { PackSrc p = p0;
      p.f[0]=T; p.f[1]=T + (long)B*128; p.f[2]=T + (long)2*B*128;
      mlayer_kernel<128,false><<<3*B/64, NTHREADS>>>(p, Bf+WB+229376, Bf+WB+245760,
          phiE_b2 + 128, S+OFF_M1, nullptr, nullptr, nullptr, 1, 0); }
    // 7: pack2 @ N1k1 -> U (relu+LN), M=3B
    { PackSrc p = p0;
      p.f[0]=ha; p.f[1]=hb; p.f[2]=hb;
      p.a[0]=mab; p.a[1]=mba; p.a[2]=mbb;
      p.bb[1]=mbb; p.s[2]=2.f;
      mlayer_kernel<256,true><<<3*B/64, NTHREADS>>>(p, Bf+WB+262144, Bf+WB+294912,
          phiN_b1 + 128, S+OFF_U, phiN_g + 128, phiN_be + 128, nullptr, 1, 1); }
    // 8: mix
    mix_kernel<<<B * 32 / NTHREADS, NTHREADS>>>();
    // 9: umix @ N2k1 + hmix -> ZG
    { PackSrc p = p0; p.f[0] = S + OFF_UMIX;
      mlayer_kernel<128,false><<<B/64, NTHREADS>>>(p, Bf+WB+327680, Bf+WB+344064,
          phiN_b2 + 128, S+OFF_ZG, nullptr, nullptr, S+OFF_HMIX, B, 0); }
    // heads
    sh_kernel<<<B/32, NTHREADS>>>(S + OFF_ZG, sh_W, sh_b, ln_g, ln_b, S + OFF_X,
                                  Bf + OB_XH, Bf + OB_XL);
    pol_mma_kernel<<<dim3(960/64, B/128), NTHREADS>>>(
        Bf + OB_XH, Bf + OB_XL, Bf + OB_WTH, Bf + OB_WTL, pol_b, outf);
    val_kernel<<<B/8, NTHREADS>>>(S + OFF_X, val_W, val_b, outf + (long)B * 960);
}

// round 13
// speedup vs baseline: 1.6747x; 1.1750x over previous
#include <cuda_runtime.h>
#include <cuda_bf16.h>

#define B 4096
#define NTHREADS 256

// ---------------------------------------------------------------------------
// fp32 scratch
// ---------------------------------------------------------------------------
#define OFF_BE0   16384        // 128 folded bias k0
#define OFF_BE1   16512        // 128 folded bias k1
#define OFF_ZG    10502400     // B x 128
#define OFF_X     11026688     // B x 256
#define SCRATCH_TOTAL 12075264
__device__ float g_scratch[SCRATCH_TOTAL];

// bf16 scratch
#define OB_WTH 0               // pol WT hi [960,256]
#define OB_WTL 245760          // pol WT lo
#define OB_XH  491520          // x hi [B,256]
#define OB_XL  1540096         // x lo
#define WB     2588672         // backbone weights (transposed, hi/lo)
#define BF_TOTAL 3014656
__device__ __nv_bfloat16 g_bf[BF_TOTAL];

// job0 WE0T  hi WB+0       lo WB+16384
// job1 E2k0T hi WB+32768   lo WB+49152
// job2 N1k0T hi WB+65536   lo WB+98304
// job3 N2k0T hi WB+131072  lo WB+147456
// job4 E1k1T hi WB+163840  lo WB+196608
// job5 E2k1T hi WB+229376  lo WB+245760
// job6 N1k1T hi WB+262144  lo WB+294912
// job7 N2k1T hi WB+327680  lo WB+344064
// job8 shWT  hi WB+360448  lo WB+393216

__device__ __forceinline__ unsigned smem_u32(const void* p) {
    unsigned a;
    asm("{ .reg .u64 t; cvta.to.shared.u64 t, %1; cvt.u32.u64 %0, t; }" : "=r"(a) : "l"(p));
    return a;
}
__device__ __forceinline__ void cpasync16(void* dst, const void* g) {
    asm volatile("cp.async.ca.shared.global [%0], [%1], 16;"
                 :: "r"(smem_u32(dst)), "l"(g));
}

// ---------------------------------------------------------------------------
// Prep: folded edge-bias terms
// ---------------------------------------------------------------------------
__global__ __launch_bounds__(128) void prep_kernel(
    const float* __restrict__ phiE_W1, const float* __restrict__ phiE_b1,
    const float* __restrict__ edge_attr)
{
    int i = threadIdx.x;
    float e = edge_attr[0];
    g_scratch[OFF_BE0 + i] = phiE_b1[i]       + e * phiE_W1[256 * 128 + i];
    g_scratch[OFF_BE1 + i] = phiE_b1[128 + i] + e * phiE_W1[257 * 128 + 256 * 128 + i];
}

// ---------------------------------------------------------------------------
// Batched weight transpose + bf16 split: src [K,N] fp32 -> dst [N,K] bf16 hi/lo
// ---------------------------------------------------------------------------
struct WJob { const float* src; const float* src2; int K; int N; long dstHi; long dstLo; };
struct WJobs { WJob j[9]; };

__global__ void wsplitT_kernel(WJobs jobs)
{
    WJob jb = jobs.j[blockIdx.z];
    int kb = blockIdx.y * 32, nb = blockIdx.x * 32;
    if (kb >= jb.K || nb >= jb.N) return;
    __shared__ float t[32][33];
    int tx = threadIdx.x, ty = threadIdx.y;
    for (int j = ty; j < 32; j += 8) {
        float v = jb.src[(long)(kb + j) * jb.N + nb + tx];
        if (jb.src2) v += jb.src2[(long)(kb + j) * jb.N + nb + tx];
        t[j][tx] = v;
    }
    __syncthreads();
    for (int j = ty; j < 32; j += 8) {
        float v = t[tx][j];
        __nv_bfloat16 h = __float2bfloat16(v);
        long o = (long)(nb + j) * jb.K + kb + tx;
        g_bf[jb.dstHi + o] = h;
        g_bf[jb.dstLo + o] = __float2bfloat16(v - __bfloat162float(h));
    }
}

__global__ void wsplit_kernel(const float* __restrict__ W)
{
    __shared__ float t[32][33];
    int kb = blockIdx.y * 32, nb = blockIdx.x * 32;
    int tx = threadIdx.x, ty = threadIdx.y;
    for (int j = ty; j < 32; j += 8)
        t[j][tx] = W[(long)(kb + j) * 960 + nb + tx];
    __syncthreads();
    for (int j = ty; j < 32; j += 8) {
        float v = t[tx][j];
        __nv_bfloat16 h = __float2bfloat16(v);
        long o = (long)(nb + j) * 256 + kb + tx;
        g_bf[OB_WTH + o] = h;
        g_bf[OB_WTL + o] = __float2bfloat16(v - __bfloat162float(h));
    }
}

// ---------------------------------------------------------------------------
// MEGAKERNEL: entire backbone (8 GEMMs + mix) per 32-row batch slice,
// intermediates in smem, weights streamed via cp.async double buffer.
// ---------------------------------------------------------------------------
#define APAD 40
#define SM_MEGA 219136

struct SP {     // fp32 intermediates in smem (float4 views)
    float4* z0s;  // 32 x 32
    float4* H;    // 64 x 32
    float4* M;    // 96 x 32
    float4* U;    // 96 x 32
};
struct ST {     // bf16 staging (double buffered)
    __nv_bfloat16* Ah[2]; __nv_bfloat16* Al[2];
    __nv_bfloat16* Wh[2]; __nv_bfloat16* Wl[2];
};

__device__ __forceinline__ float4 getA(int ph, const SP& sp, int r, int kk4)
{
    int v = r >> 5, b = r & 31;
    switch (ph) {
    case 1: return sp.z0s[b * 32 + kk4];
    case 3:
        if (kk4 < 32) return sp.z0s[b * 32 + kk4];
        else {
            float4 m = sp.M[b * 32 + kk4 - 32];
            if (v == 1) { m.x *= 2.f; m.y *= 2.f; m.z *= 2.f; m.w *= 2.f; }
            return m;
        }
    case 5: {
        int cls = (kk4 < 32) ? (v == 0 ? 0 : 1) : (v == 1 ? 0 : 1);
        int k = (kk4 < 32) ? kk4 : kk4 - 32;
        return sp.H[(cls * 32 + b) * 32 + k];
    }
    case 7:
        if (kk4 < 32) return sp.H[((v == 0 ? 0 : 1) * 32 + b) * 32 + kk4];
        else {
            int k = kk4 - 32;
            if (v == 0) return sp.M[b * 32 + k];
            if (v == 1) {
                float4 a = sp.M[(32 + b) * 32 + k], c = sp.M[(64 + b) * 32 + k];
                return make_float4(a.x + c.x, a.y + c.y, a.z + c.z, a.w + c.w);
            }
            float4 c = sp.M[(64 + b) * 32 + k];
            return make_float4(2.f * c.x, 2.f * c.y, 2.f * c.z, 2.f * c.w);
        }
    case 9: return sp.M[b * 32 + kk4];           // umix
    default: return sp.U[r * 32 + kk4];          // cases 2,4,6: U/T rows
    }
}

__device__ __forceinline__ void stageW(const __nv_bfloat16* Whi, const __nv_bfloat16* Wlo,
                                       int K, int ch, const ST& st, int buf, int tid)
{
    #pragma unroll
    for (int idx = tid; idx < 1024; idx += NTHREADS) {
        int mtx = idx >> 9, r = (idx >> 2) & 127, c = idx & 3;
        const __nv_bfloat16* src = (mtx ? Wlo : Whi) + (long)r * K + ch * 32 + c * 8;
        __nv_bfloat16* dst = (mtx ? st.Wl[buf] : st.Wh[buf]) + r * APAD + c * 8;
        cpasync16(dst, src);
    }
    asm volatile("cp.async.commit_group;");
}

__device__ __forceinline__ void convA(int ph, const SP& sp, const ST& st,
                                      int Mr, int ch, int buf, int tid)
{
    int n4 = Mr * 8;
    for (int idx = tid; idx < n4; idx += NTHREADS) {
        int r = idx >> 3, c4 = idx & 7;
        float4 val = getA(ph, sp, r, ch * 8 + c4);
        __nv_bfloat16 h0 = __float2bfloat16(val.x), h1 = __float2bfloat16(val.y);
        __nv_bfloat16 h2 = __float2bfloat16(val.z), h3 = __float2bfloat16(val.w);
        __nv_bfloat162 hp0; hp0.x = h0; hp0.y = h1;
        __nv_bfloat162 hp1; hp1.x = h2; hp1.y = h3;
        int o = r * APAD + c4 * 4;
        *reinterpret_cast<__nv_bfloat162*>(&st.Ah[buf][o])     = hp0;
        *reinterpret_cast<__nv_bfloat162*>(&st.Ah[buf][o + 2]) = hp1;
        __nv_bfloat162 lp0, lp1;
        lp0.x = __float2bfloat16(val.x - __bfloat162float(h0));
        lp0.y = __float2bfloat16(val.y - __bfloat162float(h1));
        lp1.x = __float2bfloat16(val.z - __bfloat162float(h2));
        lp1.y = __float2bfloat16(val.w - __bfloat162float(h3));
        *reinterpret_cast<__nv_bfloat162*>(&st.Al[buf][o])     = lp0;
        *reinterpret_cast<__nv_bfloat162*>(&st.Al[buf][o + 2]) = lp1;
    }
}

// One GEMM phase: out[Mr,128] = epi(A @ W + bias). Raw accums staged to outp,
// then in-place row epilogue (bias/relu/LN/resid), optional global write.
__device__ void gphase(int ph, int Mr, int K,
                       const __nv_bfloat16* Whi, const __nv_bfloat16* Wlo,
                       const float* bias, int do_relu,
                       const float* lng, const float* lnb,
                       const float* resid,   // smem, per-b rows of 128
                       float* outp,          // smem Mr x 128
                       float* outg, int gbase,
                       const SP& sp, const ST& st)
{
    const int tid = threadIdx.x, lane = tid & 31, w = tid >> 5;
    const int wm = (w & 1) * 16, wn = (w >> 1) * 32;
    const int lrow = lane & 15, lcol8 = (lane >> 4) * 8;
    const int nch = K / 32, mchn = Mr / 32;

    float acc[3][4][4];
    #pragma unroll
    for (int mc = 0; mc < 3; mc++)
        #pragma unroll
        for (int nt = 0; nt < 4; nt++)
            #pragma unroll
            for (int q = 0; q < 4; q++) acc[mc][nt][q] = 0.f;

    stageW(Whi, Wlo, K, 0, st, 0, tid);
    convA(ph, sp, st, Mr, 0, 0, tid);

    for (int ch = 0; ch < nch; ch++) {
        const int cur = ch & 1;
        if (ch + 1 < nch) {
            stageW(Whi, Wlo, K, ch + 1, st, cur ^ 1, tid);
            convA(ph, sp, st, Mr, ch + 1, cur ^ 1, tid);
            asm volatile("cp.async.wait_group 1;");
        } else {
            asm volatile("cp.async.wait_group 0;");
        }
        __syncthreads();

        const unsigned ahB = smem_u32(st.Ah[cur]), alB = smem_u32(st.Al[cur]);
        const unsigned whB = smem_u32(st.Wh[cur]), wlB = smem_u32(st.Wl[cur]);
        #pragma unroll
        for (int k16 = 0; k16 < 2; k16++) {
            unsigned bh[4][2], bl[4][2];
            #pragma unroll
            for (int nh = 0; nh < 2; nh++) {
                unsigned off = ((wn + nh * 16 + lrow) * APAD + k16 * 16 + lcol8) * 2;
                unsigned r0, r1, r2, r3;
                asm volatile("ldmatrix.sync.aligned.m8n8.x4.shared.b16 {%0,%1,%2,%3}, [%4];"
                             : "=r"(r0), "=r"(r1), "=r"(r2), "=r"(r3) : "r"(whB + off));
                bh[nh*2+0][0] = r0; bh[nh*2+0][1] = r2;
                bh[nh*2+1][0] = r1; bh[nh*2+1][1] = r3;
                asm volatile("ldmatrix.sync.aligned.m8n8.x4.shared.b16 {%0,%1,%2,%3}, [%4];"
                             : "=r"(r0), "=r"(r1), "=r"(r2), "=r"(r3) : "r"(wlB + off));
                bl[nh*2+0][0] = r0; bl[nh*2+0][1] = r2;
                bl[nh*2+1][0] = r1; bl[nh*2+1][1] = r3;
            }
            for (int mc = 0; mc < mchn; mc++) {
                unsigned ah[4], al[4];
                unsigned off = ((mc * 32 + wm + lrow) * APAD + k16 * 16 + lcol8) * 2;
                asm volatile("ldmatrix.sync.aligned.m8n8.x4.shared.b16 {%0,%1,%2,%3}, [%4];"
                             : "=r"(ah[0]), "=r"(ah[1]), "=r"(ah[2]), "=r"(ah[3])
                             : "r"(ahB + off));
                asm volatile("ldmatrix.sync.aligned.m8n8.x4.shared.b16 {%0,%1,%2,%3}, [%4];"
                             : "=r"(al[0]), "=r"(al[1]), "=r"(al[2]), "=r"(al[3])
                             : "r"(alB + off));
                #pragma unroll
                for (int nt = 0; nt < 4; nt++) {
                    asm volatile(
                        "mma.sync.aligned.m16n8k16.row.col.f32.bf16.bf16.f32 "
                        "{%0,%1,%2,%3}, {%4,%5,%6,%7}, {%8,%9}, {%0,%1,%2,%3};"
                        : "+f"(acc[mc][nt][0]), "+f"(acc[mc][nt][1]),
                          "+f"(acc[mc][nt][2]), "+f"(acc[mc][nt][3])
                        : "r"(ah[0]), "r"(ah[1]), "r"(ah[2]), "r"(ah[3]),
                          "r"(bh[nt][0]), "r"(bh[nt][1]));
                    asm volatile(
                        "mma.sync.aligned.m16n8k16.row.col.f32.bf16.bf16.f32 "
                        "{%0,%1,%2,%3}, {%4,%5,%6,%7}, {%8,%9}, {%0,%1,%2,%3};"
                        : "+f"(acc[mc][nt][0]), "+f"(acc[mc][nt][1]),
                          "+f"(acc[mc][nt][2]), "+f"(acc[mc][nt][3])
                        : "r"(ah[0]), "r"(ah[1]), "r"(ah[2]), "r"(ah[3]),
                          "r"(bl[nt][0]), "r"(bl[nt][1]));
                    asm volatile(
                        "mma.sync.aligned.m16n8k16.row.col.f32.bf16.bf16.f32 "
                        "{%0,%1,%2,%3}, {%4,%5,%6,%7}, {%8,%9}, {%0,%1,%2,%3};"
                        : "+f"(acc[mc][nt][0]), "+f"(acc[mc][nt][1]),
                          "+f"(acc[mc][nt][2]), "+f"(acc[mc][nt][3])
                        : "r"(al[0]), "r"(al[1]), "r"(al[2]), "r"(al[3]),
                          "r"(bh[nt][0]), "r"(bh[nt][1]));
                }
            }
        }
        __syncthreads();
    }

    // raw accums -> outp
    const int gid = lane >> 2, tq = (lane & 3) * 2;
    for (int mc = 0; mc < mchn; mc++)
        #pragma unroll
        for (int nt = 0; nt < 4; nt++) {
            int r = mc * 32 + wm + gid, c = wn + nt * 8 + tq;
            outp[r * 128 + c]           = acc[mc][nt][0];
            outp[r * 128 + c + 1]       = acc[mc][nt][1];
            outp[(r + 8) * 128 + c]     = acc[mc][nt][2];
            outp[(r + 8) * 128 + c + 1] = acc[mc][nt][3];
        }
    __syncthreads();

    // row epilogue
    float4 bv = *reinterpret_cast<const float4*>(&bias[lane * 4]);
    float4 gv, ev;
    if (lng) {
        gv = *reinterpret_cast<const float4*>(&lng[lane * 4]);
        ev = *reinterpret_cast<const float4*>(&lnb[lane * 4]);
    }
    for (int r = w; r < Mr; r += 8) {
        int b = r & 31;
        float4 vv = *reinterpret_cast<float4*>(&outp[r * 128 + lane * 4]);
        vv.x += bv.x; vv.y += bv.y; vv.z += bv.z; vv.w += bv.w;
        if (do_relu) {
            vv.x = fmaxf(vv.x, 0.f); vv.y = fmaxf(vv.y, 0.f);
            vv.z = fmaxf(vv.z, 0.f); vv.w = fmaxf(vv.w, 0.f);
        }
        if (lng) {
            float su = vv.x + vv.y + vv.z + vv.w;
            float q = vv.x*vv.x + vv.y*vv.y + vv.z*vv.z + vv.w*vv.w;
            #pragma unroll
            for (int off = 16; off > 0; off >>= 1) {
                su += __shfl_xor_sync(0xffffffffu, su, off);
                q  += __shfl_xor_sync(0xffffffffu, q, off);
            }
            float mu = su * (1.f / 128.f);
            float var = q * (1.f / 128.f) - mu * mu;
            float rs = rsqrtf(var + 1e-5f);
            vv.x = (vv.x - mu) * rs * gv.x + ev.x;
            vv.y = (vv.y - mu) * rs * gv.y + ev.y;
            vv.z = (vv.z - mu) * rs * gv.z + ev.z;
            vv.w = (vv.w - mu) * rs * gv.w + ev.w;
        }
        if (resid) {
            float4 rv = *reinterpret_cast<const float4*>(&resid[b * 128 + lane * 4]);
            vv.x += rv.x; vv.y += rv.y; vv.z += rv.z; vv.w += rv.w;
        }
        *reinterpret_cast<float4*>(&outp[r * 128 + lane * 4]) = vv;
        if (outg)
            *reinterpret_cast<float4*>(&outg[(long)(gbase + b) * 128 + lane * 4]) = vv;
    }
    __syncthreads();
}

__global__ __launch_bounds__(NTHREADS, 1) void mega_kernel(
    const float* __restrict__ z0,
    const float* __restrict__ be0, const float* __restrict__ be1,
    const float* __restrict__ phiE_b2,
    const float* __restrict__ phiN_b1, const float* __restrict__ phiN_g,
    const float* __restrict__ phiN_be, const float* __restrict__ phiN_b2,
    float* __restrict__ zg, const __nv_bfloat16* __restrict__ wb)
{
    extern __shared__ __align__(16) char sm[];
    float* z0s = reinterpret_cast<float*>(sm);              // 16384 B
    float* H   = reinterpret_cast<float*>(sm + 16384);      // 32768
    float* M   = reinterpret_cast<float*>(sm + 49152);      // 49152
    float* U   = reinterpret_cast<float*>(sm + 98304);      // 49152
    ST st;
    st.Ah[0] = reinterpret_cast<__nv_bfloat16*>(sm + 147456);
    st.Al[0] = reinterpret_cast<__nv_bfloat16*>(sm + 155136);
    st.Ah[1] = reinterpret_cast<__nv_bfloat16*>(sm + 162816);
    st.Al[1] = reinterpret_cast<__nv_bfloat16*>(sm + 170496);
    st.Wh[0] = reinterpret_cast<__nv_bfloat16*>(sm + 178176);
    st.Wl[0] = reinterpret_cast<__nv_bfloat16*>(sm + 188416);
    st.Wh[1] = reinterpret_cast<__nv_bfloat16*>(sm + 198656);
    st.Wl[1] = reinterpret_cast<__nv_bfloat16*>(sm + 208896);
    SP sp;
    sp.z0s = reinterpret_cast<float4*>(z0s);
    sp.H   = reinterpret_cast<float4*>(H);
    sp.M   = reinterpret_cast<float4*>(M);
    sp.U   = reinterpret_cast<float4*>(U);

    const int tid = threadIdx.x;
    const int bb = blockIdx.x;          // batch slice [bb*32, bb*32+32)

    {   // load z0 slice
        const float4* zsrc = reinterpret_cast<const float4*>(z0 + (long)bb * 32 * 128);
        #pragma unroll
        for (int i = tid; i < 1024; i += NTHREADS) sp.z0s[i] = zsrc[i];
    }
    __syncthreads();

    // P1: T = relu(z0 @ WE0 + be0) -> U[0:32]
    gphase(1, 32, 128, wb + WB + 0, wb + WB + 16384, be0, 1,
           nullptr, nullptr, nullptr, U, nullptr, 0, sp, st);
    // P2: m0 = T @ E2k0 + b2 -> M[0:32]
    gphase(2, 32, 128, wb + WB + 32768, wb + WB + 49152, phiE_b2, 0,
           nullptr, nullptr, nullptr, M, nullptr, 0, sp, st);
    // P3: U = LN(relu(pack0 @ N1k0 + b1)) -> U[0:64]
    gphase(3, 64, 256, wb + WB + 65536, wb + WB + 98304, phiN_b1, 1,
           phiN_g, phiN_be, nullptr, U, nullptr, 0, sp, st);
    // P4: H = U @ N2k0 + b2 + z0 -> H[0:64]
    gphase(4, 64, 128, wb + WB + 131072, wb + WB + 147456, phiN_b2, 0,
           nullptr, nullptr, z0s, H, nullptr, 0, sp, st);
    // P5: T = relu(pack1 @ E1k1 + be1) -> U[0:96]
    gphase(5, 96, 256, wb + WB + 163840, wb + WB + 196608, be1, 1,
           nullptr, nullptr, nullptr, U, nullptr, 0, sp, st);
    // P6: m1 = T @ E2k1 + b2' -> M[0:96]
    gphase(6, 96, 128, wb + WB + 229376, wb + WB + 245760, phiE_b2 + 128, 0,
           nullptr, nullptr, nullptr, M, nullptr, 0, sp, st);
    // P7: U = LN(relu(pack2 @ N1k1 + b1')) -> U[0:96]
    gphase(7, 96, 256, wb + WB + 262144, wb + WB + 294912, phiN_b1 + 128, 1,
           phiN_g + 128, phiN_be + 128, nullptr, U, nullptr, 0, sp, st);
    // mix: umix -> M[0:32], hmix -> M[32:64]
    for (int idx = tid; idx < 1024; idx += NTHREADS) {
        int r = idx >> 5, c = idx & 31;
        float4 u0 = sp.U[r * 32 + c], u1 = sp.U[(32 + r) * 32 + c], u2 = sp.U[(64 + r) * 32 + c];
        float4 rm;
        rm.x = (2.f * (u0.x + u1.x) + 60.f * u2.x) * (1.f / 64.f);
        rm.y = (2.f * (u0.y + u1.y) + 60.f * u2.y) * (1.f / 64.f);
        rm.z = (2.f * (u0.z + u1.z) + 60.f * u2.z) * (1.f / 64.f);
        rm.w = (2.f * (u0.w + u1.w) + 60.f * u2.w) * (1.f / 64.f);
        sp.M[r * 32 + c] = rm;
        float4 h0 = sp.H[r * 32 + c], h1 = sp.H[(32 + r) * 32 + c];
        float4 rh;
        rh.x = (2.f * h0.x + 62.f * h1.x) * (1.f / 64.f);
        rh.y = (2.f * h0.y + 62.f * h1.y) * (1.f / 64.f);
        rh.z = (2.f * h0.z + 62.f * h1.z) * (1.f / 64.f);
        rh.w = (2.f * h0.w + 62.f * h1.w) * (1.f / 64.f);
        sp.M[(32 + r) * 32 + c] = rh;
    }
    __syncthreads();
    // P9: zG = umix @ N2k1 + b2' + hmix -> global (staging in U)
    gphase(9, 32, 128, wb + WB + 327680, wb + WB + 344064, phiN_b2 + 128, 0,
           nullptr, nullptr, M + 32 * 128, U, zg, bb * 32, sp, st);
}

// ---------------------------------------------------------------------------
// Shared head (SIMT): x = LN256(relu(zg @ sh_W + sh_b)); emits fp32 + bf16 hi/lo
// ---------------------------------------------------------------------------
__global__ __launch_bounds__(NTHREADS) void sh_kernel(
    const float* __restrict__ A, const float* __restrict__ W,
    const float* __restrict__ bias, const float* __restrict__ lng,
    const float* __restrict__ lnb, float* __restrict__ out,
    __nv_bfloat16* __restrict__ xh, __nv_bfloat16* __restrict__ xl)
{
    __shared__ float As[32 * 128];
    __shared__ float Ws[32 * 256];
    const int tid = threadIdx.x;
    const int m0 = blockIdx.x * 32;
    {
        const float4* Ag = reinterpret_cast<const float4*>(A + (long)m0 * 128);
        float4* As4 = reinterpret_cast<float4*>(As);
        #pragma unroll
        for (int i = tid; i < 1024; i += NTHREADS) As4[i] = Ag[i];
    }
    const int lane = tid & 31, warp = tid >> 5;
    const int r0 = warp * 4, c0 = lane * 4, c1 = 128 + lane * 4;
    float acc[4][8];
    #pragma unroll
    for (int i = 0; i < 4; i++)
        #pragma unroll
        for (int j = 0; j < 8; j++) acc[i][j] = 0.f;

    for (int kc = 0; kc < 128; kc += 32) {
        __syncthreads();
        {
            const float4* Wg = reinterpret_cast<const float4*>(W + (long)kc * 256);
            float4* Ws4 = reinterpret_cast<float4*>(Ws);
            #pragma unroll
            for (int i = tid; i < 2048; i += NTHREADS) Ws4[i] = Wg[i];
        }
        __syncthreads();
        #pragma unroll 4
        for (int k = 0; k < 32; k++) {
            float4 w0 = *reinterpret_cast<const float4*>(&Ws[k * 256 + c0]);
            float4 w1 = *reinterpret_cast<const float4*>(&Ws[k * 256 + c1]);
            #pragma unroll
            for (int i = 0; i < 4; i++) {
                float a = As[(r0 + i) * 128 + kc + k];
                acc[i][0] = fmaf(a, w0.x, acc[i][0]); acc[i][1] = fmaf(a, w0.y, acc[i][1]);
                acc[i][2] = fmaf(a, w0.z, acc[i][2]); acc[i][3] = fmaf(a, w0.w, acc[i][3]);
                acc[i][4] = fmaf(a, w1.x, acc[i][4]); acc[i][5] = fmaf(a, w1.y, acc[i][5]);
                acc[i][6] = fmaf(a, w1.z, acc[i][6]); acc[i][7] = fmaf(a, w1.w, acc[i][7]);
            }
        }
    }
    float4 bv0 = *reinterpret_cast<const float4*>(&bias[c0]);
    float4 bv1 = *reinterpret_cast<const float4*>(&bias[c1]);
    float4 g0 = *reinterpret_cast<const float4*>(&lng[c0]);
    float4 g1 = *reinterpret_cast<const float4*>(&lng[c1]);
    float4 e0 = *reinterpret_cast<const float4*>(&lnb[c0]);
    float4 e1 = *reinterpret_cast<const float4*>(&lnb[c1]);
    #pragma unroll
    for (int i = 0; i < 4; i++) {
        acc[i][0] = fmaxf(acc[i][0] + bv0.x, 0.f); acc[i][1] = fmaxf(acc[i][1] + bv0.y, 0.f);
        acc[i][2] = fmaxf(acc[i][2] + bv0.z, 0.f); acc[i][3] = fmaxf(acc[i][3] + bv0.w, 0.f);
        acc[i][4] = fmaxf(acc[i][4] + bv1.x, 0.f); acc[i][5] = fmaxf(acc[i][5] + bv1.y, 0.f);
        acc[i][6] = fmaxf(acc[i][6] + bv1.z, 0.f); acc[i][7] = fmaxf(acc[i][7] + bv1.w, 0.f);
        float s = 0.f, q = 0.f;
        #pragma unroll
        for (int j = 0; j < 8; j++) { s += acc[i][j]; q += acc[i][j] * acc[i][j]; }
        #pragma unroll
        for (int off = 16; off > 0; off >>= 1) {
            s += __shfl_xor_sync(0xffffffffu, s, off);
            q += __shfl_xor_sync(0xffffffffu, q, off);
        }
        float mu = s * (1.f / 256.f);
        float var = q * (1.f / 256.f) - mu * mu;
        float rs = rsqrtf(var + 1e-5f);
        acc[i][0] = (acc[i][0]-mu)*rs*g0.x + e0.x; acc[i][1] = (acc[i][1]-mu)*rs*g0.y + e0.y;
        acc[i][2] = (acc[i][2]-mu)*rs*g0.z + e0.z; acc[i][3] = (acc[i][3]-mu)*rs*g0.w + e0.w;
        acc[i][4] = (acc[i][4]-mu)*rs*g1.x + e1.x; acc[i][5] = (acc[i][5]-mu)*rs*g1.y + e1.y;
        acc[i][6] = (acc[i][6]-mu)*rs*g1.z + e1.z; acc[i][7] = (acc[i][7]-mu)*rs*g1.w + e1.w;
        int row = m0 + r0 + i;
        *reinterpret_cast<float4*>(&out[(long)row * 256 + c0]) =
            make_float4(acc[i][0], acc[i][1], acc[i][2], acc[i][3]);
        *reinterpret_cast<float4*>(&out[(long)row * 256 + c1]) =
            make_float4(acc[i][4], acc[i][5], acc[i][6], acc[i][7]);
        __nv_bfloat162* XH = reinterpret_cast<__nv_bfloat162*>(xh + (long)row * 256);
        __nv_bfloat162* XL = reinterpret_cast<__nv_bfloat162*>(xl + (long)row * 256);
        #pragma unroll
        for (int j = 0; j < 2; j++) {
            float va = acc[i][j*2], vb = acc[i][j*2+1];
            __nv_bfloat16 ha = __float2bfloat16(va), hb = __float2bfloat16(vb);
            __nv_bfloat162 hp; hp.x = ha; hp.y = hb;
            XH[lane * 2 + j] = hp;
            __nv_bfloat162 lp;
            lp.x = __float2bfloat16(va - __bfloat162float(ha));
            lp.y = __float2bfloat16(vb - __bfloat162float(hb));
            XL[lane * 2 + j] = lp;
            float vc = acc[i][4 + j*2], vd = acc[i][4 + j*2+1];
            __nv_bfloat16 hc = __float2bfloat16(vc), hd = __float2bfloat16(vd);
            __nv_bfloat162 hp2; hp2.x = hc; hp2.y = hd;
            XH[64 + lane * 2 + j] = hp2;
            __nv_bfloat162 lp2;
            lp2.x = __float2bfloat16(vc - __bfloat162float(hc));
            lp2.y = __float2bfloat16(vd - __bfloat162float(hd));
            XL[64 + lane * 2 + j] = lp2;
        }
    }
}

// ---------------------------------------------------------------------------
// Policy head mma (validated)
// ---------------------------------------------------------------------------
#define PPAD 72

__global__ __launch_bounds__(NTHREADS) void pol_mma_kernel(
    const __nv_bfloat16* __restrict__ Xhi, const __nv_bfloat16* __restrict__ Xlo,
    const __nv_bfloat16* __restrict__ Whi, const __nv_bfloat16* __restrict__ Wlo,
    const float* __restrict__ bias, float* __restrict__ out)
{
    __shared__ __align__(16) __nv_bfloat16 As[128 * PPAD];
    __shared__ __align__(16) __nv_bfloat16 Bs[64 * PPAD];
    const int tid = threadIdx.x;
    const int lane = tid & 31, w = tid >> 5;
    const int wm = (w & 3) * 32, wn = (w >> 2) * 32;
    const int m0 = blockIdx.y * 128, n0 = blockIdx.x * 64;

    float acc[2][4][4];
    #pragma unroll
    for (int mt = 0; mt < 2; mt++)
        #pragma unroll
        for (int nt = 0; nt < 4; nt++)
            #pragma unroll
            for (int q = 0; q < 4; q++) acc[mt][nt][q] = 0.f;

    const __nv_bfloat16* Aps[3] = {Xhi, Xhi, Xlo};
    const __nv_bfloat16* Bps[3] = {Whi, Wlo, Whi};

    const unsigned a_base = smem_u32(As);
    const unsigned b_base = smem_u32(Bs);
    const int lrow = lane & 15, lcol8 = (lane >> 4) * 8;

    for (int p = 0; p < 3; p++) {
        const __nv_bfloat16* Ap = Aps[p];
        const __nv_bfloat16* Bp = Bps[p];
        for (int kc = 0; kc < 256; kc += 64) {
            __syncthreads();
            #pragma unroll
            for (int i = tid; i < 1024; i += NTHREADS) {
                int r = i >> 3, c8 = i & 7;
                *reinterpret_cast<uint4*>(&As[r * PPAD + c8 * 8]) =
                    *reinterpret_cast<const uint4*>(&Ap[(long)(m0 + r) * 256 + kc + c8 * 8]);
            }
            #pragma unroll
            for (int i = tid; i < 512; i += NTHREADS) {
                int r = i >> 3, c8 = i & 7;
                *reinterpret_cast<uint4*>(&Bs[r * PPAD + c8 * 8]) =
                    *reinterpret_cast<const uint4*>(&Bp[(long)(n0 + r) * 256 + kc + c8 * 8]);
            }
            __syncthreads();
            #pragma unroll
            for (int k16 = 0; k16 < 4; k16++) {
                unsigned a[2][4];
                #pragma unroll
                for (int mt = 0; mt < 2; mt++) {
                    unsigned addr = a_base +
                        ((wm + mt * 16 + lrow) * PPAD + k16 * 16 + lcol8) * 2;
                    asm volatile("ldmatrix.sync.aligned.m8n8.x4.shared.b16 "
                                 "{%0,%1,%2,%3}, [%4];"
                                 : "=r"(a[mt][0]), "=r"(a[mt][1]),
                                   "=r"(a[mt][2]), "=r"(a[mt][3]) : "r"(addr));
                }
                unsigned b[4][2];
                #pragma unroll
                for (int nh = 0; nh < 2; nh++) {
                    unsigned r0, r1, r2, r3;
                    unsigned addr = b_base +
                        ((wn + nh * 16 + lrow) * PPAD + k16 * 16 + lcol8) * 2;
                    asm volatile("ldmatrix.sync.aligned.m8n8.x4.shared.b16 "
                                 "{%0,%1,%2,%3}, [%4];"
                                 : "=r"(r0), "=r"(r1), "=r"(r2), "=r"(r3) : "r"(addr));
                    b[nh * 2 + 0][0] = r0; b[nh * 2 + 0][1] = r2;
                    b[nh * 2 + 1][0] = r1; b[nh * 2 + 1][1] = r3;
                }
                #pragma unroll
                for (int mt = 0; mt < 2; mt++)
                    #pragma unroll
                    for (int nt = 0; nt < 4; nt++) {
                        asm volatile(
                            "mma.sync.aligned.m16n8k16.row.col.f32.bf16.bf16.f32 "
                            "{%0,%1,%2,%3}, {%4,%5,%6,%7}, {%8,%9}, {%0,%1,%2,%3};"
                            : "+f"(acc[mt][nt][0]), "+f"(acc[mt][nt][1]),
                              "+f"(acc[mt][nt][2]), "+f"(acc[mt][nt][3])
                            : "r"(a[mt][0]), "r"(a[mt][1]), "r"(a[mt][2]), "r"(a[mt][3]),
                              "r"(b[nt][0]), "r"(b[nt][1]));
                    }
            }
        }
    }
    const int gid = lane >> 2, tq = (lane & 3) * 2;
    #pragma unroll
    for (int mt = 0; mt < 2; mt++) {
        #pragma unroll
        for (int nt = 0; nt < 4; nt++) {
            int col = n0 + wn + nt * 8 + tq;
            float bx = bias[col], by = bias[col + 1];
            int row0 = m0 + wm + mt * 16 + gid;
            float2 v0 = make_float2(acc[mt][nt][0] + bx, acc[mt][nt][1] + by);
            float2 v1 = make_float2(acc[mt][nt][2] + bx, acc[mt][nt][3] + by);
            *reinterpret_cast<float2*>(&out[(long)row0 * 960 + col]) = v0;
            *reinterpret_cast<float2*>(&out[(long)(row0 + 8) * 960 + col]) = v1;
        }
    }
}

// ---------------------------------------------------------------------------
// Value head
// ---------------------------------------------------------------------------
__global__ __launch_bounds__(NTHREADS) void val_kernel(
    const float* __restrict__ x, const float* __restrict__ vW,
    const float* __restrict__ vb, float* __restrict__ V)
{
    int warp = threadIdx.x >> 5, lane = threadIdx.x & 31;
    int m = blockIdx.x * 8 + warp;
    float s = 0.f;
    #pragma unroll
    for (int k = lane; k < 256; k += 32) s += x[(long)m * 256 + k] * vW[k];
    #pragma unroll
    for (int off = 16; off > 0; off >>= 1) s += __shfl_xor_sync(0xffffffffu, s, off);
    if (lane == 0) V[m] = s + vb[0];
}

// ---------------------------------------------------------------------------
// Launch
// ---------------------------------------------------------------------------
extern "C" void kernel_launch(void* const* d_in, const int* in_sizes, int n_in,
                              void* d_out, int out_size)
{
    const float* z0       = (const float*)d_in[0];
    const float* edge     = (const float*)d_in[3];
    const float* phiE_W1  = (const float*)d_in[4];
    const float* phiE_b1  = (const float*)d_in[5];
    const float* phiE_W2  = (const float*)d_in[6];
    const float* phiE_b2  = (const float*)d_in[7];
    const float* phiN_W1  = (const float*)d_in[8];
    const float* phiN_b1  = (const float*)d_in[9];
    const float* phiN_g   = (const float*)d_in[10];
    const float* phiN_be  = (const float*)d_in[11];
    const float* phiN_W2  = (const float*)d_in[12];
    const float* phiN_b2  = (const float*)d_in[13];
    const float* sh_W     = (const float*)d_in[14];
    const float* sh_b     = (const float*)d_in[15];
    const float* ln_g     = (const float*)d_in[16];
    const float* ln_b     = (const float*)d_in[17];
    const float* pol_W    = (const float*)d_in[18];
    const float* pol_b    = (const float*)d_in[19];
    const float* val_W    = (const float*)d_in[20];
    const float* val_b    = (const float*)d_in[21];
    float* outf = (float*)d_out;

    float* S = nullptr;
    cudaGetSymbolAddress((void**)&S, g_scratch);
    __nv_bfloat16* Bf = nullptr;
    cudaGetSymbolAddress((void**)&Bf, g_bf);

    cudaFuncSetAttribute(mega_kernel, cudaFuncAttributeMaxDynamicSharedMemorySize, SM_MEGA);

    // --- prep + weight splits ---
    prep_kernel<<<1, 128>>>(phiE_W1, phiE_b1, edge);
    wsplit_kernel<<<dim3(30, 8), dim3(32, 8)>>>(pol_W);
    {
        WJobs jb;
        jb.j[0] = { phiE_W1,           phiE_W1 + 128*128, 128, 128, WB+0,      WB+16384 };
        jb.j[1] = { phiE_W2,           nullptr,           128, 128, WB+32768,  WB+49152 };
        jb.j[2] = { phiN_W1,           nullptr,           256, 128, WB+65536,  WB+98304 };
        jb.j[3] = { phiN_W2,           nullptr,           128, 128, WB+131072, WB+147456 };
        jb.j[4] = { phiE_W1 + 257*128, nullptr,           256, 128, WB+163840, WB+196608 };
        jb.j[5] = { phiE_W2 + 128*128, nullptr,           128, 128, WB+229376, WB+245760 };
        jb.j[6] = { phiN_W1 + 256*128, nullptr,           256, 128, WB+262144, WB+294912 };
        jb.j[7] = { phiN_W2 + 128*128, nullptr,           128, 128, WB+327680, WB+344064 };
        jb.j[8] = { sh_W,              nullptr,           128, 256, WB+360448, WB+393216 };
        wsplitT_kernel<<<dim3(8, 8, 9), dim3(32, 8)>>>(jb);
    }

    // --- full backbone in one persistent kernel ---
    mega_kernel<<<B / 32, NTHREADS, SM_MEGA>>>(
        z0, S + OFF_BE0, S + OFF_BE1, phiE_b2,
        phiN_b1, phiN_g, phiN_be, phiN_b2,
        S + OFF_ZG, Bf);

    // --- heads ---
    sh_kernel<<<B / 32, NTHREADS>>>(S + OFF_ZG, sh_W, sh_b, ln_g, ln_b, S + OFF_X,
                                    Bf + OB_XH, Bf + OB_XL);
    pol_mma_kernel<<<dim3(960 / 64, B / 128), NTHREADS>>>(
        Bf + OB_XH, Bf + OB_XL, Bf + OB_WTH, Bf + OB_WTL, pol_b, outf);
    val_kernel<<<B / 8, NTHREADS>>>(S + OFF_X, val_W, val_b, outf + (long)B * 960);
}

// round 14
// speedup vs baseline: 1.7013x; 1.0159x over previous
#include <cuda_runtime.h>
#include <cuda_bf16.h>

#define B 4096
#define NTHREADS 256
#define MT 512          // mega kernel threads

// ---------------------------------------------------------------------------
// fp32 scratch
// ---------------------------------------------------------------------------
#define OFF_BE0   16384        // 128 folded bias k0
#define OFF_BE1   16512        // 128 folded bias k1
#define OFF_ZG    10502400     // B x 128
#define OFF_X     11026688     // B x 256
#define SCRATCH_TOTAL 12075264
__device__ float g_scratch[SCRATCH_TOTAL];

// bf16 scratch
#define OB_WTH 0               // pol WT hi [960,256]
#define OB_WTL 245760          // pol WT lo
#define OB_XH  491520          // x hi [B,256]
#define OB_XL  1540096         // x lo
#define WB     2588672         // backbone weights (transposed, hi/lo)
#define BF_TOTAL 3014656
__device__ __nv_bfloat16 g_bf[BF_TOTAL];

// job0 WE0T  hi WB+0       lo WB+16384
// job1 E2k0T hi WB+32768   lo WB+49152
// job2 N1k0T hi WB+65536   lo WB+98304
// job3 N2k0T hi WB+131072  lo WB+147456
// job4 E1k1T hi WB+163840  lo WB+196608
// job5 E2k1T hi WB+229376  lo WB+245760
// job6 N1k1T hi WB+262144  lo WB+294912
// job7 N2k1T hi WB+327680  lo WB+344064
// job8 shWT  hi WB+360448  lo WB+393216

__device__ __forceinline__ unsigned smem_u32(const void* p) {
    unsigned a;
    asm("{ .reg .u64 t; cvta.to.shared.u64 t, %1; cvt.u32.u64 %0, t; }" : "=r"(a) : "l"(p));
    return a;
}
__device__ __forceinline__ void cpasync16(void* dst, const void* g) {
    asm volatile("cp.async.ca.shared.global [%0], [%1], 16;"
                 :: "r"(smem_u32(dst)), "l"(g));
}

// ---------------------------------------------------------------------------
// Prep: folded edge-bias terms
// ---------------------------------------------------------------------------
__global__ __launch_bounds__(128) void prep_kernel(
    const float* __restrict__ phiE_W1, const float* __restrict__ phiE_b1,
    const float* __restrict__ edge_attr)
{
    int i = threadIdx.x;
    float e = edge_attr[0];
    g_scratch[OFF_BE0 + i] = phiE_b1[i]       + e * phiE_W1[256 * 128 + i];
    g_scratch[OFF_BE1 + i] = phiE_b1[128 + i] + e * phiE_W1[257 * 128 + 256 * 128 + i];
}

// ---------------------------------------------------------------------------
// Batched weight transpose + bf16 split: src [K,N] fp32 -> dst [N,K] bf16 hi/lo
// ---------------------------------------------------------------------------
struct WJob { const float* src; const float* src2; int K; int N; long dstHi; long dstLo; };
struct WJobs { WJob j[9]; };

__global__ void wsplitT_kernel(WJobs jobs)
{
    WJob jb = jobs.j[blockIdx.z];
    int kb = blockIdx.y * 32, nb = blockIdx.x * 32;
    if (kb >= jb.K || nb >= jb.N) return;
    __shared__ float t[32][33];
    int tx = threadIdx.x, ty = threadIdx.y;
    for (int j = ty; j < 32; j += 8) {
        float v = jb.src[(long)(kb + j) * jb.N + nb + tx];
        if (jb.src2) v += jb.src2[(long)(kb + j) * jb.N + nb + tx];
        t[j][tx] = v;
    }
    __syncthreads();
    for (int j = ty; j < 32; j += 8) {
        float v = t[tx][j];
        __nv_bfloat16 h = __float2bfloat16(v);
        long o = (long)(nb + j) * jb.K + kb + tx;
        g_bf[jb.dstHi + o] = h;
        g_bf[jb.dstLo + o] = __float2bfloat16(v - __bfloat162float(h));
    }
}

__global__ void wsplit_kernel(const float* __restrict__ W)
{
    __shared__ float t[32][33];
    int kb = blockIdx.y * 32, nb = blockIdx.x * 32;
    int tx = threadIdx.x, ty = threadIdx.y;
    for (int j = ty; j < 32; j += 8)
        t[j][tx] = W[(long)(kb + j) * 960 + nb + tx];
    __syncthreads();
    for (int j = ty; j < 32; j += 8) {
        float v = t[tx][j];
        __nv_bfloat16 h = __float2bfloat16(v);
        long o = (long)(nb + j) * 256 + kb + tx;
        g_bf[OB_WTH + o] = h;
        g_bf[OB_WTL + o] = __float2bfloat16(v - __bfloat162float(h));
    }
}

// ---------------------------------------------------------------------------
// MEGAKERNEL: entire backbone per 32-row batch slice, 512 threads (16 warps),
// intermediates in smem, weights streamed via cp.async double buffer.
// ---------------------------------------------------------------------------
#define APAD 40
#define SM_MEGA 219136

struct SP {
    float4* z0s;  // 32 x 32
    float4* H;    // 64 x 32
    float4* M;    // 96 x 32
    float4* U;    // 96 x 32
};
struct ST {
    __nv_bfloat16* Ah[2]; __nv_bfloat16* Al[2];
    __nv_bfloat16* Wh[2]; __nv_bfloat16* Wl[2];
};

__device__ __forceinline__ float4 getA(int ph, const SP& sp, int r, int kk4)
{
    int v = r >> 5, b = r & 31;
    switch (ph) {
    case 1: return sp.z0s[b * 32 + kk4];
    case 3:
        if (kk4 < 32) return sp.z0s[b * 32 + kk4];
        else {
            float4 m = sp.M[b * 32 + kk4 - 32];
            if (v == 1) { m.x *= 2.f; m.y *= 2.f; m.z *= 2.f; m.w *= 2.f; }
            return m;
        }
    case 5: {
        int cls = (kk4 < 32) ? (v == 0 ? 0 : 1) : (v == 1 ? 0 : 1);
        int k = (kk4 < 32) ? kk4 : kk4 - 32;
        return sp.H[(cls * 32 + b) * 32 + k];
    }
    case 7:
        if (kk4 < 32) return sp.H[((v == 0 ? 0 : 1) * 32 + b) * 32 + kk4];
        else {
            int k = kk4 - 32;
            if (v == 0) return sp.M[b * 32 + k];
            if (v == 1) {
                float4 a = sp.M[(32 + b) * 32 + k], c = sp.M[(64 + b) * 32 + k];
                return make_float4(a.x + c.x, a.y + c.y, a.z + c.z, a.w + c.w);
            }
            float4 c = sp.M[(64 + b) * 32 + k];
            return make_float4(2.f * c.x, 2.f * c.y, 2.f * c.z, 2.f * c.w);
        }
    case 9: return sp.M[b * 32 + kk4];           // umix
    default: return sp.U[r * 32 + kk4];          // cases 2,4,6
    }
}

__device__ __forceinline__ void stageW(const __nv_bfloat16* Whi, const __nv_bfloat16* Wlo,
                                       int K, int ch, const ST& st, int buf, int tid)
{
    #pragma unroll
    for (int idx = tid; idx < 1024; idx += MT) {
        int mtx = idx >> 9, r = (idx >> 2) & 127, c = idx & 3;
        const __nv_bfloat16* src = (mtx ? Wlo : Whi) + (long)r * K + ch * 32 + c * 8;
        __nv_bfloat16* dst = (mtx ? st.Wl[buf] : st.Wh[buf]) + r * APAD + c * 8;
        cpasync16(dst, src);
    }
    asm volatile("cp.async.commit_group;");
}

__device__ __forceinline__ void convA(int ph, const SP& sp, const ST& st,
                                      int Mr, int ch, int buf, int tid)
{
    int n4 = Mr * 8;
    for (int idx = tid; idx < n4; idx += MT) {
        int r = idx >> 3, c4 = idx & 7;
        float4 val = getA(ph, sp, r, ch * 8 + c4);
        __nv_bfloat16 h0 = __float2bfloat16(val.x), h1 = __float2bfloat16(val.y);
        __nv_bfloat16 h2 = __float2bfloat16(val.z), h3 = __float2bfloat16(val.w);
        __nv_bfloat162 hp0; hp0.x = h0; hp0.y = h1;
        __nv_bfloat162 hp1; hp1.x = h2; hp1.y = h3;
        int o = r * APAD + c4 * 4;
        *reinterpret_cast<__nv_bfloat162*>(&st.Ah[buf][o])     = hp0;
        *reinterpret_cast<__nv_bfloat162*>(&st.Ah[buf][o + 2]) = hp1;
        __nv_bfloat162 lp0, lp1;
        lp0.x = __float2bfloat16(val.x - __bfloat162float(h0));
        lp0.y = __float2bfloat16(val.y - __bfloat162float(h1));
        lp1.x = __float2bfloat16(val.z - __bfloat162float(h2));
        lp1.y = __float2bfloat16(val.w - __bfloat162float(h3));
        *reinterpret_cast<__nv_bfloat162*>(&st.Al[buf][o])     = lp0;
        *reinterpret_cast<__nv_bfloat162*>(&st.Al[buf][o + 2]) = lp1;
    }
}

// One GEMM phase with 16 warps: warp grid 4m x 4n over 64x128 per m-iter.
__device__ void gphase(int ph, int Mr, int K,
                       const __nv_bfloat16* Whi, const __nv_bfloat16* Wlo,
                       const float* bias, int do_relu,
                       const float* lng, const float* lnb,
                       const float* resid,
                       float* outp,
                       float* outg, int gbase,
                       const SP& sp, const ST& st)
{
    const int tid = threadIdx.x, lane = tid & 31, w = tid >> 5;
    const int wm = (w & 3) * 16, wn = (w >> 2) * 32;
    const int lrow = lane & 15, lcol8 = (lane >> 4) * 8;
    const int nch = K / 32;
    const int nmi = (Mr + 63) / 64;

    float acc[2][4][4];
    #pragma unroll
    for (int it = 0; it < 2; it++)
        #pragma unroll
        for (int nt = 0; nt < 4; nt++)
            #pragma unroll
            for (int q = 0; q < 4; q++) acc[it][nt][q] = 0.f;

    stageW(Whi, Wlo, K, 0, st, 0, tid);
    convA(ph, sp, st, Mr, 0, 0, tid);

    for (int ch = 0; ch < nch; ch++) {
        const int cur = ch & 1;
        if (ch + 1 < nch) {
            stageW(Whi, Wlo, K, ch + 1, st, cur ^ 1, tid);
            convA(ph, sp, st, Mr, ch + 1, cur ^ 1, tid);
            asm volatile("cp.async.wait_group 1;");
        } else {
            asm volatile("cp.async.wait_group 0;");
        }
        __syncthreads();

        const unsigned ahB = smem_u32(st.Ah[cur]), alB = smem_u32(st.Al[cur]);
        const unsigned whB = smem_u32(st.Wh[cur]), wlB = smem_u32(st.Wl[cur]);
        #pragma unroll
        for (int k16 = 0; k16 < 2; k16++) {
            unsigned bh[4][2], bl[4][2];
            #pragma unroll
            for (int nh = 0; nh < 2; nh++) {
                unsigned off = ((wn + nh * 16 + lrow) * APAD + k16 * 16 + lcol8) * 2;
                unsigned r0, r1, r2, r3;
                asm volatile("ldmatrix.sync.aligned.m8n8.x4.shared.b16 {%0,%1,%2,%3}, [%4];"
                             : "=r"(r0), "=r"(r1), "=r"(r2), "=r"(r3) : "r"(whB + off));
                bh[nh*2+0][0] = r0; bh[nh*2+0][1] = r2;
                bh[nh*2+1][0] = r1; bh[nh*2+1][1] = r3;
                asm volatile("ldmatrix.sync.aligned.m8n8.x4.shared.b16 {%0,%1,%2,%3}, [%4];"
                             : "=r"(r0), "=r"(r1), "=r"(r2), "=r"(r3) : "r"(wlB + off));
                bl[nh*2+0][0] = r0; bl[nh*2+0][1] = r2;
                bl[nh*2+1][0] = r1; bl[nh*2+1][1] = r3;
            }
            #pragma unroll 2
            for (int it = 0; it < nmi; it++) {
                int rb = it * 64 + wm;
                if (rb < Mr) {
                    unsigned ah[4], al[4];
                    unsigned off = ((rb + lrow) * APAD + k16 * 16 + lcol8) * 2;
                    asm volatile("ldmatrix.sync.aligned.m8n8.x4.shared.b16 {%0,%1,%2,%3}, [%4];"
                                 : "=r"(ah[0]), "=r"(ah[1]), "=r"(ah[2]), "=r"(ah[3])
                                 : "r"(ahB + off));
                    asm volatile("ldmatrix.sync.aligned.m8n8.x4.shared.b16 {%0,%1,%2,%3}, [%4];"
                                 : "=r"(al[0]), "=r"(al[1]), "=r"(al[2]), "=r"(al[3])
                                 : "r"(alB + off));
                    #pragma unroll
                    for (int nt = 0; nt < 4; nt++) {
                        asm volatile(
                            "mma.sync.aligned.m16n8k16.row.col.f32.bf16.bf16.f32 "
                            "{%0,%1,%2,%3}, {%4,%5,%6,%7}, {%8,%9}, {%0,%1,%2,%3};"
                            : "+f"(acc[it][nt][0]), "+f"(acc[it][nt][1]),
                              "+f"(acc[it][nt][2]), "+f"(acc[it][nt][3])
                            : "r"(ah[0]), "r"(ah[1]), "r"(ah[2]), "r"(ah[3]),
                              "r"(bh[nt][0]), "r"(bh[nt][1]));
                        asm volatile(
                            "mma.sync.aligned.m16n8k16.row.col.f32.bf16.bf16.f32 "
                            "{%0,%1,%2,%3}, {%4,%5,%6,%7}, {%8,%9}, {%0,%1,%2,%3};"
                            : "+f"(acc[it][nt][0]), "+f"(acc[it][nt][1]),
                              "+f"(acc[it][nt][2]), "+f"(acc[it][nt][3])
                            : "r"(ah[0]), "r"(ah[1]), "r"(ah[2]), "r"(ah[3]),
                              "r"(bl[nt][0]), "r"(bl[nt][1]));
                        asm volatile(
                            "mma.sync.aligned.m16n8k16.row.col.f32.bf16.bf16.f32 "
                            "{%0,%1,%2,%3}, {%4,%5,%6,%7}, {%8,%9}, {%0,%1,%2,%3};"
                            : "+f"(acc[it][nt][0]), "+f"(acc[it][nt][1]),
                              "+f"(acc[it][nt][2]), "+f"(acc[it][nt][3])
                            : "r"(al[0]), "r"(al[1]), "r"(al[2]), "r"(al[3]),
                              "r"(bh[nt][0]), "r"(bh[nt][1]));
                    }
                }
            }
        }
        __syncthreads();
    }

    // raw accums -> outp
    const int gid = lane >> 2, tq = (lane & 3) * 2;
    #pragma unroll 2
    for (int it = 0; it < nmi; it++) {
        int rb = it * 64 + wm;
        if (rb < Mr) {
            #pragma unroll
            for (int nt = 0; nt < 4; nt++) {
                int r = rb + gid, c = wn + nt * 8 + tq;
                outp[r * 128 + c]           = acc[it][nt][0];
                outp[r * 128 + c + 1]       = acc[it][nt][1];
                outp[(r + 8) * 128 + c]     = acc[it][nt][2];
                outp[(r + 8) * 128 + c + 1] = acc[it][nt][3];
            }
        }
    }
    __syncthreads();

    // row epilogue (16 warps: rows stride 16)
    float4 bv = *reinterpret_cast<const float4*>(&bias[lane * 4]);
    float4 gv, ev;
    if (lng) {
        gv = *reinterpret_cast<const float4*>(&lng[lane * 4]);
        ev = *reinterpret_cast<const float4*>(&lnb[lane * 4]);
    }
    for (int r = w; r < Mr; r += 16) {
        int b = r & 31;
        float4 vv = *reinterpret_cast<float4*>(&outp[r * 128 + lane * 4]);
        vv.x += bv.x; vv.y += bv.y; vv.z += bv.z; vv.w += bv.w;
        if (do_relu) {
            vv.x = fmaxf(vv.x, 0.f); vv.y = fmaxf(vv.y, 0.f);
            vv.z = fmaxf(vv.z, 0.f); vv.w = fmaxf(vv.w, 0.f);
        }
        if (lng) {
            float su = vv.x + vv.y + vv.z + vv.w;
            float q = vv.x*vv.x + vv.y*vv.y + vv.z*vv.z + vv.w*vv.w;
            #pragma unroll
            for (int off = 16; off > 0; off >>= 1) {
                su += __shfl_xor_sync(0xffffffffu, su, off);
                q  += __shfl_xor_sync(0xffffffffu, q, off);
            }
            float mu = su * (1.f / 128.f);
            float var = q * (1.f / 128.f) - mu * mu;
            float rs = rsqrtf(var + 1e-5f);
            vv.x = (vv.x - mu) * rs * gv.x + ev.x;
            vv.y = (vv.y - mu) * rs * gv.y + ev.y;
            vv.z = (vv.z - mu) * rs * gv.z + ev.z;
            vv.w = (vv.w - mu) * rs * gv.w + ev.w;
        }
        if (resid) {
            float4 rv = *reinterpret_cast<const float4*>(&resid[b * 128 + lane * 4]);
            vv.x += rv.x; vv.y += rv.y; vv.z += rv.z; vv.w += rv.w;
        }
        *reinterpret_cast<float4*>(&outp[r * 128 + lane * 4]) = vv;
        if (outg)
            *reinterpret_cast<float4*>(&outg[(long)(gbase + b) * 128 + lane * 4]) = vv;
    }
    __syncthreads();
}

__global__ __launch_bounds__(MT, 1) void mega_kernel(
    const float* __restrict__ z0,
    const float* __restrict__ be0, const float* __restrict__ be1,
    const float* __restrict__ phiE_b2,
    const float* __restrict__ phiN_b1, const float* __restrict__ phiN_g,
    const float* __restrict__ phiN_be, const float* __restrict__ phiN_b2,
    float* __restrict__ zg, const __nv_bfloat16* __restrict__ wb)
{
    extern __shared__ __align__(16) char sm[];
    float* z0s = reinterpret_cast<float*>(sm);              // 16384 B
    float* H   = reinterpret_cast<float*>(sm + 16384);      // 32768
    float* M   = reinterpret_cast<float*>(sm + 49152);      // 49152
    float* U   = reinterpret_cast<float*>(sm + 98304);      // 49152
    ST st;
    st.Ah[0] = reinterpret_cast<__nv_bfloat16*>(sm + 147456);
    st.Al[0] = reinterpret_cast<__nv_bfloat16*>(sm + 155136);
    st.Ah[1] = reinterpret_cast<__nv_bfloat16*>(sm + 162816);
    st.Al[1] = reinterpret_cast<__nv_bfloat16*>(sm + 170496);
    st.Wh[0] = reinterpret_cast<__nv_bfloat16*>(sm + 178176);
    st.Wl[0] = reinterpret_cast<__nv_bfloat16*>(sm + 188416);
    st.Wh[1] = reinterpret_cast<__nv_bfloat16*>(sm + 198656);
    st.Wl[1] = reinterpret_cast<__nv_bfloat16*>(sm + 208896);
    SP sp;
    sp.z0s = reinterpret_cast<float4*>(z0s);
    sp.H   = reinterpret_cast<float4*>(H);
    sp.M   = reinterpret_cast<float4*>(M);
    sp.U   = reinterpret_cast<float4*>(U);

    const int tid = threadIdx.x;
    const int bb = blockIdx.x;

    {   // load z0 slice
        const float4* zsrc = reinterpret_cast<const float4*>(z0 + (long)bb * 32 * 128);
        #pragma unroll
        for (int i = tid; i < 1024; i += MT) sp.z0s[i] = zsrc[i];
    }
    __syncthreads();

    // P1: T = relu(z0 @ WE0 + be0) -> U[0:32]
    gphase(1, 32, 128, wb + WB + 0, wb + WB + 16384, be0, 1,
           nullptr, nullptr, nullptr, U, nullptr, 0, sp, st);
    // P2: m0 = T @ E2k0 + b2 -> M[0:32]
    gphase(2, 32, 128, wb + WB + 32768, wb + WB + 49152, phiE_b2, 0,
           nullptr, nullptr, nullptr, M, nullptr, 0, sp, st);
    // P3: U = LN(relu(pack0 @ N1k0 + b1)) -> U[0:64]
    gphase(3, 64, 256, wb + WB + 65536, wb + WB + 98304, phiN_b1, 1,
           phiN_g, phiN_be, nullptr, U, nullptr, 0, sp, st);
    // P4: H = U @ N2k0 + b2 + z0 -> H[0:64]
    gphase(4, 64, 128, wb + WB + 131072, wb + WB + 147456, phiN_b2, 0,
           nullptr, nullptr, z0s, H, nullptr, 0, sp, st);
    // P5: T = relu(pack1 @ E1k1 + be1) -> U[0:96]
    gphase(5, 96, 256, wb + WB + 163840, wb + WB + 196608, be1, 1,
           nullptr, nullptr, nullptr, U, nullptr, 0, sp, st);
    // P6: m1 = T @ E2k1 + b2' -> M[0:96]
    gphase(6, 96, 128, wb + WB + 229376, wb + WB + 245760, phiE_b2 + 128, 0,
           nullptr, nullptr, nullptr, M, nullptr, 0, sp, st);
    // P7: U = LN(relu(pack2 @ N1k1 + b1')) -> U[0:96]
    gphase(7, 96, 256, wb + WB + 262144, wb + WB + 294912, phiN_b1 + 128, 1,
           phiN_g + 128, phiN_be + 128, nullptr, U, nullptr, 0, sp, st);
    // mix: umix -> M[0:32], hmix -> M[32:64]
    for (int idx = tid; idx < 1024; idx += MT) {
        int r = idx >> 5, c = idx & 31;
        float4 u0 = sp.U[r * 32 + c], u1 = sp.U[(32 + r) * 32 + c], u2 = sp.U[(64 + r) * 32 + c];
        float4 rm;
        rm.x = (2.f * (u0.x + u1.x) + 60.f * u2.x) * (1.f / 64.f);
        rm.y = (2.f * (u0.y + u1.y) + 60.f * u2.y) * (1.f / 64.f);
        rm.z = (2.f * (u0.z + u1.z) + 60.f * u2.z) * (1.f / 64.f);
        rm.w = (2.f * (u0.w + u1.w) + 60.f * u2.w) * (1.f / 64.f);
        sp.M[r * 32 + c] = rm;
        float4 h0 = sp.H[r * 32 + c], h1 = sp.H[(32 + r) * 32 + c];
        float4 rh;
        rh.x = (2.f * h0.x + 62.f * h1.x) * (1.f / 64.f);
        rh.y = (2.f * h0.y + 62.f * h1.y) * (1.f / 64.f);
        rh.z = (2.f * h0.z + 62.f * h1.z) * (1.f / 64.f);
        rh.w = (2.f * h0.w + 62.f * h1.w) * (1.f / 64.f);
        sp.M[(32 + r) * 32 + c] = rh;
    }
    __syncthreads();
    // P9: zG = umix @ N2k1 + b2' + hmix -> global (staging in U)
    gphase(9, 32, 128, wb + WB + 327680, wb + WB + 344064, phiN_b2 + 128, 0,
           nullptr, nullptr, M + 32 * 128, U, zg, bb * 32, sp, st);
}

// ---------------------------------------------------------------------------
// Shared head (SIMT): x = LN256(relu(zg @ sh_W + sh_b)); emits fp32 + bf16 hi/lo
// ---------------------------------------------------------------------------
__global__ __launch_bounds__(NTHREADS) void sh_kernel(
    const float* __restrict__ A, const float* __restrict__ W,
    const float* __restrict__ bias, const float* __restrict__ lng,
    const float* __restrict__ lnb, float* __restrict__ out,
    __nv_bfloat16* __restrict__ xh, __nv_bfloat16* __restrict__ xl)
{
    __shared__ float As[32 * 128];
    __shared__ float Ws[32 * 256];
    const int tid = threadIdx.x;
    const int m0 = blockIdx.x * 32;
    {
        const float4* Ag = reinterpret_cast<const float4*>(A + (long)m0 * 128);
        float4* As4 = reinterpret_cast<float4*>(As);
        #pragma unroll
        for (int i = tid; i < 1024; i += NTHREADS) As4[i] = Ag[i];
    }
    const int lane = tid & 31, warp = tid >> 5;
    const int r0 = warp * 4, c0 = lane * 4, c1 = 128 + lane * 4;
    float acc[4][8];
    #pragma unroll
    for (int i = 0; i < 4; i++)
        #pragma unroll
        for (int j = 0; j < 8; j++) acc[i][j] = 0.f;

    for (int kc = 0; kc < 128; kc += 32) {
        __syncthreads();
        {
            const float4* Wg = reinterpret_cast<const float4*>(W + (long)kc * 256);
            float4* Ws4 = reinterpret_cast<float4*>(Ws);
            #pragma unroll
            for (int i = tid; i < 2048; i += NTHREADS) Ws4[i] = Wg[i];
        }
        __syncthreads();
        #pragma unroll 4
        for (int k = 0; k < 32; k++) {
            float4 w0 = *reinterpret_cast<const float4*>(&Ws[k * 256 + c0]);
            float4 w1 = *reinterpret_cast<const float4*>(&Ws[k * 256 + c1]);
            #pragma unroll
            for (int i = 0; i < 4; i++) {
                float a = As[(r0 + i) * 128 + kc + k];
                acc[i][0] = fmaf(a, w0.x, acc[i][0]); acc[i][1] = fmaf(a, w0.y, acc[i][1]);
                acc[i][2] = fmaf(a, w0.z, acc[i][2]); acc[i][3] = fmaf(a, w0.w, acc[i][3]);
                acc[i][4] = fmaf(a, w1.x, acc[i][4]); acc[i][5] = fmaf(a, w1.y, acc[i][5]);
                acc[i][6] = fmaf(a, w1.z, acc[i][6]); acc[i][7] = fmaf(a, w1.w, acc[i][7]);
            }
        }
    }
    float4 bv0 = *reinterpret_cast<const float4*>(&bias[c0]);
    float4 bv1 = *reinterpret_cast<const float4*>(&bias[c1]);
    float4 g0 = *reinterpret_cast<const float4*>(&lng[c0]);
    float4 g1 = *reinterpret_cast<const float4*>(&lng[c1]);
    float4 e0 = *reinterpret_cast<const float4*>(&lnb[c0]);
    float4 e1 = *reinterpret_cast<const float4*>(&lnb[c1]);
    #pragma unroll
    for (int i = 0; i < 4; i++) {
        acc[i][0] = fmaxf(acc[i][0] + bv0.x, 0.f); acc[i][1] = fmaxf(acc[i][1] + bv0.y, 0.f);
        acc[i][2] = fmaxf(acc[i][2] + bv0.z, 0.f); acc[i][3] = fmaxf(acc[i][3] + bv0.w, 0.f);
        acc[i][4] = fmaxf(acc[i][4] + bv1.x, 0.f); acc[i][5] = fmaxf(acc[i][5] + bv1.y, 0.f);
        acc[i][6] = fmaxf(acc[i][6] + bv1.z, 0.f); acc[i][7] = fmaxf(acc[i][7] + bv1.w, 0.f);
        float s = 0.f, q = 0.f;
        #pragma unroll
        for (int j = 0; j < 8; j++) { s += acc[i][j]; q += acc[i][j] * acc[i][j]; }
        #pragma unroll
        for (int off = 16; off > 0; off >>= 1) {
            s += __shfl_xor_sync(0xffffffffu, s, off);
            q += __shfl_xor_sync(0xffffffffu, q, off);
        }
        float mu = s * (1.f / 256.f);
        float var = q * (1.f / 256.f) - mu * mu;
        float rs = rsqrtf(var + 1e-5f);
        acc[i][0] = (acc[i][0]-mu)*rs*g0.x + e0.x; acc[i][1] = (acc[i][1]-mu)*rs*g0.y + e0.y;
        acc[i][2] = (acc[i][2]-mu)*rs*g0.z + e0.z; acc[i][3] = (acc[i][3]-mu)*rs*g0.w + e0.w;
        acc[i][4] = (acc[i][4]-mu)*rs*g1.x + e1.x; acc[i][5] = (acc[i][5]-mu)*rs*g1.y + e1.y;
        acc[i][6] = (acc[i][6]-mu)*rs*g1.z + e1.z; acc[i][7] = (acc[i][7]-mu)*rs*g1.w + e1.w;
        int row = m0 + r0 + i;
        *reinterpret_cast<float4*>(&out[(long)row * 256 + c0]) =
            make_float4(acc[i][0], acc[i][1], acc[i][2], acc[i][3]);
        *reinterpret_cast<float4*>(&out[(long)row * 256 + c1]) =
            make_float4(acc[i][4], acc[i][5], acc[i][6], acc[i][7]);
        __nv_bfloat162* XH = reinterpret_cast<__nv_bfloat162*>(xh + (long)row * 256);
        __nv_bfloat162* XL = reinterpret_cast<__nv_bfloat162*>(xl + (long)row * 256);
        #pragma unroll
        for (int j = 0; j < 2; j++) {
            float va = acc[i][j*2], vb = acc[i][j*2+1];
            __nv_bfloat16 ha = __float2bfloat16(va), hb = __float2bfloat16(vb);
            __nv_bfloat162 hp; hp.x = ha; hp.y = hb;
            XH[lane * 2 + j] = hp;
            __nv_bfloat162 lp;
            lp.x = __float2bfloat16(va - __bfloat162float(ha));
            lp.y = __float2bfloat16(vb - __bfloat162float(hb));
            XL[lane * 2 + j] = lp;
            float vc = acc[i][4 + j*2], vd = acc[i][4 + j*2+1];
            __nv_bfloat16 hc = __float2bfloat16(vc), hd = __float2bfloat16(vd);
            __nv_bfloat162 hp2; hp2.x = hc; hp2.y = hd;
            XH[64 + lane * 2 + j] = hp2;
            __nv_bfloat162 lp2;
            lp2.x = __float2bfloat16(vc - __bfloat162float(hc));
            lp2.y = __float2bfloat16(vd - __bfloat162float(hd));
            XL[64 + lane * 2 + j] = lp2;
        }
    }
}

// ---------------------------------------------------------------------------
// Policy head mma (validated)
// ---------------------------------------------------------------------------
#define PPAD 72

__global__ __launch_bounds__(NTHREADS) void pol_mma_kernel(
    const __nv_bfloat16* __restrict__ Xhi, const __nv_bfloat16* __restrict__ Xlo,
    const __nv_bfloat16* __restrict__ Whi, const __nv_bfloat16* __restrict__ Wlo,
    const float* __restrict__ bias, float* __restrict__ out)
{
    __shared__ __align__(16) __nv_bfloat16 As[128 * PPAD];
    __shared__ __align__(16) __nv_bfloat16 Bs[64 * PPAD];
    const int tid = threadIdx.x;
    const int lane = tid & 31, w = tid >> 5;
    const int wm = (w & 3) * 32, wn = (w >> 2) * 32;
    const int m0 = blockIdx.y * 128, n0 = blockIdx.x * 64;

    float acc[2][4][4];
    #pragma unroll
    for (int mt = 0; mt < 2; mt++)
        #pragma unroll
        for (int nt = 0; nt < 4; nt++)
            #pragma unroll
            for (int q = 0; q < 4; q++) acc[mt][nt][q] = 0.f;

    const __nv_bfloat16* Aps[3] = {Xhi, Xhi, Xlo};
    const __nv_bfloat16* Bps[3] = {Whi, Wlo, Whi};

    const unsigned a_base = smem_u32(As);
    const unsigned b_base = smem_u32(Bs);
    const int lrow = lane & 15, lcol8 = (lane >> 4) * 8;

    for (int p = 0; p < 3; p++) {
        const __nv_bfloat16* Ap = Aps[p];
        const __nv_bfloat16* Bp = Bps[p];
        for (int kc = 0; kc < 256; kc += 64) {
            __syncthreads();
            #pragma unroll
            for (int i = tid; i < 1024; i += NTHREADS) {
                int r = i >> 3, c8 = i & 7;
                *reinterpret_cast<uint4*>(&As[r * PPAD + c8 * 8]) =
                    *reinterpret_cast<const uint4*>(&Ap[(long)(m0 + r) * 256 + kc + c8 * 8]);
            }
            #pragma unroll
            for (int i = tid; i < 512; i += NTHREADS) {
                int r = i >> 3, c8 = i & 7;
                *reinterpret_cast<uint4*>(&Bs[r * PPAD + c8 * 8]) =
                    *reinterpret_cast<const uint4*>(&Bp[(long)(n0 + r) * 256 + kc + c8 * 8]);
            }
            __syncthreads();
            #pragma unroll
            for (int k16 = 0; k16 < 4; k16++) {
                unsigned a[2][4];
                #pragma unroll
                for (int mt = 0; mt < 2; mt++) {
                    unsigned addr = a_base +
                        ((wm + mt * 16 + lrow) * PPAD + k16 * 16 + lcol8) * 2;
                    asm volatile("ldmatrix.sync.aligned.m8n8.x4.shared.b16 "
                                 "{%0,%1,%2,%3}, [%4];"
                                 : "=r"(a[mt][0]), "=r"(a[mt][1]),
                                   "=r"(a[mt][2]), "=r"(a[mt][3]) : "r"(addr));
                }
                unsigned b[4][2];
                #pragma unroll
                for (int nh = 0; nh < 2; nh++) {
                    unsigned r0, r1, r2, r3;
                    unsigned addr = b_base +
                        ((wn + nh * 16 + lrow) * PPAD + k16 * 16 + lcol8) * 2;
                    asm volatile("ldmatrix.sync.aligned.m8n8.x4.shared.b16 "
                                 "{%0,%1,%2,%3}, [%4];"
                                 : "=r"(r0), "=r"(r1), "=r"(r2), "=r"(r3) : "r"(addr));
                    b[nh * 2 + 0][0] = r0; b[nh * 2 + 0][1] = r2;
                    b[nh * 2 + 1][0] = r1; b[nh * 2 + 1][1] = r3;
                }
                #pragma unroll
                for (int mt = 0; mt < 2; mt++)
                    #pragma unroll
                    for (int nt = 0; nt < 4; nt++) {
                        asm volatile(
                            "mma.sync.aligned.m16n8k16.row.col.f32.bf16.bf16.f32 "
                            "{%0,%1,%2,%3}, {%4,%5,%6,%7}, {%8,%9}, {%0,%1,%2,%3};"
                            : "+f"(acc[mt][nt][0]), "+f"(acc[mt][nt][1]),
                              "+f"(acc[mt][nt][2]), "+f"(acc[mt][nt][3])
                            : "r"(a[mt][0]), "r"(a[mt][1]), "r"(a[mt][2]), "r"(a[mt][3]),
                              "r"(b[nt][0]), "r"(b[nt][1]));
                    }
            }
        }
    }
    const int gid = lane >> 2, tq = (lane & 3) * 2;
    #pragma unroll
    for (int mt = 0; mt < 2; mt++) {
        #pragma unroll
        for (int nt = 0; nt < 4; nt++) {
            int col = n0 + wn + nt * 8 + tq;
            float bx = bias[col], by = bias[col + 1];
            int row0 = m0 + wm + mt * 16 + gid;
            float2 v0 = make_float2(acc[mt][nt][0] + bx, acc[mt][nt][1] + by);
            float2 v1 = make_float2(acc[mt][nt][2] + bx, acc[mt][nt][3] + by);
            *reinterpret_cast<float2*>(&out[(long)row0 * 960 + col]) = v0;
            *reinterpret_cast<float2*>(&out[(long)(row0 + 8) * 960 + col]) = v1;
        }
    }
}

// ---------------------------------------------------------------------------
// Value head
// ---------------------------------------------------------------------------
__global__ __launch_bounds__(NTHREADS) void val_kernel(
    const float* __restrict__ x, const float* __restrict__ vW,
    const float* __restrict__ vb, float* __restrict__ V)
{
    int warp = threadIdx.x >> 5, lane = threadIdx.x & 31;
    int m = blockIdx.x * 8 + warp;
    float s = 0.f;
    #pragma unroll
    for (int k = lane; k < 256; k += 32) s += x[(long)m * 256 + k] * vW[k];
    #pragma unroll
    for (int off = 16; off > 0; off >>= 1) s += __shfl_xor_sync(0xffffffffu, s, off);
    if (lane == 0) V[m] = s + vb[0];
}

// ---------------------------------------------------------------------------
// Launch
// ---------------------------------------------------------------------------
extern "C" void kernel_launch(void* const* d_in, const int* in_sizes, int n_in,
                              void* d_out, int out_size)
{
    const float* z0       = (const float*)d_in[0];
    const float* edge     = (const float*)d_in[3];
    const float* phiE_W1  = (const float*)d_in[4];
    const float* phiE_b1  = (const float*)d_in[5];
    const float* phiE_W2  = (const float*)d_in[6];
    const float* phiE_b2  = (const float*)d_in[7];
    const float* phiN_W1  = (const float*)d_in[8];
    const float* phiN_b1  = (const float*)d_in[9];
    const float* phiN_g   = (const float*)d_in[10];
    const float* phiN_be  = (const float*)d_in[11];
    const float* phiN_W2  = (const float*)d_in[12];
    const float* phiN_b2  = (const float*)d_in[13];
    const float* sh_W     = (const float*)d_in[14];
    const float* sh_b     = (const float*)d_in[15];
    const float* ln_g     = (const float*)d_in[16];
    const float* ln_b     = (const float*)d_in[17];
    const float* pol_W    = (const float*)d_in[18];
    const float* pol_b    = (const float*)d_in[19];
    const float* val_W    = (const float*)d_in[20];
    const float* val_b    = (const float*)d_in[21];
    float* outf = (float*)d_out;

    float* S = nullptr;
    cudaGetSymbolAddress((void**)&S, g_scratch);
    __nv_bfloat16* Bf = nullptr;
    cudaGetSymbolAddress((void**)&Bf, g_bf);

    cudaFuncSetAttribute(mega_kernel, cudaFuncAttributeMaxDynamicSharedMemorySize, SM_MEGA);

    // --- prep + weight splits ---
    prep_kernel<<<1, 128>>>(phiE_W1, phiE_b1, edge);
    wsplit_kernel<<<dim3(30, 8), dim3(32, 8)>>>(pol_W);
    {
        WJobs jb;
        jb.j[0] = { phiE_W1,           phiE_W1 + 128*128, 128, 128, WB+0,      WB+16384 };
        jb.j[1] = { phiE_W2,           nullptr,           128, 128, WB+32768,  WB+49152 };
        jb.j[2] = { phiN_W1,           nullptr,           256, 128, WB+65536,  WB+98304 };
        jb.j[3] = { phiN_W2,           nullptr,           128, 128, WB+131072, WB+147456 };
        jb.j[4] = { phiE_W1 + 257*128, nullptr,           256, 128, WB+163840, WB+196608 };
        jb.j[5] = { phiE_W2 + 128*128, nullptr,           128, 128, WB+229376, WB+245760 };
        jb.j[6] = { phiN_W1 + 256*128, nullptr,           256, 128, WB+262144, WB+294912 };
        jb.j[7] = { phiN_W2 + 128*128, nullptr,           128, 128, WB+327680, WB+344064 };
        jb.j[8] = { sh_W,              nullptr,           128, 256, WB+360448, WB+393216 };
        wsplitT_kernel<<<dim3(8, 8, 9), dim3(32, 8)>>>(jb);
    }

    // --- full backbone in one persistent kernel (512 threads/block) ---
    mega_kernel<<<B / 32, MT, SM_MEGA>>>(
        z0, S + OFF_BE0, S + OFF_BE1, phiE_b2,
        phiN_b1, phiN_g, phiN_be, phiN_b2,
        S + OFF_ZG, Bf);

    // --- heads ---
    sh_kernel<<<B / 32, NTHREADS>>>(S + OFF_ZG, sh_W, sh_b, ln_g, ln_b, S + OFF_X,
                                    Bf + OB_XH, Bf + OB_XL);
    pol_mma_kernel<<<dim3(960 / 64, B / 128), NTHREADS>>>(
        Bf + OB_XH, Bf + OB_XL, Bf + OB_WTH, Bf + OB_WTL, pol_b, outf);
    val_kernel<<<B / 8, NTHREADS>>>(S + OFF_X, val_W, val_b, outf + (long)B * 960);
}

// round 15
// speedup vs baseline: 1.7231x; 1.0128x over previous
#include <cuda_runtime.h>
#include <cuda_bf16.h>

#define B 4096
#define NTHREADS 256
#define MT 512          // mega kernel threads

// ---------------------------------------------------------------------------
// fp32 scratch
// ---------------------------------------------------------------------------
#define OFF_BE0   16384        // 128 folded bias k0
#define OFF_BE1   16512        // 128 folded bias k1
#define SCRATCH_TOTAL 12075264
__device__ float g_scratch[SCRATCH_TOTAL];

// bf16 scratch
#define OB_WTH 0               // pol WT hi [960,256]
#define OB_WTL 245760          // pol WT lo
#define OB_XH  491520          // x hi [B,256]
#define OB_XL  1540096         // x lo
#define WB     2588672         // backbone weights (transposed, hi/lo)
#define BF_TOTAL 3014656
__device__ __nv_bfloat16 g_bf[BF_TOTAL];

// job0 WE0T  hi WB+0       lo WB+16384
// job1 E2k0T hi WB+32768   lo WB+49152
// job2 N1k0T hi WB+65536   lo WB+98304
// job3 N2k0T hi WB+131072  lo WB+147456
// job4 E1k1T hi WB+163840  lo WB+196608
// job5 E2k1T hi WB+229376  lo WB+245760
// job6 N1k1T hi WB+262144  lo WB+294912
// job7 N2k1T hi WB+327680  lo WB+344064
// job8 shWT  hi WB+360448  lo WB+393216  (rows 128.. at +16384)

__device__ __forceinline__ unsigned smem_u32(const void* p) {
    unsigned a;
    asm("{ .reg .u64 t; cvta.to.shared.u64 t, %1; cvt.u32.u64 %0, t; }" : "=r"(a) : "l"(p));
    return a;
}
__device__ __forceinline__ void cpasync16(void* dst, const void* g) {
    asm volatile("cp.async.ca.shared.global [%0], [%1], 16;"
                 :: "r"(smem_u32(dst)), "l"(g));
}

// ---------------------------------------------------------------------------
// Prep: folded edge-bias terms
// ---------------------------------------------------------------------------
__global__ __launch_bounds__(128) void prep_kernel(
    const float* __restrict__ phiE_W1, const float* __restrict__ phiE_b1,
    const float* __restrict__ edge_attr)
{
    int i = threadIdx.x;
    float e = edge_attr[0];
    g_scratch[OFF_BE0 + i] = phiE_b1[i]       + e * phiE_W1[256 * 128 + i];
    g_scratch[OFF_BE1 + i] = phiE_b1[128 + i] + e * phiE_W1[257 * 128 + 256 * 128 + i];
}

// ---------------------------------------------------------------------------
// Batched weight transpose + bf16 split: src [K,N] fp32 -> dst [N,K] bf16 hi/lo
// ---------------------------------------------------------------------------
struct WJob { const float* src; const float* src2; int K; int N; long dstHi; long dstLo; };
struct WJobs { WJob j[9]; };

__global__ void wsplitT_kernel(WJobs jobs)
{
    WJob jb = jobs.j[blockIdx.z];
    int kb = blockIdx.y * 32, nb = blockIdx.x * 32;
    if (kb >= jb.K || nb >= jb.N) return;
    __shared__ float t[32][33];
    int tx = threadIdx.x, ty = threadIdx.y;
    for (int j = ty; j < 32; j += 8) {
        float v = jb.src[(long)(kb + j) * jb.N + nb + tx];
        if (jb.src2) v += jb.src2[(long)(kb + j) * jb.N + nb + tx];
        t[j][tx] = v;
    }
    __syncthreads();
    for (int j = ty; j < 32; j += 8) {
        float v = t[tx][j];
        __nv_bfloat16 h = __float2bfloat16(v);
        long o = (long)(nb + j) * jb.K + kb + tx;
        g_bf[jb.dstHi + o] = h;
        g_bf[jb.dstLo + o] = __float2bfloat16(v - __bfloat162float(h));
    }
}

__global__ void wsplit_kernel(const float* __restrict__ W)
{
    __shared__ float t[32][33];
    int kb = blockIdx.y * 32, nb = blockIdx.x * 32;
    int tx = threadIdx.x, ty = threadIdx.y;
    for (int j = ty; j < 32; j += 8)
        t[j][tx] = W[(long)(kb + j) * 960 + nb + tx];
    __syncthreads();
    for (int j = ty; j < 32; j += 8) {
        float v = t[tx][j];
        __nv_bfloat16 h = __float2bfloat16(v);
        long o = (long)(nb + j) * 256 + kb + tx;
        g_bf[OB_WTH + o] = h;
        g_bf[OB_WTL + o] = __float2bfloat16(v - __bfloat162float(h));
    }
}

// ---------------------------------------------------------------------------
// MEGAKERNEL: entire backbone + shared head per 32-row batch slice.
// ---------------------------------------------------------------------------
#define APAD 40
#define SM_MEGA 219136

struct SP {
    float4* z0s;  // 32 x 32
    float4* H;    // 64 x 32
    float4* M;    // 96 x 32 (also 32x256 C for shared head)
    float4* U;    // 96 x 32
};
struct ST {
    __nv_bfloat16* Ah[2]; __nv_bfloat16* Al[2];
    __nv_bfloat16* Wh[2]; __nv_bfloat16* Wl[2];
};

__device__ __forceinline__ float4 getA(int ph, const SP& sp, int r, int kk4)
{
    int v = r >> 5, b = r & 31;
    switch (ph) {
    case 1: return sp.z0s[b * 32 + kk4];
    case 3:
        if (kk4 < 32) return sp.z0s[b * 32 + kk4];
        else {
            float4 m = sp.M[b * 32 + kk4 - 32];
            if (v == 1) { m.x *= 2.f; m.y *= 2.f; m.z *= 2.f; m.w *= 2.f; }
            return m;
        }
    case 5: {
        int cls = (kk4 < 32) ? (v == 0 ? 0 : 1) : (v == 1 ? 0 : 1);
        int k = (kk4 < 32) ? kk4 : kk4 - 32;
        return sp.H[(cls * 32 + b) * 32 + k];
    }
    case 7:
        if (kk4 < 32) return sp.H[((v == 0 ? 0 : 1) * 32 + b) * 32 + kk4];
        else {
            int k = kk4 - 32;
            if (v == 0) return sp.M[b * 32 + k];
            if (v == 1) {
                float4 a = sp.M[(32 + b) * 32 + k], c = sp.M[(64 + b) * 32 + k];
                return make_float4(a.x + c.x, a.y + c.y, a.z + c.z, a.w + c.w);
            }
            float4 c = sp.M[(64 + b) * 32 + k];
            return make_float4(2.f * c.x, 2.f * c.y, 2.f * c.z, 2.f * c.w);
        }
    case 9: return sp.M[b * 32 + kk4];           // umix
    default: return sp.U[r * 32 + kk4];          // cases 2,4,6,10
    }
}

__device__ __forceinline__ void stageW(const __nv_bfloat16* Whi, const __nv_bfloat16* Wlo,
                                       int K, int ch, const ST& st, int buf, int tid)
{
    #pragma unroll
    for (int idx = tid; idx < 1024; idx += MT) {
        int mtx = idx >> 9, r = (idx >> 2) & 127, c = idx & 3;
        const __nv_bfloat16* src = (mtx ? Wlo : Whi) + (long)r * K + ch * 32 + c * 8;
        __nv_bfloat16* dst = (mtx ? st.Wl[buf] : st.Wh[buf]) + r * APAD + c * 8;
        cpasync16(dst, src);
    }
    asm volatile("cp.async.commit_group;");
}

__device__ __forceinline__ void convA(int ph, const SP& sp, const ST& st,
                                      int Mr, int ch, int buf, int tid)
{
    int n4 = Mr * 8;
    for (int idx = tid; idx < n4; idx += MT) {
        int r = idx >> 3, c4 = idx & 7;
        float4 val = getA(ph, sp, r, ch * 8 + c4);
        __nv_bfloat16 h0 = __float2bfloat16(val.x), h1 = __float2bfloat16(val.y);
        __nv_bfloat16 h2 = __float2bfloat16(val.z), h3 = __float2bfloat16(val.w);
        __nv_bfloat162 hp0; hp0.x = h0; hp0.y = h1;
        __nv_bfloat162 hp1; hp1.x = h2; hp1.y = h3;
        int o = r * APAD + c4 * 4;
        *reinterpret_cast<__nv_bfloat162*>(&st.Ah[buf][o])     = hp0;
        *reinterpret_cast<__nv_bfloat162*>(&st.Ah[buf][o + 2]) = hp1;
        __nv_bfloat162 lp0, lp1;
        lp0.x = __float2bfloat16(val.x - __bfloat162float(h0));
        lp0.y = __float2bfloat16(val.y - __bfloat162float(h1));
        lp1.x = __float2bfloat16(val.z - __bfloat162float(h2));
        lp1.y = __float2bfloat16(val.w - __bfloat162float(h3));
        *reinterpret_cast<__nv_bfloat162*>(&st.Al[buf][o])     = lp0;
        *reinterpret_cast<__nv_bfloat162*>(&st.Al[buf][o + 2]) = lp1;
    }
}

// One GEMM phase with 16 warps. out columns land at [ocol, ocol+128) of rows
// with stride ostride in outp.
__device__ void gphase(int ph, int Mr, int K,
                       const __nv_bfloat16* Whi, const __nv_bfloat16* Wlo,
                       const float* bias, int do_relu,
                       const float* lng, const float* lnb,
                       const float* resid,
                       float* outp, int ostride, int ocol,
                       const SP& sp, const ST& st)
{
    const int tid = threadIdx.x, lane = tid & 31, w = tid >> 5;
    const int wm = (w & 3) * 16, wn = (w >> 2) * 32;
    const int lrow = lane & 15, lcol8 = (lane >> 4) * 8;
    const int nch = K / 32;
    const int nmi = (Mr + 63) / 64;

    float acc[2][4][4];
    #pragma unroll
    for (int it = 0; it < 2; it++)
        #pragma unroll
        for (int nt = 0; nt < 4; nt++)
            #pragma unroll
            for (int q = 0; q < 4; q++) acc[it][nt][q] = 0.f;

    stageW(Whi, Wlo, K, 0, st, 0, tid);
    convA(ph, sp, st, Mr, 0, 0, tid);

    for (int ch = 0; ch < nch; ch++) {
        const int cur = ch & 1;
        if (ch + 1 < nch) {
            stageW(Whi, Wlo, K, ch + 1, st, cur ^ 1, tid);
            convA(ph, sp, st, Mr, ch + 1, cur ^ 1, tid);
            asm volatile("cp.async.wait_group 1;");
        } else {
            asm volatile("cp.async.wait_group 0;");
        }
        __syncthreads();

        const unsigned ahB = smem_u32(st.Ah[cur]), alB = smem_u32(st.Al[cur]);
        const unsigned whB = smem_u32(st.Wh[cur]), wlB = smem_u32(st.Wl[cur]);
        #pragma unroll
        for (int k16 = 0; k16 < 2; k16++) {
            unsigned bh[4][2], bl[4][2];
            #pragma unroll
            for (int nh = 0; nh < 2; nh++) {
                unsigned off = ((wn + nh * 16 + lrow) * APAD + k16 * 16 + lcol8) * 2;
                unsigned r0, r1, r2, r3;
                asm volatile("ldmatrix.sync.aligned.m8n8.x4.shared.b16 {%0,%1,%2,%3}, [%4];"
                             : "=r"(r0), "=r"(r1), "=r"(r2), "=r"(r3) : "r"(whB + off));
                bh[nh*2+0][0] = r0; bh[nh*2+0][1] = r2;
                bh[nh*2+1][0] = r1; bh[nh*2+1][1] = r3;
                asm volatile("ldmatrix.sync.aligned.m8n8.x4.shared.b16 {%0,%1,%2,%3}, [%4];"
                             : "=r"(r0), "=r"(r1), "=r"(r2), "=r"(r3) : "r"(wlB + off));
                bl[nh*2+0][0] = r0; bl[nh*2+0][1] = r2;
                bl[nh*2+1][0] = r1; bl[nh*2+1][1] = r3;
            }
            #pragma unroll 2
            for (int it = 0; it < nmi; it++) {
                int rb = it * 64 + wm;
                if (rb < Mr) {
                    unsigned ah[4], al[4];
                    unsigned off = ((rb + lrow) * APAD + k16 * 16 + lcol8) * 2;
                    asm volatile("ldmatrix.sync.aligned.m8n8.x4.shared.b16 {%0,%1,%2,%3}, [%4];"
                                 : "=r"(ah[0]), "=r"(ah[1]), "=r"(ah[2]), "=r"(ah[3])
                                 : "r"(ahB + off));
                    asm volatile("ldmatrix.sync.aligned.m8n8.x4.shared.b16 {%0,%1,%2,%3}, [%4];"
                                 : "=r"(al[0]), "=r"(al[1]), "=r"(al[2]), "=r"(al[3])
                                 : "r"(alB + off));
                    #pragma unroll
                    for (int nt = 0; nt < 4; nt++) {
                        asm volatile(
                            "mma.sync.aligned.m16n8k16.row.col.f32.bf16.bf16.f32 "
                            "{%0,%1,%2,%3}, {%4,%5,%6,%7}, {%8,%9}, {%0,%1,%2,%3};"
                            : "+f"(acc[it][nt][0]), "+f"(acc[it][nt][1]),
                              "+f"(acc[it][nt][2]), "+f"(acc[it][nt][3])
                            : "r"(ah[0]), "r"(ah[1]), "r"(ah[2]), "r"(ah[3]),
                              "r"(bh[nt][0]), "r"(bh[nt][1]));
                        asm volatile(
                            "mma.sync.aligned.m16n8k16.row.col.f32.bf16.bf16.f32 "
                            "{%0,%1,%2,%3}, {%4,%5,%6,%7}, {%8,%9}, {%0,%1,%2,%3};"
                            : "+f"(acc[it][nt][0]), "+f"(acc[it][nt][1]),
                              "+f"(acc[it][nt][2]), "+f"(acc[it][nt][3])
                            : "r"(ah[0]), "r"(ah[1]), "r"(ah[2]), "r"(ah[3]),
                              "r"(bl[nt][0]), "r"(bl[nt][1]));
                        asm volatile(
                            "mma.sync.aligned.m16n8k16.row.col.f32.bf16.bf16.f32 "
                            "{%0,%1,%2,%3}, {%4,%5,%6,%7}, {%8,%9}, {%0,%1,%2,%3};"
                            : "+f"(acc[it][nt][0]), "+f"(acc[it][nt][1]),
                              "+f"(acc[it][nt][2]), "+f"(acc[it][nt][3])
                            : "r"(al[0]), "r"(al[1]), "r"(al[2]), "r"(al[3]),
                              "r"(bh[nt][0]), "r"(bh[nt][1]));
                    }
                }
            }
        }
        __syncthreads();
    }

    // raw accums -> outp
    const int gid = lane >> 2, tq = (lane & 3) * 2;
    #pragma unroll 2
    for (int it = 0; it < nmi; it++) {
        int rb = it * 64 + wm;
        if (rb < Mr) {
            #pragma unroll
            for (int nt = 0; nt < 4; nt++) {
                int r = rb + gid, c = ocol + wn + nt * 8 + tq;
                outp[r * ostride + c]           = acc[it][nt][0];
                outp[r * ostride + c + 1]       = acc[it][nt][1];
                outp[(r + 8) * ostride + c]     = acc[it][nt][2];
                outp[(r + 8) * ostride + c + 1] = acc[it][nt][3];
            }
        }
    }
    __syncthreads();

    // row epilogue over the 128 cols written by this phase
    float4 bv = *reinterpret_cast<const float4*>(&bias[lane * 4]);
    float4 gv, ev;
    if (lng) {
        gv = *reinterpret_cast<const float4*>(&lng[lane * 4]);
        ev = *reinterpret_cast<const float4*>(&lnb[lane * 4]);
    }
    for (int r = w; r < Mr; r += 16) {
        int b = r & 31;
        float4 vv = *reinterpret_cast<float4*>(&outp[r * ostride + ocol + lane * 4]);
        vv.x += bv.x; vv.y += bv.y; vv.z += bv.z; vv.w += bv.w;
        if (do_relu) {
            vv.x = fmaxf(vv.x, 0.f); vv.y = fmaxf(vv.y, 0.f);
            vv.z = fmaxf(vv.z, 0.f); vv.w = fmaxf(vv.w, 0.f);
        }
        if (lng) {
            float su = vv.x + vv.y + vv.z + vv.w;
            float q = vv.x*vv.x + vv.y*vv.y + vv.z*vv.z + vv.w*vv.w;
            #pragma unroll
            for (int off = 16; off > 0; off >>= 1) {
                su += __shfl_xor_sync(0xffffffffu, su, off);
                q  += __shfl_xor_sync(0xffffffffu, q, off);
            }
            float mu = su * (1.f / 128.f);
            float var = q * (1.f / 128.f) - mu * mu;
            float rs = rsqrtf(var + 1e-5f);
            vv.x = (vv.x - mu) * rs * gv.x + ev.x;
            vv.y = (vv.y - mu) * rs * gv.y + ev.y;
            vv.z = (vv.z - mu) * rs * gv.z + ev.z;
            vv.w = (vv.w - mu) * rs * gv.w + ev.w;
        }
        if (resid) {
            float4 rv = *reinterpret_cast<const float4*>(&resid[b * 128 + lane * 4]);
            vv.x += rv.x; vv.y += rv.y; vv.z += rv.z; vv.w += rv.w;
        }
        *reinterpret_cast<float4*>(&outp[r * ostride + ocol + lane * 4]) = vv;
    }
    __syncthreads();
}

__global__ __launch_bounds__(MT, 1) void mega_kernel(
    const float* __restrict__ z0,
    const float* __restrict__ be0, const float* __restrict__ be1,
    const float* __restrict__ phiE_b2,
    const float* __restrict__ phiN_b1, const float* __restrict__ phiN_g,
    const float* __restrict__ phiN_be, const float* __restrict__ phiN_b2,
    const float* __restrict__ sh_b, const float* __restrict__ ln_g,
    const float* __restrict__ ln_b,
    __nv_bfloat16* __restrict__ xh, __nv_bfloat16* __restrict__ xl,
    const __nv_bfloat16* __restrict__ wb)
{
    extern __shared__ __align__(16) char sm[];
    float* z0s = reinterpret_cast<float*>(sm);              // 16384 B
    float* H   = reinterpret_cast<float*>(sm + 16384);      // 32768
    float* M   = reinterpret_cast<float*>(sm + 49152);      // 49152
    float* U   = reinterpret_cast<float*>(sm + 98304);      // 49152
    ST st;
    st.Ah[0] = reinterpret_cast<__nv_bfloat16*>(sm + 147456);
    st.Al[0] = reinterpret_cast<__nv_bfloat16*>(sm + 155136);
    st.Ah[1] = reinterpret_cast<__nv_bfloat16*>(sm + 162816);
    st.Al[1] = reinterpret_cast<__nv_bfloat16*>(sm + 170496);
    st.Wh[0] = reinterpret_cast<__nv_bfloat16*>(sm + 178176);
    st.Wl[0] = reinterpret_cast<__nv_bfloat16*>(sm + 188416);
    st.Wh[1] = reinterpret_cast<__nv_bfloat16*>(sm + 198656);
    st.Wl[1] = reinterpret_cast<__nv_bfloat16*>(sm + 208896);
    SP sp;
    sp.z0s = reinterpret_cast<float4*>(z0s);
    sp.H   = reinterpret_cast<float4*>(H);
    sp.M   = reinterpret_cast<float4*>(M);
    sp.U   = reinterpret_cast<float4*>(U);

    const int tid = threadIdx.x, lane = tid & 31, w = tid >> 5;
    const int bb = blockIdx.x;

    {   // load z0 slice
        const float4* zsrc = reinterpret_cast<const float4*>(z0 + (long)bb * 32 * 128);
        #pragma unroll
        for (int i = tid; i < 1024; i += MT) sp.z0s[i] = zsrc[i];
    }
    __syncthreads();

    // P1: T = relu(z0 @ WE0 + be0) -> U[0:32]
    gphase(1, 32, 128, wb + WB + 0, wb + WB + 16384, be0, 1,
           nullptr, nullptr, nullptr, U, 128, 0, sp, st);
    // P2: m0 = T @ E2k0 + b2 -> M[0:32]
    gphase(2, 32, 128, wb + WB + 32768, wb + WB + 49152, phiE_b2, 0,
           nullptr, nullptr, nullptr, M, 128, 0, sp, st);
    // P3: U = LN(relu(pack0 @ N1k0 + b1)) -> U[0:64]
    gphase(3, 64, 256, wb + WB + 65536, wb + WB + 98304, phiN_b1, 1,
           phiN_g, phiN_be, nullptr, U, 128, 0, sp, st);
    // P4: H = U @ N2k0 + b2 + z0 -> H[0:64]
    gphase(4, 64, 128, wb + WB + 131072, wb + WB + 147456, phiN_b2, 0,
           nullptr, nullptr, z0s, H, 128, 0, sp, st);
    // P5: T = relu(pack1 @ E1k1 + be1) -> U[0:96]
    gphase(5, 96, 256, wb + WB + 163840, wb + WB + 196608, be1, 1,
           nullptr, nullptr, nullptr, U, 128, 0, sp, st);
    // P6: m1 = T @ E2k1 + b2' -> M[0:96]
    gphase(6, 96, 128, wb + WB + 229376, wb + WB + 245760, phiE_b2 + 128, 0,
           nullptr, nullptr, nullptr, M, 128, 0, sp, st);
    // P7: U = LN(relu(pack2 @ N1k1 + b1')) -> U[0:96]
    gphase(7, 96, 256, wb + WB + 262144, wb + WB + 294912, phiN_b1 + 128, 1,
           phiN_g + 128, phiN_be + 128, nullptr, U, 128, 0, sp, st);
    // mix: umix -> M[0:32], hmix -> M[32:64]
    for (int idx = tid; idx < 1024; idx += MT) {
        int r = idx >> 5, c = idx & 31;
        float4 u0 = sp.U[r * 32 + c], u1 = sp.U[(32 + r) * 32 + c], u2 = sp.U[(64 + r) * 32 + c];
        float4 rm;
        rm.x = (2.f * (u0.x + u1.x) + 60.f * u2.x) * (1.f / 64.f);
        rm.y = (2.f * (u0.y + u1.y) + 60.f * u2.y) * (1.f / 64.f);
        rm.z = (2.f * (u0.z + u1.z) + 60.f * u2.z) * (1.f / 64.f);
        rm.w = (2.f * (u0.w + u1.w) + 60.f * u2.w) * (1.f / 64.f);
        sp.M[r * 32 + c] = rm;
        float4 h0 = sp.H[r * 32 + c], h1 = sp.H[(32 + r) * 32 + c];
        float4 rh;
        rh.x = (2.f * h0.x + 62.f * h1.x) * (1.f / 64.f);
        rh.y = (2.f * h0.y + 62.f * h1.y) * (1.f / 64.f);
        rh.z = (2.f * h0.z + 62.f * h1.z) * (1.f / 64.f);
        rh.w = (2.f * h0.w + 62.f * h1.w) * (1.f / 64.f);
        sp.M[(32 + r) * 32 + c] = rh;
    }
    __syncthreads();
    // P9: zG = umix @ N2k1 + b2' + hmix -> U[0:32]
    gphase(9, 32, 128, wb + WB + 327680, wb + WB + 344064, phiN_b2 + 128, 0,
           nullptr, nullptr, M + 32 * 128, U, 128, 0, sp, st);
    // P10a/b: x = relu(zG @ sh_W + sh_b), both 128-col halves into C=M (32x256)
    gphase(10, 32, 128, wb + WB + 360448, wb + WB + 393216, sh_b, 1,
           nullptr, nullptr, nullptr, M, 256, 0, sp, st);
    gphase(10, 32, 128, wb + WB + 376832, wb + WB + 409600, sh_b + 128, 1,
           nullptr, nullptr, nullptr, M, 256, 128, sp, st);

    // LN256 over C rows + emit bf16 hi/lo split to global
    {
        float4 g0 = *reinterpret_cast<const float4*>(&ln_g[lane * 4]);
        float4 g1 = *reinterpret_cast<const float4*>(&ln_g[128 + lane * 4]);
        float4 e0 = *reinterpret_cast<const float4*>(&ln_b[lane * 4]);
        float4 e1 = *reinterpret_cast<const float4*>(&ln_b[128 + lane * 4]);
        for (int r = w; r < 32; r += 16) {
            float4 v0 = *reinterpret_cast<float4*>(&M[r * 256 + lane * 4]);
            float4 v1 = *reinterpret_cast<float4*>(&M[r * 256 + 128 + lane * 4]);
            float su = v0.x + v0.y + v0.z + v0.w + v1.x + v1.y + v1.z + v1.w;
            float q = v0.x*v0.x + v0.y*v0.y + v0.z*v0.z + v0.w*v0.w
                    + v1.x*v1.x + v1.y*v1.y + v1.z*v1.z + v1.w*v1.w;
            #pragma unroll
            for (int off = 16; off > 0; off >>= 1) {
                su += __shfl_xor_sync(0xffffffffu, su, off);
                q  += __shfl_xor_sync(0xffffffffu, q, off);
            }
            float mu = su * (1.f / 256.f);
            float var = q * (1.f / 256.f) - mu * mu;
            float rs = rsqrtf(var + 1e-5f);
            v0.x = (v0.x - mu) * rs * g0.x + e0.x;
            v0.y = (v0.y - mu) * rs * g0.y + e0.y;
            v0.z = (v0.z - mu) * rs * g0.z + e0.z;
            v0.w = (v0.w - mu) * rs * g0.w + e0.w;
            v1.x = (v1.x - mu) * rs * g1.x + e1.x;
            v1.y = (v1.y - mu) * rs * g1.y + e1.y;
            v1.z = (v1.z - mu) * rs * g1.z + e1.z;
            v1.w = (v1.w - mu) * rs * g1.w + e1.w;
            long row = (long)bb * 32 + r;
            __nv_bfloat162* XH = reinterpret_cast<__nv_bfloat162*>(xh + row * 256);
            __nv_bfloat162* XL = reinterpret_cast<__nv_bfloat162*>(xl + row * 256);
            float vals[8] = {v0.x, v0.y, v0.z, v0.w, v1.x, v1.y, v1.z, v1.w};
            #pragma unroll
            for (int half = 0; half < 2; half++) {
                #pragma unroll
                for (int j = 0; j < 2; j++) {
                    float va = vals[half * 4 + j * 2], vb2 = vals[half * 4 + j * 2 + 1];
                    __nv_bfloat16 ha = __float2bfloat16(va), hb2 = __float2bfloat16(vb2);
                    __nv_bfloat162 hp; hp.x = ha; hp.y = hb2;
                    XH[half * 64 + lane * 2 + j] = hp;
                    __nv_bfloat162 lp;
                    lp.x = __float2bfloat16(va - __bfloat162float(ha));
                    lp.y = __float2bfloat16(vb2 - __bfloat162float(hb2));
                    XL[half * 64 + lane * 2 + j] = lp;
                }
            }
        }
    }
}

// ---------------------------------------------------------------------------
// Policy head mma (validated)
// ---------------------------------------------------------------------------
#define PPAD 72

__global__ __launch_bounds__(NTHREADS) void pol_mma_kernel(
    const __nv_bfloat16* __restrict__ Xhi, const __nv_bfloat16* __restrict__ Xlo,
    const __nv_bfloat16* __restrict__ Whi, const __nv_bfloat16* __restrict__ Wlo,
    const float* __restrict__ bias, float* __restrict__ out)
{
    __shared__ __align__(16) __nv_bfloat16 As[128 * PPAD];
    __shared__ __align__(16) __nv_bfloat16 Bs[64 * PPAD];
    const int tid = threadIdx.x;
    const int lane = tid & 31, w = tid >> 5;
    const int wm = (w & 3) * 32, wn = (w >> 2) * 32;
    const int m0 = blockIdx.y * 128, n0 = blockIdx.x * 64;

    float acc[2][4][4];
    #pragma unroll
    for (int mt = 0; mt < 2; mt++)
        #pragma unroll
        for (int nt = 0; nt < 4; nt++)
            #pragma unroll
            for (int q = 0; q < 4; q++) acc[mt][nt][q] = 0.f;

    const __nv_bfloat16* Aps[3] = {Xhi, Xhi, Xlo};
    const __nv_bfloat16* Bps[3] = {Whi, Wlo, Whi};

    const unsigned a_base = smem_u32(As);
    const unsigned b_base = smem_u32(Bs);
    const int lrow = lane & 15, lcol8 = (lane >> 4) * 8;

    for (int p = 0; p < 3; p++) {
        const __nv_bfloat16* Ap = Aps[p];
        const __nv_bfloat16* Bp = Bps[p];
        for (int kc = 0; kc < 256; kc += 64) {
            __syncthreads();
            #pragma unroll
            for (int i = tid; i < 1024; i += NTHREADS) {
                int r = i >> 3, c8 = i & 7;
                *reinterpret_cast<uint4*>(&As[r * PPAD + c8 * 8]) =
                    *reinterpret_cast<const uint4*>(&Ap[(long)(m0 + r) * 256 + kc + c8 * 8]);
            }
            #pragma unroll
            for (int i = tid; i < 512; i += NTHREADS) {
                int r = i >> 3, c8 = i & 7;
                *reinterpret_cast<uint4*>(&Bs[r * PPAD + c8 * 8]) =
                    *reinterpret_cast<const uint4*>(&Bp[(long)(n0 + r) * 256 + kc + c8 * 8]);
            }
            __syncthreads();
            #pragma unroll
            for (int k16 = 0; k16 < 4; k16++) {
                unsigned a[2][4];
                #pragma unroll
                for (int mt = 0; mt < 2; mt++) {
                    unsigned addr = a_base +
                        ((wm + mt * 16 + lrow) * PPAD + k16 * 16 + lcol8) * 2;
                    asm volatile("ldmatrix.sync.aligned.m8n8.x4.shared.b16 "
                                 "{%0,%1,%2,%3}, [%4];"
                                 : "=r"(a[mt][0]), "=r"(a[mt][1]),
                                   "=r"(a[mt][2]), "=r"(a[mt][3]) : "r"(addr));
                }
                unsigned b[4][2];
                #pragma unroll
                for (int nh = 0; nh < 2; nh++) {
                    unsigned r0, r1, r2, r3;
                    unsigned addr = b_base +
                        ((wn + nh * 16 + lrow) * PPAD + k16 * 16 + lcol8) * 2;
                    asm volatile("ldmatrix.sync.aligned.m8n8.x4.shared.b16 "
                                 "{%0,%1,%2,%3}, [%4];"
                                 : "=r"(r0), "=r"(r1), "=r"(r2), "=r"(r3) : "r"(addr));
                    b[nh * 2 + 0][0] = r0; b[nh * 2 + 0][1] = r2;
                    b[nh * 2 + 1][0] = r1; b[nh * 2 + 1][1] = r3;
                }
                #pragma unroll
                for (int mt = 0; mt < 2; mt++)
                    #pragma unroll
                    for (int nt = 0; nt < 4; nt++) {
                        asm volatile(
                            "mma.sync.aligned.m16n8k16.row.col.f32.bf16.bf16.f32 "
                            "{%0,%1,%2,%3}, {%4,%5,%6,%7}, {%8,%9}, {%0,%1,%2,%3};"
                            : "+f"(acc[mt][nt][0]), "+f"(acc[mt][nt][1]),
                              "+f"(acc[mt][nt][2]), "+f"(acc[mt][nt][3])
                            : "r"(a[mt][0]), "r"(a[mt][1]), "r"(a[mt][2]), "r"(a[mt][3]),
                              "r"(b[nt][0]), "r"(b[nt][1]));
                    }
            }
        }
    }
    const int gid = lane >> 2, tq = (lane & 3) * 2;
    #pragma unroll
    for (int mt = 0; mt < 2; mt++) {
        #pragma unroll
        for (int nt = 0; nt < 4; nt++) {
            int col = n0 + wn + nt * 8 + tq;
            float bx = bias[col], by = bias[col + 1];
            int row0 = m0 + wm + mt * 16 + gid;
            float2 v0 = make_float2(acc[mt][nt][0] + bx, acc[mt][nt][1] + by);
            float2 v1 = make_float2(acc[mt][nt][2] + bx, acc[mt][nt][3] + by);
            *reinterpret_cast<float2*>(&out[(long)row0 * 960 + col]) = v0;
            *reinterpret_cast<float2*>(&out[(long)(row0 + 8) * 960 + col]) = v1;
        }
    }
}

// ---------------------------------------------------------------------------
// Value head: x reconstructed from bf16 hi/lo split
// ---------------------------------------------------------------------------
__global__ __launch_bounds__(NTHREADS) void val_kernel(
    const __nv_bfloat16* __restrict__ xh, const __nv_bfloat16* __restrict__ xl,
    const float* __restrict__ vW, const float* __restrict__ vb,
    float* __restrict__ V)
{
    int warp = threadIdx.x >> 5, lane = threadIdx.x & 31;
    int m = blockIdx.x * 8 + warp;
    float s = 0.f;
    #pragma unroll
    for (int k = lane; k < 256; k += 32) {
        float x = __bfloat162float(xh[(long)m * 256 + k]) +
                  __bfloat162float(xl[(long)m * 256 + k]);
        s += x * vW[k];
    }
    #pragma unroll
    for (int off = 16; off > 0; off >>= 1) s += __shfl_xor_sync(0xffffffffu, s, off);
    if (lane == 0) V[m] = s + vb[0];
}

// ---------------------------------------------------------------------------
// Launch
// ---------------------------------------------------------------------------
extern "C" void kernel_launch(void* const* d_in, const int* in_sizes, int n_in,
                              void* d_out, int out_size)
{
    const float* z0       = (const float*)d_in[0];
    const float* edge     = (const float*)d_in[3];
    const float* phiE_W1  = (const float*)d_in[4];
    const float* phiE_b1  = (const float*)d_in[5];
    const float* phiE_W2  = (const float*)d_in[6];
    const float* phiE_b2  = (const float*)d_in[7];
    const float* phiN_W1  = (const float*)d_in[8];
    const float* phiN_b1  = (const float*)d_in[9];
    const float* phiN_g   = (const float*)d_in[10];
    const float* phiN_be  = (const float*)d_in[11];
    const float* phiN_W2  = (const float*)d_in[12];
    const float* phiN_b2  = (const float*)d_in[13];
    const float* sh_W     = (const float*)d_in[14];
    const float* sh_b     = (const float*)d_in[15];
    const float* ln_g     = (const float*)d_in[16];
    const float* ln_b     = (const float*)d_in[17];
    const float* pol_W    = (const float*)d_in[18];
    const float* pol_b    = (const float*)d_in[19];
    const float* val_W    = (const float*)d_in[20];
    const float* val_b    = (const float*)d_in[21];
    float* outf = (float*)d_out;

    float* S = nullptr;
    cudaGetSymbolAddress((void**)&S, g_scratch);
    __nv_bfloat16* Bf = nullptr;
    cudaGetSymbolAddress((void**)&Bf, g_bf);

    cudaFuncSetAttribute(mega_kernel, cudaFuncAttributeMaxDynamicSharedMemorySize, SM_MEGA);

    // --- prep + weight splits ---
    prep_kernel<<<1, 128>>>(phiE_W1, phiE_b1, edge);
    wsplit_kernel<<<dim3(30, 8), dim3(32, 8)>>>(pol_W);
    {
        WJobs jb;
        jb.j[0] = { phiE_W1,           phiE_W1 + 128*128, 128, 128, WB+0,      WB+16384 };
        jb.j[1] = { phiE_W2,           nullptr,           128, 128, WB+32768,  WB+49152 };
        jb.j[2] = { phiN_W1,           nullptr,           256, 128, WB+65536,  WB+98304 };
        jb.j[3] = { phiN_W2,           nullptr,           128, 128, WB+131072, WB+147456 };
        jb.j[4] = { phiE_W1 + 257*128, nullptr,           256, 128, WB+163840, WB+196608 };
        jb.j[5] = { phiE_W2 + 128*128, nullptr,           128, 128, WB+229376, WB+245760 };
        jb.j[6] = { phiN_W1 + 256*128, nullptr,           256, 128, WB+262144, WB+294912 };
        jb.j[7] = { phiN_W2 + 128*128, nullptr,           128, 128, WB+327680, WB+344064 };
        jb.j[8] = { sh_W,              nullptr,           128, 256, WB+360448, WB+393216 };
        wsplitT_kernel<<<dim3(8, 8, 9), dim3(32, 8)>>>(jb);
    }

    // --- backbone + shared head in one persistent kernel ---
    mega_kernel<<<B / 32, MT, SM_MEGA>>>(
        z0, S + OFF_BE0, S + OFF_BE1, phiE_b2,
        phiN_b1, phiN_g, phiN_be, phiN_b2,
        sh_b, ln_g, ln_b,
        Bf + OB_XH, Bf + OB_XL, Bf);

    // --- heads ---
    pol_mma_kernel<<<dim3(960 / 64, B / 128), NTHREADS>>>(
        Bf + OB_XH, Bf + OB_XL, Bf + OB_WTH, Bf + OB_WTL, pol_b, outf);
    val_kernel<<<B / 8, NTHREADS>>>(Bf + OB_XH, Bf + OB_XL, val_W, val_b,
                                    outf + (long)B * 960);
}

// round 16
// speedup vs baseline: 1.7858x; 1.0364x over previous
#include <cuda_runtime.h>
#include <cuda_bf16.h>

#define B 4096
#define NTHREADS 256
#define MT 256          // mega kernel threads (8 warps)
#define SLICE 16        // batch rows per block

// ---------------------------------------------------------------------------
// fp32 scratch
// ---------------------------------------------------------------------------
#define OFF_BE0   16384        // 128 folded bias k0
#define OFF_BE1   16512        // 128 folded bias k1
#define SCRATCH_TOTAL 12075264
__device__ float g_scratch[SCRATCH_TOTAL];

// bf16 scratch
#define OB_WTH 0               // pol WT hi [960,256]
#define OB_WTL 245760          // pol WT lo
#define OB_XH  491520          // x hi [B,256]
#define OB_XL  1540096         // x lo
#define WB     2588672         // backbone weights (transposed, hi/lo)
#define BF_TOTAL 3014656
__device__ __nv_bfloat16 g_bf[BF_TOTAL];

// job0 WE0T  hi WB+0       lo WB+16384
// job1 E2k0T hi WB+32768   lo WB+49152
// job2 N1k0T hi WB+65536   lo WB+98304
// job3 N2k0T hi WB+131072  lo WB+147456
// job4 E1k1T hi WB+163840  lo WB+196608
// job5 E2k1T hi WB+229376  lo WB+245760
// job6 N1k1T hi WB+262144  lo WB+294912
// job7 N2k1T hi WB+327680  lo WB+344064
// job8 shWT  hi WB+360448  lo WB+393216  (rows 128.. at +16384)

__device__ __forceinline__ unsigned smem_u32(const void* p) {
    unsigned a;
    asm("{ .reg .u64 t; cvta.to.shared.u64 t, %1; cvt.u32.u64 %0, t; }" : "=r"(a) : "l"(p));
    return a;
}
__device__ __forceinline__ void cpasync16(void* dst, const void* g) {
    asm volatile("cp.async.ca.shared.global [%0], [%1], 16;"
                 :: "r"(smem_u32(dst)), "l"(g));
}

// ---------------------------------------------------------------------------
// Prep: folded edge-bias terms
// ---------------------------------------------------------------------------
__global__ __launch_bounds__(128) void prep_kernel(
    const float* __restrict__ phiE_W1, const float* __restrict__ phiE_b1,
    const float* __restrict__ edge_attr)
{
    int i = threadIdx.x;
    float e = edge_attr[0];
    g_scratch[OFF_BE0 + i] = phiE_b1[i]       + e * phiE_W1[256 * 128 + i];
    g_scratch[OFF_BE1 + i] = phiE_b1[128 + i] + e * phiE_W1[257 * 128 + 256 * 128 + i];
}

// ---------------------------------------------------------------------------
// Batched weight transpose + bf16 split: src [K,N] fp32 -> dst [N,K] bf16 hi/lo
// ---------------------------------------------------------------------------
struct WJob { const float* src; const float* src2; int K; int N; long dstHi; long dstLo; };
struct WJobs { WJob j[9]; };

__global__ void wsplitT_kernel(WJobs jobs)
{
    WJob jb = jobs.j[blockIdx.z];
    int kb = blockIdx.y * 32, nb = blockIdx.x * 32;
    if (kb >= jb.K || nb >= jb.N) return;
    __shared__ float t[32][33];
    int tx = threadIdx.x, ty = threadIdx.y;
    for (int j = ty; j < 32; j += 8) {
        float v = jb.src[(long)(kb + j) * jb.N + nb + tx];
        if (jb.src2) v += jb.src2[(long)(kb + j) * jb.N + nb + tx];
        t[j][tx] = v;
    }
    __syncthreads();
    for (int j = ty; j < 32; j += 8) {
        float v = t[tx][j];
        __nv_bfloat16 h = __float2bfloat16(v);
        long o = (long)(nb + j) * jb.K + kb + tx;
        g_bf[jb.dstHi + o] = h;
        g_bf[jb.dstLo + o] = __float2bfloat16(v - __bfloat162float(h));
    }
}

__global__ void wsplit_kernel(const float* __restrict__ W)
{
    __shared__ float t[32][33];
    int kb = blockIdx.y * 32, nb = blockIdx.x * 32;
    int tx = threadIdx.x, ty = threadIdx.y;
    for (int j = ty; j < 32; j += 8)
        t[j][tx] = W[(long)(kb + j) * 960 + nb + tx];
    __syncthreads();
    for (int j = ty; j < 32; j += 8) {
        float v = t[tx][j];
        __nv_bfloat16 h = __float2bfloat16(v);
        long o = (long)(nb + j) * 256 + kb + tx;
        g_bf[OB_WTH + o] = h;
        g_bf[OB_WTL + o] = __float2bfloat16(v - __bfloat162float(h));
    }
}

// ---------------------------------------------------------------------------
// MEGAKERNEL: backbone + shared head per 16-row batch slice, 8 warps,
// 2 blocks/SM co-resident (cross-block latency hiding), single-buffer staging.
// ---------------------------------------------------------------------------
#define APAD 40
// smem layout (bytes):
//   z0s 0..8192 | H 8192..24576 | M 24576..49152 | U 49152..73728
//   Ah 73728 (+3840) | Al 77568 | Wh 81408 (+10240) | Wl 91648 | end 101888
#define SM_MEGA 101888

struct SP {
    float4* z0s;  // 16 x 32
    float4* H;    // 32 x 32
    float4* M;    // 48 x 32 (also 16x256 C for shared head)
    float4* U;    // 48 x 32
};
struct ST {
    __nv_bfloat16* Ah; __nv_bfloat16* Al;
    __nv_bfloat16* Wh; __nv_bfloat16* Wl;
};

__device__ __forceinline__ float4 getA(int ph, const SP& sp, int r, int kk4)
{
    int v = r >> 4, b = r & (SLICE - 1);
    switch (ph) {
    case 1: return sp.z0s[b * 32 + kk4];
    case 3:
        if (kk4 < 32) return sp.z0s[b * 32 + kk4];
        else {
            float4 m = sp.M[b * 32 + kk4 - 32];
            if (v == 1) { m.x *= 2.f; m.y *= 2.f; m.z *= 2.f; m.w *= 2.f; }
            return m;
        }
    case 5: {
        int cls = (kk4 < 32) ? (v == 0 ? 0 : 1) : (v == 1 ? 0 : 1);
        int k = (kk4 < 32) ? kk4 : kk4 - 32;
        return sp.H[(cls * SLICE + b) * 32 + k];
    }
    case 7:
        if (kk4 < 32) return sp.H[((v == 0 ? 0 : 1) * SLICE + b) * 32 + kk4];
        else {
            int k = kk4 - 32;
            if (v == 0) return sp.M[b * 32 + k];
            if (v == 1) {
                float4 a = sp.M[(SLICE + b) * 32 + k], c = sp.M[(2 * SLICE + b) * 32 + k];
                return make_float4(a.x + c.x, a.y + c.y, a.z + c.z, a.w + c.w);
            }
            float4 c = sp.M[(2 * SLICE + b) * 32 + k];
            return make_float4(2.f * c.x, 2.f * c.y, 2.f * c.z, 2.f * c.w);
        }
    case 9: return sp.M[b * 32 + kk4];           // umix
    default: return sp.U[r * 32 + kk4];          // cases 2,4,6,10
    }
}

__device__ __forceinline__ void stageW(const __nv_bfloat16* Whi, const __nv_bfloat16* Wlo,
                                       int K, int ch, const ST& st, int tid)
{
    #pragma unroll
    for (int idx = tid; idx < 1024; idx += MT) {
        int mtx = idx >> 9, r = (idx >> 2) & 127, c = idx & 3;
        const __nv_bfloat16* src = (mtx ? Wlo : Whi) + (long)r * K + ch * 32 + c * 8;
        __nv_bfloat16* dst = (mtx ? st.Wl : st.Wh) + r * APAD + c * 8;
        cpasync16(dst, src);
    }
    asm volatile("cp.async.commit_group;");
}

__device__ __forceinline__ void convA(int ph, const SP& sp, const ST& st,
                                      int Mr, int ch, int tid)
{
    int n4 = Mr * 8;
    for (int idx = tid; idx < n4; idx += MT) {
        int r = idx >> 3, c4 = idx & 7;
        float4 val = getA(ph, sp, r, ch * 8 + c4);
        __nv_bfloat16 h0 = __float2bfloat16(val.x), h1 = __float2bfloat16(val.y);
        __nv_bfloat16 h2 = __float2bfloat16(val.z), h3 = __float2bfloat16(val.w);
        __nv_bfloat162 hp0; hp0.x = h0; hp0.y = h1;
        __nv_bfloat162 hp1; hp1.x = h2; hp1.y = h3;
        int o = r * APAD + c4 * 4;
        *reinterpret_cast<__nv_bfloat162*>(&st.Ah[o])     = hp0;
        *reinterpret_cast<__nv_bfloat162*>(&st.Ah[o + 2]) = hp1;
        __nv_bfloat162 lp0, lp1;
        lp0.x = __float2bfloat16(val.x - __bfloat162float(h0));
        lp0.y = __float2bfloat16(val.y - __bfloat162float(h1));
        lp1.x = __float2bfloat16(val.z - __bfloat162float(h2));
        lp1.y = __float2bfloat16(val.w - __bfloat162float(h3));
        *reinterpret_cast<__nv_bfloat162*>(&st.Al[o])     = lp0;
        *reinterpret_cast<__nv_bfloat162*>(&st.Al[o + 2]) = lp1;
    }
}

// One GEMM phase with 8 warps (2m x 4n). out cols land at [ocol, ocol+128),
// row stride ostride.
__device__ void gphase(int ph, int Mr, int K,
                       const __nv_bfloat16* Whi, const __nv_bfloat16* Wlo,
                       const float* bias, int do_relu,
                       const float* lng, const float* lnb,
                       const float* resid,
                       float* outp, int ostride, int ocol,
                       const SP& sp, const ST& st)
{
    const int tid = threadIdx.x, lane = tid & 31, w = tid >> 5;
    const int wm = (w & 1) * 16, wn = (w >> 1) * 32;
    const int lrow = lane & 15, lcol8 = (lane >> 4) * 8;
    const int nch = K / 32;
    const int nmi = (Mr + 31) / 32;

    float acc[2][4][4];
    #pragma unroll
    for (int it = 0; it < 2; it++)
        #pragma unroll
        for (int nt = 0; nt < 4; nt++)
            #pragma unroll
            for (int q = 0; q < 4; q++) acc[it][nt][q] = 0.f;

    for (int ch = 0; ch < nch; ch++) {
        stageW(Whi, Wlo, K, ch, st, tid);
        convA(ph, sp, st, Mr, ch, tid);
        asm volatile("cp.async.wait_group 0;");
        __syncthreads();

        const unsigned ahB = smem_u32(st.Ah), alB = smem_u32(st.Al);
        const unsigned whB = smem_u32(st.Wh), wlB = smem_u32(st.Wl);
        #pragma unroll
        for (int k16 = 0; k16 < 2; k16++) {
            unsigned bh[4][2], bl[4][2];
            #pragma unroll
            for (int nh = 0; nh < 2; nh++) {
                unsigned off = ((wn + nh * 16 + lrow) * APAD + k16 * 16 + lcol8) * 2;
                unsigned r0, r1, r2, r3;
                asm volatile("ldmatrix.sync.aligned.m8n8.x4.shared.b16 {%0,%1,%2,%3}, [%4];"
                             : "=r"(r0), "=r"(r1), "=r"(r2), "=r"(r3) : "r"(whB + off));
                bh[nh*2+0][0] = r0; bh[nh*2+0][1] = r2;
                bh[nh*2+1][0] = r1; bh[nh*2+1][1] = r3;
                asm volatile("ldmatrix.sync.aligned.m8n8.x4.shared.b16 {%0,%1,%2,%3}, [%4];"
                             : "=r"(r0), "=r"(r1), "=r"(r2), "=r"(r3) : "r"(wlB + off));
                bl[nh*2+0][0] = r0; bl[nh*2+0][1] = r2;
                bl[nh*2+1][0] = r1; bl[nh*2+1][1] = r3;
            }
            #pragma unroll 2
            for (int it = 0; it < nmi; it++) {
                int rb = it * 32 + wm;
                if (rb < Mr) {
                    unsigned ah[4], al[4];
                    unsigned off = ((rb + lrow) * APAD + k16 * 16 + lcol8) * 2;
                    asm volatile("ldmatrix.sync.aligned.m8n8.x4.shared.b16 {%0,%1,%2,%3}, [%4];"
                                 : "=r"(ah[0]), "=r"(ah[1]), "=r"(ah[2]), "=r"(ah[3])
                                 : "r"(ahB + off));
                    asm volatile("ldmatrix.sync.aligned.m8n8.x4.shared.b16 {%0,%1,%2,%3}, [%4];"
                                 : "=r"(al[0]), "=r"(al[1]), "=r"(al[2]), "=r"(al[3])
                                 : "r"(alB + off));
                    #pragma unroll
                    for (int nt = 0; nt < 4; nt++) {
                        asm volatile(
                            "mma.sync.aligned.m16n8k16.row.col.f32.bf16.bf16.f32 "
                            "{%0,%1,%2,%3}, {%4,%5,%6,%7}, {%8,%9}, {%0,%1,%2,%3};"
                            : "+f"(acc[it][nt][0]), "+f"(acc[it][nt][1]),
                              "+f"(acc[it][nt][2]), "+f"(acc[it][nt][3])
                            : "r"(ah[0]), "r"(ah[1]), "r"(ah[2]), "r"(ah[3]),
                              "r"(bh[nt][0]), "r"(bh[nt][1]));
                        asm volatile(
                            "mma.sync.aligned.m16n8k16.row.col.f32.bf16.bf16.f32 "
                            "{%0,%1,%2,%3}, {%4,%5,%6,%7}, {%8,%9}, {%0,%1,%2,%3};"
                            : "+f"(acc[it][nt][0]), "+f"(acc[it][nt][1]),
                              "+f"(acc[it][nt][2]), "+f"(acc[it][nt][3])
                            : "r"(ah[0]), "r"(ah[1]), "r"(ah[2]), "r"(ah[3]),
                              "r"(bl[nt][0]), "r"(bl[nt][1]));
                        asm volatile(
                            "mma.sync.aligned.m16n8k16.row.col.f32.bf16.bf16.f32 "
                            "{%0,%1,%2,%3}, {%4,%5,%6,%7}, {%8,%9}, {%0,%1,%2,%3};"
                            : "+f"(acc[it][nt][0]), "+f"(acc[it][nt][1]),
                              "+f"(acc[it][nt][2]), "+f"(acc[it][nt][3])
                            : "r"(al[0]), "r"(al[1]), "r"(al[2]), "r"(al[3]),
                              "r"(bh[nt][0]), "r"(bh[nt][1]));
                    }
                }
            }
        }
        __syncthreads();
    }

    // raw accums -> outp
    const int gid = lane >> 2, tq = (lane & 3) * 2;
    #pragma unroll 2
    for (int it = 0; it < nmi; it++) {
        int rb = it * 32 + wm;
        if (rb < Mr) {
            #pragma unroll
            for (int nt = 0; nt < 4; nt++) {
                int r = rb + gid, c = ocol + wn + nt * 8 + tq;
                outp[r * ostride + c]           = acc[it][nt][0];
                outp[r * ostride + c + 1]       = acc[it][nt][1];
                outp[(r + 8) * ostride + c]     = acc[it][nt][2];
                outp[(r + 8) * ostride + c + 1] = acc[it][nt][3];
            }
        }
    }
    __syncthreads();

    // row epilogue over the 128 cols written by this phase (8 warps)
    float4 bv = *reinterpret_cast<const float4*>(&bias[lane * 4]);
    float4 gv, ev;
    if (lng) {
        gv = *reinterpret_cast<const float4*>(&lng[lane * 4]);
        ev = *reinterpret_cast<const float4*>(&lnb[lane * 4]);
    }
    for (int r = w; r < Mr; r += 8) {
        int b = r & (SLICE - 1);
        float4 vv = *reinterpret_cast<float4*>(&outp[r * ostride + ocol + lane * 4]);
        vv.x += bv.x; vv.y += bv.y; vv.z += bv.z; vv.w += bv.w;
        if (do_relu) {
            vv.x = fmaxf(vv.x, 0.f); vv.y = fmaxf(vv.y, 0.f);
            vv.z = fmaxf(vv.z, 0.f); vv.w = fmaxf(vv.w, 0.f);
        }
        if (lng) {
            float su = vv.x + vv.y + vv.z + vv.w;
            float q = vv.x*vv.x + vv.y*vv.y + vv.z*vv.z + vv.w*vv.w;
            #pragma unroll
            for (int off = 16; off > 0; off >>= 1) {
                su += __shfl_xor_sync(0xffffffffu, su, off);
                q  += __shfl_xor_sync(0xffffffffu, q, off);
            }
            float mu = su * (1.f / 128.f);
            float var = q * (1.f / 128.f) - mu * mu;
            float rs = rsqrtf(var + 1e-5f);
            vv.x = (vv.x - mu) * rs * gv.x + ev.x;
            vv.y = (vv.y - mu) * rs * gv.y + ev.y;
            vv.z = (vv.z - mu) * rs * gv.z + ev.z;
            vv.w = (vv.w - mu) * rs * gv.w + ev.w;
        }
        if (resid) {
            float4 rv = *reinterpret_cast<const float4*>(&resid[b * 128 + lane * 4]);
            vv.x += rv.x; vv.y += rv.y; vv.z += rv.z; vv.w += rv.w;
        }
        *reinterpret_cast<float4*>(&outp[r * ostride + ocol + lane * 4]) = vv;
    }
    __syncthreads();
}

__global__ __launch_bounds__(MT, 2) void mega_kernel(
    const float* __restrict__ z0,
    const float* __restrict__ be0, const float* __restrict__ be1,
    const float* __restrict__ phiE_b2,
    const float* __restrict__ phiN_b1, const float* __restrict__ phiN_g,
    const float* __restrict__ phiN_be, const float* __restrict__ phiN_b2,
    const float* __restrict__ sh_b, const float* __restrict__ ln_g,
    const float* __restrict__ ln_b,
    __nv_bfloat16* __restrict__ xh, __nv_bfloat16* __restrict__ xl,
    const __nv_bfloat16* __restrict__ wb)
{
    extern __shared__ __align__(16) char sm[];
    float* z0s = reinterpret_cast<float*>(sm);              // 8192 B
    float* H   = reinterpret_cast<float*>(sm + 8192);       // 16384
    float* M   = reinterpret_cast<float*>(sm + 24576);      // 24576
    float* U   = reinterpret_cast<float*>(sm + 49152);      // 24576
    ST st;
    st.Ah = reinterpret_cast<__nv_bfloat16*>(sm + 73728);   // 3840
    st.Al = reinterpret_cast<__nv_bfloat16*>(sm + 77568);   // 3840
    st.Wh = reinterpret_cast<__nv_bfloat16*>(sm + 81408);   // 10240
    st.Wl = reinterpret_cast<__nv_bfloat16*>(sm + 91648);   // 10240 -> 101888
    SP sp;
    sp.z0s = reinterpret_cast<float4*>(z0s);
    sp.H   = reinterpret_cast<float4*>(H);
    sp.M   = reinterpret_cast<float4*>(M);
    sp.U   = reinterpret_cast<float4*>(U);

    const int tid = threadIdx.x, lane = tid & 31, w = tid >> 5;
    const int bb = blockIdx.x;

    {   // load z0 slice (16 x 128)
        const float4* zsrc = reinterpret_cast<const float4*>(z0 + (long)bb * SLICE * 128);
        #pragma unroll
        for (int i = tid; i < SLICE * 32; i += MT) sp.z0s[i] = zsrc[i];
    }
    __syncthreads();

    // P1: T = relu(z0 @ WE0 + be0) -> U[0:16]
    gphase(1, SLICE, 128, wb + WB + 0, wb + WB + 16384, be0, 1,
           nullptr, nullptr, nullptr, U, 128, 0, sp, st);
    // P2: m0 = T @ E2k0 + b2 -> M[0:16]
    gphase(2, SLICE, 128, wb + WB + 32768, wb + WB + 49152, phiE_b2, 0,
           nullptr, nullptr, nullptr, M, 128, 0, sp, st);
    // P3: U = LN(relu(pack0 @ N1k0 + b1)) -> U[0:32]
    gphase(3, 2 * SLICE, 256, wb + WB + 65536, wb + WB + 98304, phiN_b1, 1,
           phiN_g, phiN_be, nullptr, U, 128, 0, sp, st);
    // P4: H = U @ N2k0 + b2 + z0 -> H[0:32]
    gphase(4, 2 * SLICE, 128, wb + WB + 131072, wb + WB + 147456, phiN_b2, 0,
           nullptr, nullptr, z0s, H, 128, 0, sp, st);
    // P5: T = relu(pack1 @ E1k1 + be1) -> U[0:48]
    gphase(5, 3 * SLICE, 256, wb + WB + 163840, wb + WB + 196608, be1, 1,
           nullptr, nullptr, nullptr, U, 128, 0, sp, st);
    // P6: m1 = T @ E2k1 + b2' -> M[0:48]
    gphase(6, 3 * SLICE, 128, wb + WB + 229376, wb + WB + 245760, phiE_b2 + 128, 0,
           nullptr, nullptr, nullptr, M, 128, 0, sp, st);
    // P7: U = LN(relu(pack2 @ N1k1 + b1')) -> U[0:48]
    gphase(7, 3 * SLICE, 256, wb + WB + 262144, wb + WB + 294912, phiN_b1 + 128, 1,
           phiN_g + 128, phiN_be + 128, nullptr, U, 128, 0, sp, st);
    // mix: umix -> M[0:16], hmix -> M[16:32]
    for (int idx = tid; idx < SLICE * 32; idx += MT) {
        int r = idx >> 5, c = idx & 31;
        float4 u0 = sp.U[r * 32 + c], u1 = sp.U[(SLICE + r) * 32 + c],
               u2 = sp.U[(2 * SLICE + r) * 32 + c];
        float4 rm;
        rm.x = (2.f * (u0.x + u1.x) + 60.f * u2.x) * (1.f / 64.f);
        rm.y = (2.f * (u0.y + u1.y) + 60.f * u2.y) * (1.f / 64.f);
        rm.z = (2.f * (u0.z + u1.z) + 60.f * u2.z) * (1.f / 64.f);
        rm.w = (2.f * (u0.w + u1.w) + 60.f * u2.w) * (1.f / 64.f);
        sp.M[r * 32 + c] = rm;
        float4 h0 = sp.H[r * 32 + c], h1 = sp.H[(SLICE + r) * 32 + c];
        float4 rh;
        rh.x = (2.f * h0.x + 62.f * h1.x) * (1.f / 64.f);
        rh.y = (2.f * h0.y + 62.f * h1.y) * (1.f / 64.f);
        rh.z = (2.f * h0.z + 62.f * h1.z) * (1.f / 64.f);
        rh.w = (2.f * h0.w + 62.f * h1.w) * (1.f / 64.f);
        sp.M[(SLICE + r) * 32 + c] = rh;
    }
    __syncthreads();
    // P9: zG = umix @ N2k1 + b2' + hmix -> U[0:16]
    gphase(9, SLICE, 128, wb + WB + 327680, wb + WB + 344064, phiN_b2 + 128, 0,
           nullptr, nullptr, M + SLICE * 128, U, 128, 0, sp, st);
    // P10a/b: x = relu(zG @ sh_W + sh_b), both halves into C=M (16x256)
    gphase(10, SLICE, 128, wb + WB + 360448, wb + WB + 393216, sh_b, 1,
           nullptr, nullptr, nullptr, M, 256, 0, sp, st);
    gphase(10, SLICE, 128, wb + WB + 376832, wb + WB + 409600, sh_b + 128, 1,
           nullptr, nullptr, nullptr, M, 256, 128, sp, st);

    // LN256 over C rows + emit bf16 hi/lo split to global
    {
        float4 g0 = *reinterpret_cast<const float4*>(&ln_g[lane * 4]);
        float4 g1 = *reinterpret_cast<const float4*>(&ln_g[128 + lane * 4]);
        float4 e0 = *reinterpret_cast<const float4*>(&ln_b[lane * 4]);
        float4 e1 = *reinterpret_cast<const float4*>(&ln_b[128 + lane * 4]);
        for (int r = w; r < SLICE; r += 8) {
            float4 v0 = *reinterpret_cast<float4*>(&M[r * 256 + lane * 4]);
            float4 v1 = *reinterpret_cast<float4*>(&M[r * 256 + 128 + lane * 4]);
            float su = v0.x + v0.y + v0.z + v0.w + v1.x + v1.y + v1.z + v1.w;
            float q = v0.x*v0.x + v0.y*v0.y + v0.z*v0.z + v0.w*v0.w
                    + v1.x*v1.x + v1.y*v1.y + v1.z*v1.z + v1.w*v1.w;
            #pragma unroll
            for (int off = 16; off > 0; off >>= 1) {
                su += __shfl_xor_sync(0xffffffffu, su, off);
                q  += __shfl_xor_sync(0xffffffffu, q, off);
            }
            float mu = su * (1.f / 256.f);
            float var = q * (1.f / 256.f) - mu * mu;
            float rs = rsqrtf(var + 1e-5f);
            v0.x = (v0.x - mu) * rs * g0.x + e0.x;
            v0.y = (v0.y - mu) * rs * g0.y + e0.y;
            v0.z = (v0.z - mu) * rs * g0.z + e0.z;
            v0.w = (v0.w - mu) * rs * g0.w + e0.w;
            v1.x = (v1.x - mu) * rs * g1.x + e1.x;
            v1.y = (v1.y - mu) * rs * g1.y + e1.y;
            v1.z = (v1.z - mu) * rs * g1.z + e1.z;
            v1.w = (v1.w - mu) * rs * g1.w + e1.w;
            long row = (long)bb * SLICE + r;
            __nv_bfloat162* XH = reinterpret_cast<__nv_bfloat162*>(xh + row * 256);
            __nv_bfloat162* XL = reinterpret_cast<__nv_bfloat162*>(xl + row * 256);
            float vals[8] = {v0.x, v0.y, v0.z, v0.w, v1.x, v1.y, v1.z, v1.w};
            #pragma unroll
            for (int half = 0; half < 2; half++) {
                #pragma unroll
                for (int j = 0; j < 2; j++) {
                    float va = vals[half * 4 + j * 2], vb2 = vals[half * 4 + j * 2 + 1];
                    __nv_bfloat16 ha = __float2bfloat16(va), hb2 = __float2bfloat16(vb2);
                    __nv_bfloat162 hp; hp.x = ha; hp.y = hb2;
                    XH[half * 64 + lane * 2 + j] = hp;
                    __nv_bfloat162 lp;
                    lp.x = __float2bfloat16(va - __bfloat162float(ha));
                    lp.y = __float2bfloat16(vb2 - __bfloat162float(hb2));
                    XL[half * 64 + lane * 2 + j] = lp;
                }
            }
        }
    }
}

// ---------------------------------------------------------------------------
// Policy head mma (validated)
// ---------------------------------------------------------------------------
#define PPAD 72

__global__ __launch_bounds__(NTHREADS) void pol_mma_kernel(
    const __nv_bfloat16* __restrict__ Xhi, const __nv_bfloat16* __restrict__ Xlo,
    const __nv_bfloat16* __restrict__ Whi, const __nv_bfloat16* __restrict__ Wlo,
    const float* __restrict__ bias, float* __restrict__ out)
{
    __shared__ __align__(16) __nv_bfloat16 As[128 * PPAD];
    __shared__ __align__(16) __nv_bfloat16 Bs[64 * PPAD];
    const int tid = threadIdx.x;
    const int lane = tid & 31, w = tid >> 5;
    const int wm = (w & 3) * 32, wn = (w >> 2) * 32;
    const int m0 = blockIdx.y * 128, n0 = blockIdx.x * 64;

    float acc[2][4][4];
    #pragma unroll
    for (int mt = 0; mt < 2; mt++)
        #pragma unroll
        for (int nt = 0; nt < 4; nt++)
            #pragma unroll
            for (int q = 0; q < 4; q++) acc[mt][nt][q] = 0.f;

    const __nv_bfloat16* Aps[3] = {Xhi, Xhi, Xlo};
    const __nv_bfloat16* Bps[3] = {Whi, Wlo, Whi};

    const unsigned a_base = smem_u32(As);
    const unsigned b_base = smem_u32(Bs);
    const int lrow = lane & 15, lcol8 = (lane >> 4) * 8;

    for (int p = 0; p < 3; p++) {
        const __nv_bfloat16* Ap = Aps[p];
        const __nv_bfloat16* Bp = Bps[p];
        for (int kc = 0; kc < 256; kc += 64) {
            __syncthreads();
            #pragma unroll
            for (int i = tid; i < 1024; i += NTHREADS) {
                int r = i >> 3, c8 = i & 7;
                *reinterpret_cast<uint4*>(&As[r * PPAD + c8 * 8]) =
                    *reinterpret_cast<const uint4*>(&Ap[(long)(m0 + r) * 256 + kc + c8 * 8]);
            }
            #pragma unroll
            for (int i = tid; i < 512; i += NTHREADS) {
                int r = i >> 3, c8 = i & 7;
                *reinterpret_cast<uint4*>(&Bs[r * PPAD + c8 * 8]) =
                    *reinterpret_cast<const uint4*>(&Bp[(long)(n0 + r) * 256 + kc + c8 * 8]);
            }
            __syncthreads();
            #pragma unroll
            for (int k16 = 0; k16 < 4; k16++) {
                unsigned a[2][4];
                #pragma unroll
                for (int mt = 0; mt < 2; mt++) {
                    unsigned addr = a_base +
                        ((wm + mt * 16 + lrow) * PPAD + k16 * 16 + lcol8) * 2;
                    asm volatile("ldmatrix.sync.aligned.m8n8.x4.shared.b16 "
                                 "{%0,%1,%2,%3}, [%4];"
                                 : "=r"(a[mt][0]), "=r"(a[mt][1]),
                                   "=r"(a[mt][2]), "=r"(a[mt][3]) : "r"(addr));
                }
                unsigned b[4][2];
                #pragma unroll
                for (int nh = 0; nh < 2; nh++) {
                    unsigned r0, r1, r2, r3;
                    unsigned addr = b_base +
                        ((wn + nh * 16 + lrow) * PPAD + k16 * 16 + lcol8) * 2;
                    asm volatile("ldmatrix.sync.aligned.m8n8.x4.shared.b16 "
                                 "{%0,%1,%2,%3}, [%4];"
                                 : "=r"(r0), "=r"(r1), "=r"(r2), "=r"(r3) : "r"(addr));
                    b[nh * 2 + 0][0] = r0; b[nh * 2 + 0][1] = r2;
                    b[nh * 2 + 1][0] = r1; b[nh * 2 + 1][1] = r3;
                }
                #pragma unroll
                for (int mt = 0; mt < 2; mt++)
                    #pragma unroll
                    for (int nt = 0; nt < 4; nt++) {
                        asm volatile(
                            "mma.sync.aligned.m16n8k16.row.col.f32.bf16.bf16.f32 "
                            "{%0,%1,%2,%3}, {%4,%5,%6,%7}, {%8,%9}, {%0,%1,%2,%3};"
                            : "+f"(acc[mt][nt][0]), "+f"(acc[mt][nt][1]),
                              "+f"(acc[mt][nt][2]), "+f"(acc[mt][nt][3])
                            : "r"(a[mt][0]), "r"(a[mt][1]), "r"(a[mt][2]), "r"(a[mt][3]),
                              "r"(b[nt][0]), "r"(b[nt][1]));
                    }
            }
        }
    }
    const int gid = lane >> 2, tq = (lane & 3) * 2;
    #pragma unroll
    for (int mt = 0; mt < 2; mt++) {
        #pragma unroll
        for (int nt = 0; nt < 4; nt++) {
            int col = n0 + wn + nt * 8 + tq;
            float bx = bias[col], by = bias[col + 1];
            int row0 = m0 + wm + mt * 16 + gid;
            float2 v0 = make_float2(acc[mt][nt][0] + bx, acc[mt][nt][1] + by);
            float2 v1 = make_float2(acc[mt][nt][2] + bx, acc[mt][nt][3] + by);
            *reinterpret_cast<float2*>(&out[(long)row0 * 960 + col]) = v0;
            *reinterpret_cast<float2*>(&out[(long)(row0 + 8) * 960 + col]) = v1;
        }
    }
}

// ---------------------------------------------------------------------------
// Value head: x reconstructed from bf16 hi/lo split
// ---------------------------------------------------------------------------
__global__ __launch_bounds__(NTHREADS) void val_kernel(
    const __nv_bfloat16* __restrict__ xh, const __nv_bfloat16* __restrict__ xl,
    const float* __restrict__ vW, const float* __restrict__ vb,
    float* __restrict__ V)
{
    int warp = threadIdx.x >> 5, lane = threadIdx.x & 31;
    int m = blockIdx.x * 8 + warp;
    float s = 0.f;
    #pragma unroll
    for (int k = lane; k < 256; k += 32) {
        float x = __bfloat162float(xh[(long)m * 256 + k]) +
                  __bfloat162float(xl[(long)m * 256 + k]);
        s += x * vW[k];
    }
    #pragma unroll
    for (int off = 16; off > 0; off >>= 1) s += __shfl_xor_sync(0xffffffffu, s, off);
    if (lane == 0) V[m] = s + vb[0];
}

// ---------------------------------------------------------------------------
// Launch
// ---------------------------------------------------------------------------
extern "C" void kernel_launch(void* const* d_in, const int* in_sizes, int n_in,
                              void* d_out, int out_size)
{
    const float* z0       = (const float*)d_in[0];
    const float* edge     = (const float*)d_in[3];
    const float* phiE_W1  = (const float*)d_in[4];
    const float* phiE_b1  = (const float*)d_in[5];
    const float* phiE_W2  = (const float*)d_in[6];
    const float* phiE_b2  = (const float*)d_in[7];
    const float* phiN_W1  = (const float*)d_in[8];
    const float* phiN_b1  = (const float*)d_in[9];
    const float* phiN_g   = (const float*)d_in[10];
    const float* phiN_be  = (const float*)d_in[11];
    const float* phiN_W2  = (const float*)d_in[12];
    const float* phiN_b2  = (const float*)d_in[13];
    const float* sh_W     = (const float*)d_in[14];
    const float* sh_b     = (const float*)d_in[15];
    const float* ln_g     = (const float*)d_in[16];
    const float* ln_b     = (const float*)d_in[17];
    const float* pol_W    = (const float*)d_in[18];
    const float* pol_b    = (const float*)d_in[19];
    const float* val_W    = (const float*)d_in[20];
    const float* val_b    = (const float*)d_in[21];
    float* outf = (float*)d_out;

    float* S = nullptr;
    cudaGetSymbolAddress((void**)&S, g_scratch);
    __nv_bfloat16* Bf = nullptr;
    cudaGetSymbolAddress((void**)&Bf, g_bf);

    cudaFuncSetAttribute(mega_kernel, cudaFuncAttributeMaxDynamicSharedMemorySize, SM_MEGA);

    // --- prep + weight splits ---
    prep_kernel<<<1, 128>>>(phiE_W1, phiE_b1, edge);
    wsplit_kernel<<<dim3(30, 8), dim3(32, 8)>>>(pol_W);
    {
        WJobs jb;
        jb.j[0] = { phiE_W1,           phiE_W1 + 128*128, 128, 128, WB+0,      WB+16384 };
        jb.j[1] = { phiE_W2,           nullptr,           128, 128, WB+32768,  WB+49152 };
        jb.j[2] = { phiN_W1,           nullptr,           256, 128, WB+65536,  WB+98304 };
        jb.j[3] = { phiN_W2,           nullptr,           128, 128, WB+131072, WB+147456 };
        jb.j[4] = { phiE_W1 + 257*128, nullptr,           256, 128, WB+163840, WB+196608 };
        jb.j[5] = { phiE_W2 + 128*128, nullptr,           128, 128, WB+229376, WB+245760 };
        jb.j[6] = { phiN_W1 + 256*128, nullptr,           256, 128, WB+262144, WB+294912 };
        jb.j[7] = { phiN_W2 + 128*128, nullptr,           128, 128, WB+327680, WB+344064 };
        jb.j[8] = { sh_W,              nullptr,           128, 256, WB+360448, WB+393216 };
        wsplitT_kernel<<<dim3(8, 8, 9), dim3(32, 8)>>>(jb);
    }

    // --- backbone + shared head, 16-row slices, 2 blocks/SM ---
    mega_kernel<<<B / SLICE, MT, SM_MEGA>>>(
        z0, S + OFF_BE0, S + OFF_BE1, phiE_b2,
        phiN_b1, phiN_g, phiN_be, phiN_b2,
        sh_b, ln_g, ln_b,
        Bf + OB_XH, Bf + OB_XL, Bf);

    // --- heads ---
    pol_mma_kernel<<<dim3(960 / 64, B / 128), NTHREADS>>>(
        Bf + OB_XH, Bf + OB_XL, Bf + OB_WTH, Bf + OB_WTL, pol_b, outf);
    val_kernel<<<B / 8, NTHREADS>>>(Bf + OB_XH, Bf + OB_XL, val_W, val_b,
                                    outf + (long)B * 960);
}